// round 1
// baseline (speedup 1.0000x reference)
#include <cuda_runtime.h>
#include <math.h>

// ---------------------------------------------------------------------------
// Problem constants
// ---------------------------------------------------------------------------
#define BSZ   4
#define TSEQ  2048
#define CEMB  1024
#define NH    16
#define HD    64
#define RKV   512
#define FF    4096
#define MROWS (BSZ * TSEQ)   // 8192

// ---------------------------------------------------------------------------
// Scratch (static __device__ arrays -- allocation-free per harness rules)
// ---------------------------------------------------------------------------
__device__ float g_h    [MROWS * CEMB];      // LN1(x)
__device__ float g_qlin [MROWS * CEMB];      // h @ q_w
__device__ float g_ckv  [MROWS * RKV];       // LN(h @ kvd_w)
__device__ float g_kvlin[MROWS * 2 * CEMB];  // ckv @ kvu_w
__device__ float g_q    [MROWS * CEMB];      // [B,H,T,D] roped
__device__ float g_k    [MROWS * CEMB];      // [B,H,T,D] roped
__device__ float g_v    [MROWS * CEMB];      // [B,H,T,D]
__device__ float g_ctx  [MROWS * CEMB];      // attention out, [B,T,C]
__device__ float g_x1   [MROWS * CEMB];      // x + proj
__device__ float g_h2   [MROWS * CEMB];      // LN2(x1)
__device__ float g_ff1  [MROWS * FF];        // gelu(h2 @ f1_w + b)
__device__ float g_cos  [TSEQ * 32];
__device__ float g_sin  [TSEQ * 32];

// ---------------------------------------------------------------------------
// LayerNorm: one block per row, 256 threads, float4 IO. Works in-place.
// ---------------------------------------------------------------------------
__global__ void __launch_bounds__(256) ln_k(const float* __restrict__ x,
                                            const float* __restrict__ w,
                                            const float* __restrict__ b,
                                            float* __restrict__ out, int W)
{
    size_t row = blockIdx.x;
    const float* xr = x + row * (size_t)W;
    float* orow = out + row * (size_t)W;

    float s = 0.f, s2 = 0.f;
    for (int i = threadIdx.x << 2; i < W; i += 256 * 4) {
        float4 v = *(const float4*)(xr + i);
        s  += v.x + v.y + v.z + v.w;
        s2 += v.x * v.x + v.y * v.y + v.z * v.z + v.w * v.w;
    }
    __shared__ float sh[8][2];
    #pragma unroll
    for (int off = 16; off; off >>= 1) {
        s  += __shfl_xor_sync(0xffffffffu, s,  off);
        s2 += __shfl_xor_sync(0xffffffffu, s2, off);
    }
    int wrp = threadIdx.x >> 5, ln = threadIdx.x & 31;
    if (ln == 0) { sh[wrp][0] = s; sh[wrp][1] = s2; }
    __syncthreads();
    s = 0.f; s2 = 0.f;
    #pragma unroll
    for (int i = 0; i < 8; i++) { s += sh[i][0]; s2 += sh[i][1]; }

    float invW = 1.0f / (float)W;
    float mu   = s * invW;
    float var  = s2 * invW - mu * mu;
    float rstd = rsqrtf(var + 1e-5f);

    for (int i = threadIdx.x << 2; i < W; i += 256 * 4) {
        float4 v  = *(const float4*)(xr + i);
        float4 wv = *(const float4*)(w + i);
        float4 bv = *(const float4*)(b + i);
        float4 r;
        r.x = (v.x - mu) * rstd * wv.x + bv.x;
        r.y = (v.y - mu) * rstd * wv.y + bv.y;
        r.z = (v.z - mu) * rstd * wv.z + bv.z;
        r.w = (v.w - mu) * rstd * wv.w + bv.w;
        *(float4*)(orow + i) = r;
    }
}

// ---------------------------------------------------------------------------
// RoPE cos/sin table. Mimic numpy: inv_freq in f64 cast to f32, angle = f32
// product, trig evaluated accurately (f64) at the f32-rounded angle.
// ---------------------------------------------------------------------------
__global__ void rope_tab_k(float* __restrict__ ct, float* __restrict__ st)
{
    int idx = blockIdx.x * blockDim.x + threadIdx.x;
    if (idx >= TSEQ * 32) return;
    int t = idx >> 5, d = idx & 31;
    float inv = (float)pow(10000.0, -(double)d / 32.0);
    float ang = (float)t * inv;
    ct[idx] = (float)cos((double)ang);
    st[idx] = (float)sin((double)ang);
}

// ---------------------------------------------------------------------------
// Fused RoPE + transpose to [B,H,T,D] for q,k; plain transpose for v.
// One thread per (b,t,h,d<32) handles the rotation pair (d, d+32).
// ---------------------------------------------------------------------------
__global__ void __launch_bounds__(256) rope_qkv_k(
    const float* __restrict__ qlin, const float* __restrict__ kvlin,
    const float* __restrict__ ct, const float* __restrict__ st,
    float* __restrict__ q, float* __restrict__ k, float* __restrict__ v)
{
    int g = blockIdx.x * blockDim.x + threadIdx.x;   // < B*T*H*32 = 2^22
    int d = g & 31;
    int h = (g >> 5) & 15;
    int t = (g >> 9) & 2047;
    int b = g >> 20;

    float c = ct[t * 32 + d];
    float s = st[t * 32 + d];

    const float* ql = qlin + ((size_t)(b * TSEQ + t)) * CEMB + h * HD;
    const float* kl = kvlin + ((size_t)(b * TSEQ + t)) * (2 * CEMB) + h * HD;
    const float* vl = kl + CEMB;

    size_t o = (((size_t)(b * NH + h)) * TSEQ + t) * HD;

    float q0 = ql[d], q1 = ql[d + 32];
    q[o + d]      = q0 * c - q1 * s;
    q[o + d + 32] = q1 * c + q0 * s;

    float k0 = kl[d], k1 = kl[d + 32];
    k[o + d]      = k0 * c - k1 * s;
    k[o + d + 32] = k1 * c + k0 * s;

    v[o + d]      = vl[d];
    v[o + d + 32] = vl[d + 32];
}

// ---------------------------------------------------------------------------
// SGEMM 128x128x16, 256 threads, 8x8 register tiles, fused epilogues.
// C[M,N] = A[M,K] @ B[K,N] (+bias) (+gelu | +resid)
// All shapes here are multiples of tile dims -> no bounds checks.
// ---------------------------------------------------------------------------
#define EPI_NONE       0
#define EPI_BIAS_RESID 1
#define EPI_BIAS_GELU  2

__device__ __forceinline__ float gelu_exact(float x)
{
    return 0.5f * x * (1.0f + erff(x * 0.70710678118654752f));
}

template <int EPI>
__global__ void __launch_bounds__(256, 2) sgemm_k(
    const float* __restrict__ A, const float* __restrict__ B,
    float* __restrict__ C, const float* __restrict__ bias,
    const float* __restrict__ resid, int M, int N, int K)
{
    const int BK = 16;
    __shared__ float As[BK][128 + 4];
    __shared__ float Bs[BK][128];

    int tid = threadIdx.x;
    int bm = blockIdx.y * 128, bn = blockIdx.x * 128;

    int ar = tid >> 2;          // A tile row (first half; +64 for second)
    int ac = (tid & 3) << 2;    // A tile col (float4)
    int br = tid >> 5;          // B tile row (first half; +8 for second)
    int bc = (tid & 31) << 2;   // B tile col (float4)

    const float* Ap = A + (size_t)(bm + ar) * K + ac;
    const float* Bp = B + (size_t)br * N + bn + bc;

    int tr = (tid >> 4) << 3;   // output row base within tile
    int tc = (tid & 15) << 3;   // output col base within tile

    float acc[8][8] = {};

    for (int k0 = 0; k0 < K; k0 += BK) {
        float4 a0 = *(const float4*)(Ap);
        float4 a1 = *(const float4*)(Ap + (size_t)64 * K);
        float4 b0 = *(const float4*)(Bp);
        float4 b1 = *(const float4*)(Bp + (size_t)8 * N);
        __syncthreads();
        As[ac + 0][ar] = a0.x; As[ac + 1][ar] = a0.y;
        As[ac + 2][ar] = a0.z; As[ac + 3][ar] = a0.w;
        As[ac + 0][ar + 64] = a1.x; As[ac + 1][ar + 64] = a1.y;
        As[ac + 2][ar + 64] = a1.z; As[ac + 3][ar + 64] = a1.w;
        *(float4*)&Bs[br][bc]     = b0;
        *(float4*)&Bs[br + 8][bc] = b1;
        __syncthreads();

        #pragma unroll
        for (int k = 0; k < BK; k++) {
            float a[8], bb[8];
            *(float4*)(a)      = *(const float4*)&As[k][tr];
            *(float4*)(a + 4)  = *(const float4*)&As[k][tr + 4];
            *(float4*)(bb)     = *(const float4*)&Bs[k][tc];
            *(float4*)(bb + 4) = *(const float4*)&Bs[k][tc + 4];
            #pragma unroll
            for (int i = 0; i < 8; i++)
                #pragma unroll
                for (int j = 0; j < 8; j++)
                    acc[i][j] += a[i] * bb[j];
        }
        Ap += BK;
        Bp += (size_t)BK * N;
    }

    #pragma unroll
    for (int i = 0; i < 8; i++) {
        size_t row = bm + tr + i;
        float* Cp = C + row * N + bn + tc;
        #pragma unroll
        for (int j4 = 0; j4 < 8; j4 += 4) {
            float v0 = acc[i][j4 + 0], v1 = acc[i][j4 + 1];
            float v2 = acc[i][j4 + 2], v3 = acc[i][j4 + 3];
            if (EPI != EPI_NONE) {
                float4 bv = *(const float4*)(bias + bn + tc + j4);
                v0 += bv.x; v1 += bv.y; v2 += bv.z; v3 += bv.w;
            }
            if (EPI == EPI_BIAS_GELU) {
                v0 = gelu_exact(v0); v1 = gelu_exact(v1);
                v2 = gelu_exact(v2); v3 = gelu_exact(v3);
            }
            if (EPI == EPI_BIAS_RESID) {
                float4 rv = *(const float4*)(resid + row * N + bn + tc + j4);
                v0 += rv.x; v1 += rv.y; v2 += rv.z; v3 += rv.w;
            }
            float4 r = make_float4(v0, v1, v2, v3);
            *(float4*)(Cp + j4) = r;
        }
    }
}

// ---------------------------------------------------------------------------
// Flash attention (fp32, causal, D=64). Br=Bc=64. 256 threads as 16x16 grid,
// each owning a 4x4 tile of scores and a 4x4 tile of the output accumulator.
// K-tile smem is reused for the P-tile so static smem = exactly 48 KB.
// ---------------------------------------------------------------------------
__global__ void __launch_bounds__(256) attn_k(
    const float* __restrict__ Q, const float* __restrict__ Kk,
    const float* __restrict__ V, float* __restrict__ ctx)
{
    __shared__ float Qs[64][64];   // Q^T : Qs[d][r]
    __shared__ float KP[64][64];   // K^T (Ks[d][c]) then P^T (Ps[s][r])
    __shared__ float Vs[64][64];   // V   : Vs[s][d]

    int b = blockIdx.z, h = blockIdx.y, it = blockIdx.x;
    int t0 = it * 64;
    size_t bh = ((size_t)(b * NH + h)) * TSEQ * HD;

    int tid = threadIdx.x;
    int ty = tid >> 4, tx = tid & 15;
    int ry = ty << 2, cx = tx << 2;

    // Load Q tile transposed
    #pragma unroll
    for (int k = 0; k < 4; k++) {
        int f = tid + k * 256;
        int r = f >> 4, c4 = (f & 15) << 2;
        float4 q4 = *(const float4*)(Q + bh + (size_t)(t0 + r) * HD + c4);
        Qs[c4 + 0][r] = q4.x; Qs[c4 + 1][r] = q4.y;
        Qs[c4 + 2][r] = q4.z; Qs[c4 + 3][r] = q4.w;
    }

    float m_i[4], l_i[4], o[4][4];
    #pragma unroll
    for (int i = 0; i < 4; i++) {
        m_i[i] = -1e30f; l_i[i] = 0.f;
        #pragma unroll
        for (int j = 0; j < 4; j++) o[i][j] = 0.f;
    }

    int nk = it + 1;
    for (int kt = 0; kt < nk; kt++) {
        int k0 = kt * 64;
        __syncthreads();   // prior PV reads done before KP/Vs overwrite
        #pragma unroll
        for (int k = 0; k < 4; k++) {
            int f = tid + k * 256;
            int r = f >> 4, c4 = (f & 15) << 2;
            float4 k4 = *(const float4*)(Kk + bh + (size_t)(k0 + r) * HD + c4);
            KP[c4 + 0][r] = k4.x; KP[c4 + 1][r] = k4.y;
            KP[c4 + 2][r] = k4.z; KP[c4 + 3][r] = k4.w;
            float4 v4 = *(const float4*)(V + bh + (size_t)(k0 + r) * HD + c4);
            *(float4*)&Vs[r][c4] = v4;
        }
        __syncthreads();

        // S = Q K^T
        float s[4][4] = {};
        #pragma unroll 8
        for (int k = 0; k < 64; k++) {
            float a[4], bb[4];
            *(float4*)a  = *(const float4*)&Qs[k][ry];
            *(float4*)bb = *(const float4*)&KP[k][cx];
            #pragma unroll
            for (int i = 0; i < 4; i++)
                #pragma unroll
                for (int j = 0; j < 4; j++)
                    s[i][j] += a[i] * bb[j];
        }

        bool diag = (kt == nk - 1);
        #pragma unroll
        for (int i = 0; i < 4; i++)
            #pragma unroll
            for (int j = 0; j < 4; j++) {
                s[i][j] *= 0.125f;  // D^-0.5
                if (diag && (k0 + cx + j) > (t0 + ry + i)) s[i][j] = -1e30f;
            }

        // Online softmax per row (row reduction over 16 tx lanes via shfl-xor)
        #pragma unroll
        for (int i = 0; i < 4; i++) {
            float mx = fmaxf(fmaxf(s[i][0], s[i][1]), fmaxf(s[i][2], s[i][3]));
            #pragma unroll
            for (int off = 8; off >= 1; off >>= 1)
                mx = fmaxf(mx, __shfl_xor_sync(0xffffffffu, mx, off));
            float mn = fmaxf(m_i[i], mx);
            float alpha = expf(m_i[i] - mn);
            m_i[i] = mn;
            float sum = 0.f;
            #pragma unroll
            for (int j = 0; j < 4; j++) {
                s[i][j] = expf(s[i][j] - mn);
                sum += s[i][j];
            }
            #pragma unroll
            for (int off = 8; off >= 1; off >>= 1)
                sum += __shfl_xor_sync(0xffffffffu, sum, off);
            l_i[i] = l_i[i] * alpha + sum;
            #pragma unroll
            for (int j = 0; j < 4; j++) o[i][j] *= alpha;
        }

        __syncthreads();   // all S-phase reads of KP done
        #pragma unroll
        for (int i = 0; i < 4; i++)
            #pragma unroll
            for (int j = 0; j < 4; j++)
                KP[cx + j][ry + i] = s[i][j];   // P^T
        __syncthreads();

        // O += P V
        #pragma unroll 8
        for (int ss = 0; ss < 64; ss++) {
            float p[4], vv[4];
            *(float4*)p  = *(const float4*)&KP[ss][ry];
            *(float4*)vv = *(const float4*)&Vs[ss][cx];
            #pragma unroll
            for (int i = 0; i < 4; i++)
                #pragma unroll
                for (int j = 0; j < 4; j++)
                    o[i][j] += p[i] * vv[j];
        }
    }

    // Normalize and write to [B,T,C] layout for the proj GEMM
    #pragma unroll
    for (int i = 0; i < 4; i++) {
        float inv = 1.0f / l_i[i];
        int r = t0 + ry + i;
        float4 r4 = make_float4(o[i][0] * inv, o[i][1] * inv,
                                o[i][2] * inv, o[i][3] * inv);
        *(float4*)(ctx + ((size_t)(b * TSEQ + r)) * CEMB + h * HD + cx) = r4;
    }
}

// ---------------------------------------------------------------------------
// Launch
// ---------------------------------------------------------------------------
static float* sym(const void* s)
{
    void* p = nullptr;
    cudaGetSymbolAddress(&p, s);
    return (float*)p;
}

extern "C" void kernel_launch(void* const* d_in, const int* in_sizes, int n_in,
                              void* d_out, int out_size)
{
    const float* x      = (const float*)d_in[0];
    const float* ln1_w  = (const float*)d_in[1];
    const float* ln1_b  = (const float*)d_in[2];
    const float* ln2_w  = (const float*)d_in[3];
    const float* ln2_b  = (const float*)d_in[4];
    const float* q_w    = (const float*)d_in[5];
    const float* kvd_w  = (const float*)d_in[6];
    const float* kvln_w = (const float*)d_in[7];
    const float* kvln_b = (const float*)d_in[8];
    const float* kvu_w  = (const float*)d_in[9];
    const float* proj_w = (const float*)d_in[10];
    const float* proj_b = (const float*)d_in[11];
    const float* f1_w   = (const float*)d_in[12];
    const float* f1_b   = (const float*)d_in[13];
    const float* f2_w   = (const float*)d_in[14];
    const float* f2_b   = (const float*)d_in[15];
    float* out = (float*)d_out;

    float* h     = sym(g_h);
    float* qlin  = sym(g_qlin);
    float* ckv   = sym(g_ckv);
    float* kvlin = sym(g_kvlin);
    float* q     = sym(g_q);
    float* k     = sym(g_k);
    float* v     = sym(g_v);
    float* ctx   = sym(g_ctx);
    float* x1    = sym(g_x1);
    float* h2    = sym(g_h2);
    float* ff1   = sym(g_ff1);
    float* ct    = sym(g_cos);
    float* st    = sym(g_sin);

    // 1) h = LN1(x)
    ln_k<<<MROWS, 256>>>(x, ln1_w, ln1_b, h, CEMB);
    // 2) qlin = h @ q_w
    sgemm_k<EPI_NONE><<<dim3(CEMB / 128, MROWS / 128), 256>>>(
        h, q_w, qlin, nullptr, nullptr, MROWS, CEMB, CEMB);
    // 3) ckv = h @ kvd_w
    sgemm_k<EPI_NONE><<<dim3(RKV / 128, MROWS / 128), 256>>>(
        h, kvd_w, ckv, nullptr, nullptr, MROWS, RKV, CEMB);
    // 4) ckv = LN_kv(ckv)  (in-place)
    ln_k<<<MROWS, 256>>>(ckv, kvln_w, kvln_b, ckv, RKV);
    // 5) kvlin = ckv @ kvu_w
    sgemm_k<EPI_NONE><<<dim3(2 * CEMB / 128, MROWS / 128), 256>>>(
        ckv, kvu_w, kvlin, nullptr, nullptr, MROWS, 2 * CEMB, RKV);
    // 6) rope table + 7) rope & transpose to [B,H,T,D]
    rope_tab_k<<<(TSEQ * 32 + 255) / 256, 256>>>(ct, st);
    rope_qkv_k<<<(BSZ * TSEQ * NH * 32) / 256, 256>>>(qlin, kvlin, ct, st, q, k, v);
    // 8) flash attention -> ctx [B,T,C]
    attn_k<<<dim3(TSEQ / 64, NH, BSZ), 256>>>(q, k, v, ctx);
    // 9) x1 = x + ctx @ proj_w + proj_b
    sgemm_k<EPI_BIAS_RESID><<<dim3(CEMB / 128, MROWS / 128), 256>>>(
        ctx, proj_w, x1, proj_b, x, MROWS, CEMB, CEMB);
    // 10) h2 = LN2(x1)
    ln_k<<<MROWS, 256>>>(x1, ln2_w, ln2_b, h2, CEMB);
    // 11) ff1 = gelu(h2 @ f1_w + f1_b)
    sgemm_k<EPI_BIAS_GELU><<<dim3(FF / 128, MROWS / 128), 256>>>(
        h2, f1_w, ff1, f1_b, nullptr, MROWS, FF, CEMB);
    // 12) out = x1 + ff1 @ f2_w + f2_b
    sgemm_k<EPI_BIAS_RESID><<<dim3(CEMB / 128, MROWS / 128), 256>>>(
        ff1, f2_w, out, f2_b, x1, MROWS, CEMB, FF);
}

// round 5
// speedup vs baseline: 1.4764x; 1.4764x over previous
#include <cuda_runtime.h>
#include <cuda_bf16.h>
#include <math.h>
#include <stdint.h>

// ---------------------------------------------------------------------------
// Problem constants
// ---------------------------------------------------------------------------
#define BSZ   4
#define TSEQ  2048
#define CEMB  1024
#define NH    16
#define HD    64
#define RKV   512
#define FF    4096
#define MROWS (BSZ * TSEQ)   // 8192

typedef __nv_bfloat16 bf16;

// ---------------------------------------------------------------------------
// Scratch (static __device__ arrays -- allocation-free per harness rules)
// ---------------------------------------------------------------------------
__device__ float g_qlin [MROWS * CEMB];
__device__ float g_ckv  [MROWS * RKV];
__device__ float g_kvlin[MROWS * 2 * CEMB];
__device__ float g_q    [MROWS * CEMB];
__device__ float g_k    [MROWS * CEMB];
__device__ float g_v    [MROWS * CEMB];
__device__ float g_x1   [MROWS * CEMB];
__device__ float g_cos  [TSEQ * 32];
__device__ float g_sin  [TSEQ * 32];
// bf16 split activations (GEMM A operands)
__device__ bf16 g_h_h  [MROWS * CEMB];
__device__ bf16 g_h_l  [MROWS * CEMB];
__device__ bf16 g_ckv_h[MROWS * RKV];
__device__ bf16 g_ckv_l[MROWS * RKV];
__device__ bf16 g_ctx_h[MROWS * CEMB];
__device__ bf16 g_ctx_l[MROWS * CEMB];
__device__ bf16 g_h2_h [MROWS * CEMB];
__device__ bf16 g_h2_l [MROWS * CEMB];
__device__ bf16 g_ff1_h[MROWS * FF];
__device__ bf16 g_ff1_l[MROWS * FF];
// bf16 split transposed weights [N,K]
__device__ bf16 g_wq_h  [CEMB * CEMB];
__device__ bf16 g_wq_l  [CEMB * CEMB];
__device__ bf16 g_wkvd_h[RKV * CEMB];
__device__ bf16 g_wkvd_l[RKV * CEMB];
__device__ bf16 g_wkvu_h[2 * CEMB * RKV];
__device__ bf16 g_wkvu_l[2 * CEMB * RKV];
__device__ bf16 g_wpr_h [CEMB * CEMB];
__device__ bf16 g_wpr_l [CEMB * CEMB];
__device__ bf16 g_wf1_h [FF * CEMB];
__device__ bf16 g_wf1_l [FF * CEMB];
__device__ bf16 g_wf2_h [CEMB * FF];
__device__ bf16 g_wf2_l [CEMB * FF];

// ---------------------------------------------------------------------------
// Helpers
// ---------------------------------------------------------------------------
__device__ __forceinline__ void split_f32(float x, bf16& h, bf16& l)
{
    h = __float2bfloat16_rn(x);
    l = __float2bfloat16_rn(x - __bfloat162float(h));
}
__device__ __forceinline__ float gelu_exact(float x)
{
    return 0.5f * x * (1.0f + erff(x * 0.70710678118654752f));
}
__device__ __forceinline__ void cpa16(uint32_t saddr, const void* g)
{
    asm volatile("cp.async.cg.shared.global [%0], [%1], 16;"
                 :: "r"(saddr), "l"(g) : "memory");
}
__device__ __forceinline__ void cpa_commit()
{
    asm volatile("cp.async.commit_group;" ::: "memory");
}
template <int N>
__device__ __forceinline__ void cpa_wait()
{
    asm volatile("cp.async.wait_group %0;" :: "n"(N) : "memory");
}
__device__ __forceinline__ void mma_bf16(float& c0, float& c1, float& c2, float& c3,
                                         uint32_t a0, uint32_t a1, uint32_t a2,
                                         uint32_t a3, uint32_t b0, uint32_t b1)
{
    asm volatile(
        "mma.sync.aligned.m16n8k16.row.col.f32.bf16.bf16.f32 "
        "{%0,%1,%2,%3}, {%4,%5,%6,%7}, {%8,%9}, {%0,%1,%2,%3};"
        : "+f"(c0), "+f"(c1), "+f"(c2), "+f"(c3)
        : "r"(a0), "r"(a1), "r"(a2), "r"(a3), "r"(b0), "r"(b1));
}

// ---------------------------------------------------------------------------
// LayerNorm (optionally writing split bf16 output)
// ---------------------------------------------------------------------------
template <bool SPLIT>
__global__ void __launch_bounds__(256) ln_k(const float* __restrict__ x,
                                            const float* __restrict__ w,
                                            const float* __restrict__ b,
                                            float* __restrict__ out,
                                            bf16* __restrict__ oh,
                                            bf16* __restrict__ ol, int W)
{
    size_t row = blockIdx.x;
    const float* xr = x + row * (size_t)W;

    float s = 0.f, s2 = 0.f;
    for (int i = threadIdx.x << 2; i < W; i += 256 * 4) {
        float4 v = *(const float4*)(xr + i);
        s  += v.x + v.y + v.z + v.w;
        s2 += v.x * v.x + v.y * v.y + v.z * v.z + v.w * v.w;
    }
    __shared__ float sh[8][2];
    #pragma unroll
    for (int off = 16; off; off >>= 1) {
        s  += __shfl_xor_sync(0xffffffffu, s,  off);
        s2 += __shfl_xor_sync(0xffffffffu, s2, off);
    }
    int wrp = threadIdx.x >> 5, ln = threadIdx.x & 31;
    if (ln == 0) { sh[wrp][0] = s; sh[wrp][1] = s2; }
    __syncthreads();
    s = 0.f; s2 = 0.f;
    #pragma unroll
    for (int i = 0; i < 8; i++) { s += sh[i][0]; s2 += sh[i][1]; }

    float invW = 1.0f / (float)W;
    float mu   = s * invW;
    float var  = s2 * invW - mu * mu;
    float rstd = rsqrtf(var + 1e-5f);

    for (int i = threadIdx.x << 2; i < W; i += 256 * 4) {
        float4 v  = *(const float4*)(xr + i);
        float4 wv = *(const float4*)(w + i);
        float4 bv = *(const float4*)(b + i);
        float r0 = (v.x - mu) * rstd * wv.x + bv.x;
        float r1 = (v.y - mu) * rstd * wv.y + bv.y;
        float r2 = (v.z - mu) * rstd * wv.z + bv.z;
        float r3 = (v.w - mu) * rstd * wv.w + bv.w;
        if (!SPLIT) {
            *(float4*)(out + row * (size_t)W + i) = make_float4(r0, r1, r2, r3);
        } else {
            bf16 h0, l0, h1, l1, h2, l2, h3, l3;
            split_f32(r0, h0, l0); split_f32(r1, h1, l1);
            split_f32(r2, h2, l2); split_f32(r3, h3, l3);
            __nv_bfloat162 hh0; hh0.x = h0; hh0.y = h1;
            __nv_bfloat162 hh1; hh1.x = h2; hh1.y = h3;
            __nv_bfloat162 ll0; ll0.x = l0; ll0.y = l1;
            __nv_bfloat162 ll1; ll1.x = l2; ll1.y = l3;
            *(__nv_bfloat162*)(oh + row * (size_t)W + i)     = hh0;
            *(__nv_bfloat162*)(oh + row * (size_t)W + i + 2) = hh1;
            *(__nv_bfloat162*)(ol + row * (size_t)W + i)     = ll0;
            *(__nv_bfloat162*)(ol + row * (size_t)W + i + 2) = ll1;
        }
    }
}

// ---------------------------------------------------------------------------
// Weight preprocess: W[K,N] -> Th/Tl [N,K] bf16 hi/lo (tiled transpose)
// ---------------------------------------------------------------------------
__global__ void __launch_bounds__(256) prep_w(const float* __restrict__ W,
                                              bf16* __restrict__ Th,
                                              bf16* __restrict__ Tl,
                                              int K, int N)
{
    __shared__ float t[32][33];
    int nb = blockIdx.x * 32, kb = blockIdx.y * 32;
    int tx = threadIdx.x & 31, ty = threadIdx.x >> 5;  // 32 x 8
    #pragma unroll
    for (int j = 0; j < 32; j += 8)
        t[ty + j][tx] = W[(size_t)(kb + ty + j) * N + nb + tx];
    __syncthreads();
    #pragma unroll
    for (int j = 0; j < 32; j += 8) {
        float v = t[tx][ty + j];
        bf16 h, l;
        split_f32(v, h, l);
        size_t o = (size_t)(nb + ty + j) * K + kb + tx;
        Th[o] = h; Tl[o] = l;
    }
}

// ---------------------------------------------------------------------------
// RoPE table + fused RoPE/transpose (fp32)
// ---------------------------------------------------------------------------
__global__ void rope_tab_k(float* __restrict__ ct, float* __restrict__ st)
{
    int idx = blockIdx.x * blockDim.x + threadIdx.x;
    if (idx >= TSEQ * 32) return;
    int t = idx >> 5, d = idx & 31;
    float inv = (float)pow(10000.0, -(double)d / 32.0);
    float ang = (float)t * inv;
    ct[idx] = (float)cos((double)ang);
    st[idx] = (float)sin((double)ang);
}

__global__ void __launch_bounds__(256) rope_qkv_k(
    const float* __restrict__ qlin, const float* __restrict__ kvlin,
    const float* __restrict__ ct, const float* __restrict__ st,
    float* __restrict__ q, float* __restrict__ k, float* __restrict__ v)
{
    int g = blockIdx.x * blockDim.x + threadIdx.x;
    int d = g & 31;
    int h = (g >> 5) & 15;
    int t = (g >> 9) & 2047;
    int b = g >> 20;

    float c = ct[t * 32 + d];
    float s = st[t * 32 + d];

    const float* ql = qlin + ((size_t)(b * TSEQ + t)) * CEMB + h * HD;
    const float* kl = kvlin + ((size_t)(b * TSEQ + t)) * (2 * CEMB) + h * HD;
    const float* vl = kl + CEMB;

    size_t o = (((size_t)(b * NH + h)) * TSEQ + t) * HD;

    float q0 = ql[d], q1 = ql[d + 32];
    q[o + d]      = q0 * c - q1 * s;
    q[o + d + 32] = q1 * c + q0 * s;

    float k0 = kl[d], k1 = kl[d + 32];
    k[o + d]      = k0 * c - k1 * s;
    k[o + d + 32] = k1 * c + k0 * s;

    v[o + d]      = vl[d];
    v[o + d + 32] = vl[d + 32];
}

// ---------------------------------------------------------------------------
// mma.sync split-bf16 GEMM: C[M,N] = A[M,K] @ W[N,K]^T, fused epilogues.
// BM=BN=128, BK=16, 256 threads = 8 warps (2x4), warp tile 64x32.
// Static smem, 2 stages x 24KB = 48KB (no dynamic smem / no attribute calls).
// Rows padded 16 -> 24 bf16: fragment word idx = 12*qr + qc is a perfect
// residue system mod 32 -> conflict-free LDS. cp.async double buffering.
// ---------------------------------------------------------------------------
#define EPI_NONE       0
#define EPI_BIAS_RESID 1
#define EPI_BIAS_GELU  2

#define ROWP   24
#define MATB   (128 * ROWP * 2)     // 6144 bytes per matrix per stage
#define STAGEB (4 * MATB)           // 24576 bytes
// 2 stages = 49152 bytes = 48KB static

template <int EPI, int SPLITOUT>
__global__ void __launch_bounds__(256) gemm_mma(
    const bf16* __restrict__ Ah, const bf16* __restrict__ Al,
    const bf16* __restrict__ Bh, const bf16* __restrict__ Bl,
    float* __restrict__ C, bf16* __restrict__ Chi, bf16* __restrict__ Clo,
    const float* __restrict__ bias, const float* __restrict__ resid,
    int M, int N, int K)
{
    __shared__ char smem_raw[2 * STAGEB];
    uint32_t smem_u = (uint32_t)__cvta_generic_to_shared(smem_raw);

    int tid = threadIdx.x;
    int wid = tid >> 5, lid = tid & 31;
    int wm = wid & 1, wn = wid >> 1;     // 2 x 4 warp grid
    int qr = lid >> 2, qc = lid & 3;
    int bm = blockIdx.y * 128, bn = blockIdx.x * 128;

    const bf16* Ahp = Ah + (size_t)bm * K;
    const bf16* Alp = Al + (size_t)bm * K;
    const bf16* Bhp = Bh + (size_t)bn * K;
    const bf16* Blp = Bl + (size_t)bn * K;

    int NK = K >> 4;    // BK = 16

    int lrow = tid >> 1;            // 0..127
    int lc8  = (tid & 1) << 3;      // 0 or 8
    uint32_t lsoff = ((uint32_t)lrow * ROWP + lc8) * 2u;

    // global -> smem stage loader (cp.async): 1 chunk per matrix per thread
    auto stage_load = [&](int kt, int buf) {
        size_t go = (size_t)lrow * K + (kt << 4) + lc8;
        uint32_t sa = smem_u + buf * STAGEB + lsoff;
        cpa16(sa + 0 * MATB, Ahp + go);
        cpa16(sa + 1 * MATB, Alp + go);
        cpa16(sa + 2 * MATB, Bhp + go);
        cpa16(sa + 3 * MATB, Blp + go);
        cpa_commit();
    };

    float acc[4][4][4] = {};

    stage_load(0, 0);

    for (int kt = 0; kt < NK; kt++) {
        int buf = kt & 1;
        if (kt + 1 < NK) {
            stage_load(kt + 1, buf ^ 1);
            cpa_wait<1>();
        } else {
            cpa_wait<0>();
        }
        __syncthreads();

        const bf16* sAh = (const bf16*)(smem_raw + buf * STAGEB + 0 * MATB);
        const bf16* sAl = (const bf16*)(smem_raw + buf * STAGEB + 1 * MATB);
        const bf16* sBh = (const bf16*)(smem_raw + buf * STAGEB + 2 * MATB);
        const bf16* sBl = (const bf16*)(smem_raw + buf * STAGEB + 3 * MATB);

        int cA = qc * 2;
        uint32_t fah[4][4], fal[4][4];
        #pragma unroll
        for (int mi = 0; mi < 4; mi++) {
            int r0 = wm * 64 + mi * 16 + qr;
            fah[mi][0] = *(const uint32_t*)&sAh[r0 * ROWP + cA];
            fah[mi][1] = *(const uint32_t*)&sAh[(r0 + 8) * ROWP + cA];
            fah[mi][2] = *(const uint32_t*)&sAh[r0 * ROWP + cA + 8];
            fah[mi][3] = *(const uint32_t*)&sAh[(r0 + 8) * ROWP + cA + 8];
            fal[mi][0] = *(const uint32_t*)&sAl[r0 * ROWP + cA];
            fal[mi][1] = *(const uint32_t*)&sAl[(r0 + 8) * ROWP + cA];
            fal[mi][2] = *(const uint32_t*)&sAl[r0 * ROWP + cA + 8];
            fal[mi][3] = *(const uint32_t*)&sAl[(r0 + 8) * ROWP + cA + 8];
        }
        #pragma unroll
        for (int ni = 0; ni < 4; ni++) {
            int nr = wn * 32 + ni * 8 + qr;
            uint32_t bh0 = *(const uint32_t*)&sBh[nr * ROWP + cA];
            uint32_t bh1 = *(const uint32_t*)&sBh[nr * ROWP + cA + 8];
            uint32_t bl0 = *(const uint32_t*)&sBl[nr * ROWP + cA];
            uint32_t bl1 = *(const uint32_t*)&sBl[nr * ROWP + cA + 8];
            #pragma unroll
            for (int mi = 0; mi < 4; mi++) {
                float* a = acc[mi][ni];
                mma_bf16(a[0], a[1], a[2], a[3],
                         fah[mi][0], fah[mi][1], fah[mi][2], fah[mi][3],
                         bh0, bh1);
                mma_bf16(a[0], a[1], a[2], a[3],
                         fah[mi][0], fah[mi][1], fah[mi][2], fah[mi][3],
                         bl0, bl1);
                mma_bf16(a[0], a[1], a[2], a[3],
                         fal[mi][0], fal[mi][1], fal[mi][2], fal[mi][3],
                         bh0, bh1);
            }
        }
        __syncthreads();
    }

    // Epilogue
    #pragma unroll
    for (int mi = 0; mi < 4; mi++) {
        #pragma unroll
        for (int ni = 0; ni < 4; ni++) {
            int col = bn + wn * 32 + ni * 8 + qc * 2;
            #pragma unroll
            for (int half = 0; half < 2; half++) {
                int row = bm + wm * 64 + mi * 16 + qr + half * 8;
                size_t off = (size_t)row * N + col;
                float v0 = acc[mi][ni][half * 2 + 0];
                float v1 = acc[mi][ni][half * 2 + 1];
                if (EPI != EPI_NONE) {
                    v0 += bias[col];
                    v1 += bias[col + 1];
                }
                if (EPI == EPI_BIAS_GELU) {
                    v0 = gelu_exact(v0);
                    v1 = gelu_exact(v1);
                }
                if (EPI == EPI_BIAS_RESID) {
                    float2 rv = *(const float2*)(resid + off);
                    v0 += rv.x; v1 += rv.y;
                }
                if (!SPLITOUT) {
                    *(float2*)(C + off) = make_float2(v0, v1);
                } else {
                    bf16 h0, l0, h1, l1;
                    split_f32(v0, h0, l0);
                    split_f32(v1, h1, l1);
                    __nv_bfloat162 hh; hh.x = h0; hh.y = h1;
                    __nv_bfloat162 ll; ll.x = l0; ll.y = l1;
                    *(__nv_bfloat162*)(Chi + off) = hh;
                    *(__nv_bfloat162*)(Clo + off) = ll;
                }
            }
        }
    }
}

// ---------------------------------------------------------------------------
// Flash attention (fp32, causal, D=64) -- split bf16 output for proj GEMM
// ---------------------------------------------------------------------------
__global__ void __launch_bounds__(256) attn_k(
    const float* __restrict__ Q, const float* __restrict__ Kk,
    const float* __restrict__ V, bf16* __restrict__ ctxh, bf16* __restrict__ ctxl)
{
    __shared__ float Qs[64][64];
    __shared__ float KP[64][64];
    __shared__ float Vs[64][64];

    int b = blockIdx.z, h = blockIdx.y, it = blockIdx.x;
    int t0 = it * 64;
    size_t bh = ((size_t)(b * NH + h)) * TSEQ * HD;

    int tid = threadIdx.x;
    int ty = tid >> 4, tx = tid & 15;
    int ry = ty << 2, cx = tx << 2;

    #pragma unroll
    for (int k = 0; k < 4; k++) {
        int f = tid + k * 256;
        int r = f >> 4, c4 = (f & 15) << 2;
        float4 q4 = *(const float4*)(Q + bh + (size_t)(t0 + r) * HD + c4);
        Qs[c4 + 0][r] = q4.x; Qs[c4 + 1][r] = q4.y;
        Qs[c4 + 2][r] = q4.z; Qs[c4 + 3][r] = q4.w;
    }

    float m_i[4], l_i[4], o[4][4];
    #pragma unroll
    for (int i = 0; i < 4; i++) {
        m_i[i] = -1e30f; l_i[i] = 0.f;
        #pragma unroll
        for (int j = 0; j < 4; j++) o[i][j] = 0.f;
    }

    int nk = it + 1;
    for (int kt = 0; kt < nk; kt++) {
        int k0 = kt * 64;
        __syncthreads();
        #pragma unroll
        for (int k = 0; k < 4; k++) {
            int f = tid + k * 256;
            int r = f >> 4, c4 = (f & 15) << 2;
            float4 k4 = *(const float4*)(Kk + bh + (size_t)(k0 + r) * HD + c4);
            KP[c4 + 0][r] = k4.x; KP[c4 + 1][r] = k4.y;
            KP[c4 + 2][r] = k4.z; KP[c4 + 3][r] = k4.w;
            float4 v4 = *(const float4*)(V + bh + (size_t)(k0 + r) * HD + c4);
            *(float4*)&Vs[r][c4] = v4;
        }
        __syncthreads();

        float s[4][4] = {};
        #pragma unroll 8
        for (int k = 0; k < 64; k++) {
            float a[4], bb[4];
            *(float4*)a  = *(const float4*)&Qs[k][ry];
            *(float4*)bb = *(const float4*)&KP[k][cx];
            #pragma unroll
            for (int i = 0; i < 4; i++)
                #pragma unroll
                for (int j = 0; j < 4; j++)
                    s[i][j] += a[i] * bb[j];
        }

        bool diag = (kt == nk - 1);
        #pragma unroll
        for (int i = 0; i < 4; i++)
            #pragma unroll
            for (int j = 0; j < 4; j++) {
                s[i][j] *= 0.125f;
                if (diag && (k0 + cx + j) > (t0 + ry + i)) s[i][j] = -1e30f;
            }

        #pragma unroll
        for (int i = 0; i < 4; i++) {
            float mx = fmaxf(fmaxf(s[i][0], s[i][1]), fmaxf(s[i][2], s[i][3]));
            #pragma unroll
            for (int off = 8; off >= 1; off >>= 1)
                mx = fmaxf(mx, __shfl_xor_sync(0xffffffffu, mx, off));
            float mn = fmaxf(m_i[i], mx);
            float alpha = expf(m_i[i] - mn);
            m_i[i] = mn;
            float sum = 0.f;
            #pragma unroll
            for (int j = 0; j < 4; j++) {
                s[i][j] = expf(s[i][j] - mn);
                sum += s[i][j];
            }
            #pragma unroll
            for (int off = 8; off >= 1; off >>= 1)
                sum += __shfl_xor_sync(0xffffffffu, sum, off);
            l_i[i] = l_i[i] * alpha + sum;
            #pragma unroll
            for (int j = 0; j < 4; j++) o[i][j] *= alpha;
        }

        __syncthreads();
        #pragma unroll
        for (int i = 0; i < 4; i++)
            #pragma unroll
            for (int j = 0; j < 4; j++)
                KP[cx + j][ry + i] = s[i][j];
        __syncthreads();

        #pragma unroll 8
        for (int ss = 0; ss < 64; ss++) {
            float p[4], vv[4];
            *(float4*)p  = *(const float4*)&KP[ss][ry];
            *(float4*)vv = *(const float4*)&Vs[ss][cx];
            #pragma unroll
            for (int i = 0; i < 4; i++)
                #pragma unroll
                for (int j = 0; j < 4; j++)
                    o[i][j] += p[i] * vv[j];
        }
    }

    #pragma unroll
    for (int i = 0; i < 4; i++) {
        float inv = 1.0f / l_i[i];
        int r = t0 + ry + i;
        size_t base = ((size_t)(b * TSEQ + r)) * CEMB + h * HD + cx;
        #pragma unroll
        for (int j = 0; j < 4; j++) {
            bf16 hh, ll;
            split_f32(o[i][j] * inv, hh, ll);
            ctxh[base + j] = hh;
            ctxl[base + j] = ll;
        }
    }
}

// ---------------------------------------------------------------------------
// Launch
// ---------------------------------------------------------------------------
static float* sym(const void* s)
{
    void* p = nullptr;
    cudaGetSymbolAddress(&p, s);
    return (float*)p;
}
static bf16* symb(const void* s)
{
    void* p = nullptr;
    cudaGetSymbolAddress(&p, s);
    return (bf16*)p;
}

extern "C" void kernel_launch(void* const* d_in, const int* in_sizes, int n_in,
                              void* d_out, int out_size)
{
    const float* x      = (const float*)d_in[0];
    const float* ln1_w  = (const float*)d_in[1];
    const float* ln1_b  = (const float*)d_in[2];
    const float* ln2_w  = (const float*)d_in[3];
    const float* ln2_b  = (const float*)d_in[4];
    const float* q_w    = (const float*)d_in[5];
    const float* kvd_w  = (const float*)d_in[6];
    const float* kvln_w = (const float*)d_in[7];
    const float* kvln_b = (const float*)d_in[8];
    const float* kvu_w  = (const float*)d_in[9];
    const float* proj_w = (const float*)d_in[10];
    const float* proj_b = (const float*)d_in[11];
    const float* f1_w   = (const float*)d_in[12];
    const float* f1_b   = (const float*)d_in[13];
    const float* f2_w   = (const float*)d_in[14];
    const float* f2_b   = (const float*)d_in[15];
    float* out = (float*)d_out;

    float* qlin  = sym(g_qlin);
    float* ckv   = sym(g_ckv);
    float* kvlin = sym(g_kvlin);
    float* q     = sym(g_q);
    float* k     = sym(g_k);
    float* v     = sym(g_v);
    float* x1    = sym(g_x1);
    float* ct    = sym(g_cos);
    float* st    = sym(g_sin);
    bf16 *hh = symb(g_h_h),  *hl = symb(g_h_l);
    bf16 *ch = symb(g_ckv_h), *cl = symb(g_ckv_l);
    bf16 *xh = symb(g_ctx_h), *xl = symb(g_ctx_l);
    bf16 *h2h = symb(g_h2_h), *h2l = symb(g_h2_l);
    bf16 *fh = symb(g_ff1_h), *fl = symb(g_ff1_l);
    bf16 *wqh = symb(g_wq_h),  *wql = symb(g_wq_l);
    bf16 *wdh = symb(g_wkvd_h), *wdl = symb(g_wkvd_l);
    bf16 *wuh = symb(g_wkvu_h), *wul = symb(g_wkvu_l);
    bf16 *wph = symb(g_wpr_h),  *wpl = symb(g_wpr_l);
    bf16 *w1h = symb(g_wf1_h),  *w1l = symb(g_wf1_l);
    bf16 *w2h = symb(g_wf2_h),  *w2l = symb(g_wf2_l);

    // weight preprocess
    prep_w<<<dim3(CEMB / 32, CEMB / 32), 256>>>(q_w, wqh, wql, CEMB, CEMB);
    prep_w<<<dim3(RKV / 32, CEMB / 32), 256>>>(kvd_w, wdh, wdl, CEMB, RKV);
    prep_w<<<dim3(2 * CEMB / 32, RKV / 32), 256>>>(kvu_w, wuh, wul, RKV, 2 * CEMB);
    prep_w<<<dim3(CEMB / 32, CEMB / 32), 256>>>(proj_w, wph, wpl, CEMB, CEMB);
    prep_w<<<dim3(FF / 32, CEMB / 32), 256>>>(f1_w, w1h, w1l, CEMB, FF);
    prep_w<<<dim3(CEMB / 32, FF / 32), 256>>>(f2_w, w2h, w2l, FF, CEMB);

    // 1) h = LN1(x) -> split bf16
    ln_k<true><<<MROWS, 256>>>(x, ln1_w, ln1_b, nullptr, hh, hl, CEMB);
    // 2) qlin = h @ q_w
    gemm_mma<EPI_NONE, 0><<<dim3(CEMB / 128, MROWS / 128), 256>>>(
        hh, hl, wqh, wql, qlin, nullptr, nullptr, nullptr, nullptr,
        MROWS, CEMB, CEMB);
    // 3) ckv = h @ kvd_w (fp32)
    gemm_mma<EPI_NONE, 0><<<dim3(RKV / 128, MROWS / 128), 256>>>(
        hh, hl, wdh, wdl, ckv, nullptr, nullptr, nullptr, nullptr,
        MROWS, RKV, CEMB);
    // 4) ckv = LN_kv(ckv) -> split bf16
    ln_k<true><<<MROWS, 256>>>(ckv, kvln_w, kvln_b, nullptr, ch, cl, RKV);
    // 5) kvlin = ckv @ kvu_w
    gemm_mma<EPI_NONE, 0><<<dim3(2 * CEMB / 128, MROWS / 128), 256>>>(
        ch, cl, wuh, wul, kvlin, nullptr, nullptr, nullptr, nullptr,
        MROWS, 2 * CEMB, RKV);
    // 6/7) rope
    rope_tab_k<<<(TSEQ * 32 + 255) / 256, 256>>>(ct, st);
    rope_qkv_k<<<(BSZ * TSEQ * NH * 32) / 256, 256>>>(qlin, kvlin, ct, st, q, k, v);
    // 8) flash attention -> ctx split bf16
    attn_k<<<dim3(TSEQ / 64, NH, BSZ), 256>>>(q, k, v, xh, xl);
    // 9) x1 = x + ctx @ proj_w + proj_b
    gemm_mma<EPI_BIAS_RESID, 0><<<dim3(CEMB / 128, MROWS / 128), 256>>>(
        xh, xl, wph, wpl, x1, nullptr, nullptr, proj_b, x, MROWS, CEMB, CEMB);
    // 10) h2 = LN2(x1) -> split bf16
    ln_k<true><<<MROWS, 256>>>(x1, ln2_w, ln2_b, nullptr, h2h, h2l, CEMB);
    // 11) ff1 = gelu(h2 @ f1_w + f1_b) -> split bf16
    gemm_mma<EPI_BIAS_GELU, 1><<<dim3(FF / 128, MROWS / 128), 256>>>(
        h2h, h2l, w1h, w1l, nullptr, fh, fl, f1_b, nullptr, MROWS, FF, CEMB);
    // 12) out = x1 + ff1 @ f2_w + f2_b
    gemm_mma<EPI_BIAS_RESID, 0><<<dim3(CEMB / 128, MROWS / 128), 256>>>(
        fh, fl, w2h, w2l, out, nullptr, nullptr, f2_b, x1, MROWS, CEMB, FF);
}

// round 6
// speedup vs baseline: 2.0892x; 1.4151x over previous
#include <cuda_runtime.h>
#include <cuda_bf16.h>
#include <math.h>
#include <stdint.h>

// ---------------------------------------------------------------------------
// Problem constants
// ---------------------------------------------------------------------------
#define BSZ   4
#define TSEQ  2048
#define CEMB  1024
#define NH    16
#define HD    64
#define RKV   512
#define FF    4096
#define MROWS (BSZ * TSEQ)   // 8192

typedef __nv_bfloat16 bf16;

// ---------------------------------------------------------------------------
// Scratch (static __device__ arrays -- allocation-free per harness rules)
// ---------------------------------------------------------------------------
__device__ float g_qlin [MROWS * CEMB];
__device__ float g_ckv  [MROWS * RKV];
__device__ float g_kvlin[MROWS * 2 * CEMB];
__device__ float g_x1   [MROWS * CEMB];
__device__ float g_cos  [TSEQ * 32];
__device__ float g_sin  [TSEQ * 32];
// bf16 split activations
__device__ bf16 g_h_h  [MROWS * CEMB];
__device__ bf16 g_h_l  [MROWS * CEMB];
__device__ bf16 g_ckv_h[MROWS * RKV];
__device__ bf16 g_ckv_l[MROWS * RKV];
__device__ bf16 g_ctx_h[MROWS * CEMB];
__device__ bf16 g_ctx_l[MROWS * CEMB];
__device__ bf16 g_h2_h [MROWS * CEMB];
__device__ bf16 g_h2_l [MROWS * CEMB];
__device__ bf16 g_ff1_h[MROWS * FF];
__device__ bf16 g_ff1_l[MROWS * FF];
// split q/k/v in [B,H,T,D]
__device__ bf16 g_qh[MROWS * CEMB];
__device__ bf16 g_ql[MROWS * CEMB];
__device__ bf16 g_kh[MROWS * CEMB];
__device__ bf16 g_kl[MROWS * CEMB];
__device__ bf16 g_vh[MROWS * CEMB];
__device__ bf16 g_vl[MROWS * CEMB];
// bf16 split transposed weights [N,K]
__device__ bf16 g_wq_h  [CEMB * CEMB];
__device__ bf16 g_wq_l  [CEMB * CEMB];
__device__ bf16 g_wkvd_h[RKV * CEMB];
__device__ bf16 g_wkvd_l[RKV * CEMB];
__device__ bf16 g_wkvu_h[2 * CEMB * RKV];
__device__ bf16 g_wkvu_l[2 * CEMB * RKV];
__device__ bf16 g_wpr_h [CEMB * CEMB];
__device__ bf16 g_wpr_l [CEMB * CEMB];
__device__ bf16 g_wf1_h [FF * CEMB];
__device__ bf16 g_wf1_l [FF * CEMB];
__device__ bf16 g_wf2_h [CEMB * FF];
__device__ bf16 g_wf2_l [CEMB * FF];

// ---------------------------------------------------------------------------
// Helpers
// ---------------------------------------------------------------------------
__device__ __forceinline__ void split_f32(float x, bf16& h, bf16& l)
{
    h = __float2bfloat16_rn(x);
    l = __float2bfloat16_rn(x - __bfloat162float(h));
}
__device__ __forceinline__ void split2(float x, float y, uint32_t& h2, uint32_t& l2)
{
    bf16 hx, lx, hy, ly;
    split_f32(x, hx, lx);
    split_f32(y, hy, ly);
    __nv_bfloat162 H; H.x = hx; H.y = hy;
    __nv_bfloat162 L; L.x = lx; L.y = ly;
    h2 = *(uint32_t*)&H;
    l2 = *(uint32_t*)&L;
}
__device__ __forceinline__ float gelu_exact(float x)
{
    return 0.5f * x * (1.0f + erff(x * 0.70710678118654752f));
}
__device__ __forceinline__ void cpa16(uint32_t saddr, const void* g)
{
    asm volatile("cp.async.cg.shared.global [%0], [%1], 16;"
                 :: "r"(saddr), "l"(g) : "memory");
}
__device__ __forceinline__ void cpa_commit()
{
    asm volatile("cp.async.commit_group;" ::: "memory");
}
template <int N>
__device__ __forceinline__ void cpa_wait()
{
    asm volatile("cp.async.wait_group %0;" :: "n"(N) : "memory");
}
__device__ __forceinline__ void mma_bf16(float& c0, float& c1, float& c2, float& c3,
                                         uint32_t a0, uint32_t a1, uint32_t a2,
                                         uint32_t a3, uint32_t b0, uint32_t b1)
{
    asm volatile(
        "mma.sync.aligned.m16n8k16.row.col.f32.bf16.bf16.f32 "
        "{%0,%1,%2,%3}, {%4,%5,%6,%7}, {%8,%9}, {%0,%1,%2,%3};"
        : "+f"(c0), "+f"(c1), "+f"(c2), "+f"(c3)
        : "r"(a0), "r"(a1), "r"(a2), "r"(a3), "r"(b0), "r"(b1));
}
__device__ __forceinline__ void ldm4(uint32_t& r0, uint32_t& r1, uint32_t& r2,
                                     uint32_t& r3, uint32_t a)
{
    asm volatile("ldmatrix.sync.aligned.m8n8.x4.shared.b16 {%0,%1,%2,%3}, [%4];"
                 : "=r"(r0), "=r"(r1), "=r"(r2), "=r"(r3) : "r"(a));
}
__device__ __forceinline__ void ldm4t(uint32_t& r0, uint32_t& r1, uint32_t& r2,
                                      uint32_t& r3, uint32_t a)
{
    asm volatile("ldmatrix.sync.aligned.m8n8.x4.trans.shared.b16 {%0,%1,%2,%3}, [%4];"
                 : "=r"(r0), "=r"(r1), "=r"(r2), "=r"(r3) : "r"(a));
}

// ---------------------------------------------------------------------------
// LayerNorm (optionally writing split bf16 output)
// ---------------------------------------------------------------------------
template <bool SPLIT>
__global__ void __launch_bounds__(256) ln_k(const float* __restrict__ x,
                                            const float* __restrict__ w,
                                            const float* __restrict__ b,
                                            float* __restrict__ out,
                                            bf16* __restrict__ oh,
                                            bf16* __restrict__ ol, int W)
{
    size_t row = blockIdx.x;
    const float* xr = x + row * (size_t)W;

    float s = 0.f, s2 = 0.f;
    for (int i = threadIdx.x << 2; i < W; i += 256 * 4) {
        float4 v = *(const float4*)(xr + i);
        s  += v.x + v.y + v.z + v.w;
        s2 += v.x * v.x + v.y * v.y + v.z * v.z + v.w * v.w;
    }
    __shared__ float sh[8][2];
    #pragma unroll
    for (int off = 16; off; off >>= 1) {
        s  += __shfl_xor_sync(0xffffffffu, s,  off);
        s2 += __shfl_xor_sync(0xffffffffu, s2, off);
    }
    int wrp = threadIdx.x >> 5, ln = threadIdx.x & 31;
    if (ln == 0) { sh[wrp][0] = s; sh[wrp][1] = s2; }
    __syncthreads();
    s = 0.f; s2 = 0.f;
    #pragma unroll
    for (int i = 0; i < 8; i++) { s += sh[i][0]; s2 += sh[i][1]; }

    float invW = 1.0f / (float)W;
    float mu   = s * invW;
    float var  = s2 * invW - mu * mu;
    float rstd = rsqrtf(var + 1e-5f);

    for (int i = threadIdx.x << 2; i < W; i += 256 * 4) {
        float4 v  = *(const float4*)(xr + i);
        float4 wv = *(const float4*)(w + i);
        float4 bv = *(const float4*)(b + i);
        float r0 = (v.x - mu) * rstd * wv.x + bv.x;
        float r1 = (v.y - mu) * rstd * wv.y + bv.y;
        float r2 = (v.z - mu) * rstd * wv.z + bv.z;
        float r3 = (v.w - mu) * rstd * wv.w + bv.w;
        if (!SPLIT) {
            *(float4*)(out + row * (size_t)W + i) = make_float4(r0, r1, r2, r3);
        } else {
            uint32_t h0, l0, h1, l1;
            split2(r0, r1, h0, l0);
            split2(r2, r3, h1, l1);
            *(uint32_t*)(oh + row * (size_t)W + i)     = h0;
            *(uint32_t*)(oh + row * (size_t)W + i + 2) = h1;
            *(uint32_t*)(ol + row * (size_t)W + i)     = l0;
            *(uint32_t*)(ol + row * (size_t)W + i + 2) = l1;
        }
    }
}

// ---------------------------------------------------------------------------
// Weight preprocess: W[K,N] -> Th/Tl [N,K] bf16 hi/lo (tiled transpose)
// ---------------------------------------------------------------------------
__global__ void __launch_bounds__(256) prep_w(const float* __restrict__ W,
                                              bf16* __restrict__ Th,
                                              bf16* __restrict__ Tl,
                                              int K, int N)
{
    __shared__ float t[32][33];
    int nb = blockIdx.x * 32, kb = blockIdx.y * 32;
    int tx = threadIdx.x & 31, ty = threadIdx.x >> 5;  // 32 x 8
    #pragma unroll
    for (int j = 0; j < 32; j += 8)
        t[ty + j][tx] = W[(size_t)(kb + ty + j) * N + nb + tx];
    __syncthreads();
    #pragma unroll
    for (int j = 0; j < 32; j += 8) {
        float v = t[tx][ty + j];
        bf16 h, l;
        split_f32(v, h, l);
        size_t o = (size_t)(nb + ty + j) * K + kb + tx;
        Th[o] = h; Tl[o] = l;
    }
}

// ---------------------------------------------------------------------------
// RoPE table + fused RoPE/transpose -> split bf16 q/k/v in [B,H,T,D]
// ---------------------------------------------------------------------------
__global__ void rope_tab_k(float* __restrict__ ct, float* __restrict__ st)
{
    int idx = blockIdx.x * blockDim.x + threadIdx.x;
    if (idx >= TSEQ * 32) return;
    int t = idx >> 5, d = idx & 31;
    float inv = (float)pow(10000.0, -(double)d / 32.0);
    float ang = (float)t * inv;
    ct[idx] = (float)cos((double)ang);
    st[idx] = (float)sin((double)ang);
}

__global__ void __launch_bounds__(256) rope_qkv_k(
    const float* __restrict__ qlin, const float* __restrict__ kvlin,
    const float* __restrict__ ct, const float* __restrict__ st,
    bf16* __restrict__ qh, bf16* __restrict__ ql,
    bf16* __restrict__ kh, bf16* __restrict__ kl,
    bf16* __restrict__ vh, bf16* __restrict__ vl)
{
    int g = blockIdx.x * blockDim.x + threadIdx.x;
    int d = g & 31;
    int h = (g >> 5) & 15;
    int t = (g >> 9) & 2047;
    int b = g >> 20;

    float c = ct[t * 32 + d];
    float s = st[t * 32 + d];

    const float* qlp = qlin + ((size_t)(b * TSEQ + t)) * CEMB + h * HD;
    const float* klp = kvlin + ((size_t)(b * TSEQ + t)) * (2 * CEMB) + h * HD;
    const float* vlp = klp + CEMB;

    size_t o = (((size_t)(b * NH + h)) * TSEQ + t) * HD;

    float q0 = qlp[d], q1 = qlp[d + 32];
    float qa = q0 * c - q1 * s, qb = q1 * c + q0 * s;
    float k0 = klp[d], k1 = klp[d + 32];
    float ka = k0 * c - k1 * s, kb = k1 * c + k0 * s;
    float va = vlp[d], vb = vlp[d + 32];

    bf16 hh, ll;
    split_f32(qa, hh, ll); qh[o + d] = hh;      ql[o + d] = ll;
    split_f32(qb, hh, ll); qh[o + d + 32] = hh; ql[o + d + 32] = ll;
    split_f32(ka, hh, ll); kh[o + d] = hh;      kl[o + d] = ll;
    split_f32(kb, hh, ll); kh[o + d + 32] = hh; kl[o + d + 32] = ll;
    split_f32(va, hh, ll); vh[o + d] = hh;      vl[o + d] = ll;
    split_f32(vb, hh, ll); vh[o + d + 32] = hh; vl[o + d + 32] = ll;
}

// ---------------------------------------------------------------------------
// mma.sync split-bf16 GEMM (unchanged from passing Round-5 kernel)
// ---------------------------------------------------------------------------
#define EPI_NONE       0
#define EPI_BIAS_RESID 1
#define EPI_BIAS_GELU  2

#define ROWP   24
#define MATB   (128 * ROWP * 2)
#define STAGEB (4 * MATB)

template <int EPI, int SPLITOUT>
__global__ void __launch_bounds__(256) gemm_mma(
    const bf16* __restrict__ Ah, const bf16* __restrict__ Al,
    const bf16* __restrict__ Bh, const bf16* __restrict__ Bl,
    float* __restrict__ C, bf16* __restrict__ Chi, bf16* __restrict__ Clo,
    const float* __restrict__ bias, const float* __restrict__ resid,
    int M, int N, int K)
{
    __shared__ char smem_raw[2 * STAGEB];
    uint32_t smem_u = (uint32_t)__cvta_generic_to_shared(smem_raw);

    int tid = threadIdx.x;
    int wid = tid >> 5, lid = tid & 31;
    int wm = wid & 1, wn = wid >> 1;
    int qr = lid >> 2, qc = lid & 3;
    int bm = blockIdx.y * 128, bn = blockIdx.x * 128;

    const bf16* Ahp = Ah + (size_t)bm * K;
    const bf16* Alp = Al + (size_t)bm * K;
    const bf16* Bhp = Bh + (size_t)bn * K;
    const bf16* Blp = Bl + (size_t)bn * K;

    int NK = K >> 4;

    int lrow = tid >> 1;
    int lc8  = (tid & 1) << 3;
    uint32_t lsoff = ((uint32_t)lrow * ROWP + lc8) * 2u;

    auto stage_load = [&](int kt, int buf) {
        size_t go = (size_t)lrow * K + (kt << 4) + lc8;
        uint32_t sa = smem_u + buf * STAGEB + lsoff;
        cpa16(sa + 0 * MATB, Ahp + go);
        cpa16(sa + 1 * MATB, Alp + go);
        cpa16(sa + 2 * MATB, Bhp + go);
        cpa16(sa + 3 * MATB, Blp + go);
        cpa_commit();
    };

    float acc[4][4][4] = {};

    stage_load(0, 0);

    for (int kt = 0; kt < NK; kt++) {
        int buf = kt & 1;
        if (kt + 1 < NK) {
            stage_load(kt + 1, buf ^ 1);
            cpa_wait<1>();
        } else {
            cpa_wait<0>();
        }
        __syncthreads();

        const bf16* sAh = (const bf16*)(smem_raw + buf * STAGEB + 0 * MATB);
        const bf16* sAl = (const bf16*)(smem_raw + buf * STAGEB + 1 * MATB);
        const bf16* sBh = (const bf16*)(smem_raw + buf * STAGEB + 2 * MATB);
        const bf16* sBl = (const bf16*)(smem_raw + buf * STAGEB + 3 * MATB);

        int cA = qc * 2;
        uint32_t fah[4][4], fal[4][4];
        #pragma unroll
        for (int mi = 0; mi < 4; mi++) {
            int r0 = wm * 64 + mi * 16 + qr;
            fah[mi][0] = *(const uint32_t*)&sAh[r0 * ROWP + cA];
            fah[mi][1] = *(const uint32_t*)&sAh[(r0 + 8) * ROWP + cA];
            fah[mi][2] = *(const uint32_t*)&sAh[r0 * ROWP + cA + 8];
            fah[mi][3] = *(const uint32_t*)&sAh[(r0 + 8) * ROWP + cA + 8];
            fal[mi][0] = *(const uint32_t*)&sAl[r0 * ROWP + cA];
            fal[mi][1] = *(const uint32_t*)&sAl[(r0 + 8) * ROWP + cA];
            fal[mi][2] = *(const uint32_t*)&sAl[r0 * ROWP + cA + 8];
            fal[mi][3] = *(const uint32_t*)&sAl[(r0 + 8) * ROWP + cA + 8];
        }
        #pragma unroll
        for (int ni = 0; ni < 4; ni++) {
            int nr = wn * 32 + ni * 8 + qr;
            uint32_t bh0 = *(const uint32_t*)&sBh[nr * ROWP + cA];
            uint32_t bh1 = *(const uint32_t*)&sBh[nr * ROWP + cA + 8];
            uint32_t bl0 = *(const uint32_t*)&sBl[nr * ROWP + cA];
            uint32_t bl1 = *(const uint32_t*)&sBl[nr * ROWP + cA + 8];
            #pragma unroll
            for (int mi = 0; mi < 4; mi++) {
                float* a = acc[mi][ni];
                mma_bf16(a[0], a[1], a[2], a[3],
                         fah[mi][0], fah[mi][1], fah[mi][2], fah[mi][3], bh0, bh1);
                mma_bf16(a[0], a[1], a[2], a[3],
                         fah[mi][0], fah[mi][1], fah[mi][2], fah[mi][3], bl0, bl1);
                mma_bf16(a[0], a[1], a[2], a[3],
                         fal[mi][0], fal[mi][1], fal[mi][2], fal[mi][3], bh0, bh1);
            }
        }
        __syncthreads();
    }

    #pragma unroll
    for (int mi = 0; mi < 4; mi++) {
        #pragma unroll
        for (int ni = 0; ni < 4; ni++) {
            int col = bn + wn * 32 + ni * 8 + qc * 2;
            #pragma unroll
            for (int half = 0; half < 2; half++) {
                int row = bm + wm * 64 + mi * 16 + qr + half * 8;
                size_t off = (size_t)row * N + col;
                float v0 = acc[mi][ni][half * 2 + 0];
                float v1 = acc[mi][ni][half * 2 + 1];
                if (EPI != EPI_NONE) {
                    v0 += bias[col];
                    v1 += bias[col + 1];
                }
                if (EPI == EPI_BIAS_GELU) {
                    v0 = gelu_exact(v0);
                    v1 = gelu_exact(v1);
                }
                if (EPI == EPI_BIAS_RESID) {
                    float2 rv = *(const float2*)(resid + off);
                    v0 += rv.x; v1 += rv.y;
                }
                if (!SPLITOUT) {
                    *(float2*)(C + off) = make_float2(v0, v1);
                } else {
                    uint32_t h2, l2;
                    split2(v0, v1, h2, l2);
                    *(uint32_t*)(Chi + off) = h2;
                    *(uint32_t*)(Clo + off) = l2;
                }
            }
        }
    }
}

// ---------------------------------------------------------------------------
// Flash attention on mma.sync (split bf16, causal, D=64).
// Br=128, Bc=64. 8 warps, each owns 16 Q rows (full-width -> warp-local softmax).
// Q hi/lo in registers; K/V hi/lo single-buffered in 36.9KB static smem.
// 3-pass split for both QK^T and PV; P fragments built in-register from S.
// ---------------------------------------------------------------------------
#define APAD 72
#define KVMAT (64 * APAD * 2)    // 9216 bytes per 64x64 matrix

__global__ void __launch_bounds__(256) attn_mma(
    const bf16* __restrict__ qh_, const bf16* __restrict__ ql_,
    const bf16* __restrict__ kh_, const bf16* __restrict__ kl_,
    const bf16* __restrict__ vh_, const bf16* __restrict__ vl_,
    bf16* __restrict__ ctxh, bf16* __restrict__ ctxl)
{
    __shared__ char sm[4 * KVMAT];   // 36864 bytes
    uint32_t smu = (uint32_t)__cvta_generic_to_shared(sm);

    int b = blockIdx.z, h = blockIdx.y, it = blockIdx.x;
    int t0 = it * 128;
    size_t bh = ((size_t)(b * NH + h)) * TSEQ * HD;

    int tid = threadIdx.x;
    int w = tid >> 5, lid = tid & 31;
    int qr = lid >> 2, qc = lid & 3;

    // ---- stage Q (hi at 0, lo at 2*KVMAT), then ldmatrix into registers ----
    {
        const bf16* srcs[2] = { qh_ + bh + (size_t)t0 * HD,
                                ql_ + bh + (size_t)t0 * HD };
        #pragma unroll
        for (int i = 0; i < 8; i++) {
            int chunk = tid + i * 256;      // 0..2047
            int mat = chunk >> 10;          // 0=hi, 1=lo
            int wi = chunk & 1023;
            int row = wi >> 3, c8 = (wi & 7) << 3;
            cpa16(smu + mat * (2 * KVMAT) + (row * APAD + c8) * 2,
                  srcs[mat] + (size_t)row * HD + c8);
        }
        cpa_commit();
        cpa_wait<0>();
    }
    __syncthreads();

    uint32_t qa_h[4][4], qa_l[4][4];
    {
        int row = w * 16 + ((lid >> 3) & 1) * 8 + (lid & 7);
        int colb = (lid >> 4) * 8;
        #pragma unroll
        for (int ks = 0; ks < 4; ks++) {
            uint32_t off = (uint32_t)(row * APAD + colb + ks * 16) * 2;
            ldm4(qa_h[ks][0], qa_h[ks][1], qa_h[ks][2], qa_h[ks][3], smu + off);
            ldm4(qa_l[ks][0], qa_l[ks][1], qa_l[ks][2], qa_l[ks][3],
                 smu + 2 * KVMAT + off);
        }
    }

    float m_i[2] = { -1e30f, -1e30f };
    float l_i[2] = { 0.f, 0.f };
    float o[8][4] = {};
    float s[8][4];

    // ldmatrix lane address components
    int nrb = ((lid >> 4) & 1) * 8 + (lid & 7);   // K: n-row within 16-group
    int ncb = ((lid >> 3) & 1) * 8;               // K: k-col offset
    int srb = ((lid >> 3) & 1) * 8 + (lid & 7);   // V: s-row within 16-group
    int scb = ((lid >> 4) & 1) * 8;               // V: d-col offset

    int nk = 2 * (it + 1);
    for (int kt = 0; kt < nk; kt++) {
        int k0 = kt * 64;
        __syncthreads();   // prior iter's smem reads (and Q ldmatrix) done
        {
            const bf16* srcs[4] = { kh_ + bh + (size_t)k0 * HD,
                                    kl_ + bh + (size_t)k0 * HD,
                                    vh_ + bh + (size_t)k0 * HD,
                                    vl_ + bh + (size_t)k0 * HD };
            #pragma unroll
            for (int i = 0; i < 8; i++) {
                int chunk = tid + i * 256;   // 0..2047
                int mat = chunk >> 9;        // 0..3: Kh Kl Vh Vl
                int wi = chunk & 511;
                int row = wi >> 3, c8 = (wi & 7) << 3;
                cpa16(smu + mat * KVMAT + (row * APAD + c8) * 2,
                      srcs[mat] + (size_t)row * HD + c8);
            }
            cpa_commit();
            cpa_wait<0>();
        }
        __syncthreads();

        // ---- S = Q K^T (3-pass split) ----
        #pragma unroll
        for (int nt = 0; nt < 8; nt++) {
            s[nt][0] = 0.f; s[nt][1] = 0.f; s[nt][2] = 0.f; s[nt][3] = 0.f;
        }
        #pragma unroll
        for (int ks = 0; ks < 4; ks++) {
            uint32_t kb[8][2];
            #pragma unroll
            for (int g = 0; g < 4; g++) {
                uint32_t a = smu + (uint32_t)((g * 16 + nrb) * APAD + ks * 16 + ncb) * 2;
                ldm4(kb[2 * g][0], kb[2 * g][1], kb[2 * g + 1][0], kb[2 * g + 1][1], a);
            }
            #pragma unroll
            for (int nt = 0; nt < 8; nt++) {
                mma_bf16(s[nt][0], s[nt][1], s[nt][2], s[nt][3],
                         qa_h[ks][0], qa_h[ks][1], qa_h[ks][2], qa_h[ks][3],
                         kb[nt][0], kb[nt][1]);
                mma_bf16(s[nt][0], s[nt][1], s[nt][2], s[nt][3],
                         qa_l[ks][0], qa_l[ks][1], qa_l[ks][2], qa_l[ks][3],
                         kb[nt][0], kb[nt][1]);
            }
            #pragma unroll
            for (int g = 0; g < 4; g++) {
                uint32_t a = smu + KVMAT +
                             (uint32_t)((g * 16 + nrb) * APAD + ks * 16 + ncb) * 2;
                ldm4(kb[2 * g][0], kb[2 * g][1], kb[2 * g + 1][0], kb[2 * g + 1][1], a);
            }
            #pragma unroll
            for (int nt = 0; nt < 8; nt++)
                mma_bf16(s[nt][0], s[nt][1], s[nt][2], s[nt][3],
                         qa_h[ks][0], qa_h[ks][1], qa_h[ks][2], qa_h[ks][3],
                         kb[nt][0], kb[nt][1]);
        }

        // ---- scale + causal mask ----
        int row0 = t0 + w * 16 + qr;
        int row1 = row0 + 8;
        #pragma unroll
        for (int nt = 0; nt < 8; nt++) {
            int col0 = k0 + nt * 8 + qc * 2;
            s[nt][0] = (col0     > row0) ? -1e30f : s[nt][0] * 0.125f;
            s[nt][1] = (col0 + 1 > row0) ? -1e30f : s[nt][1] * 0.125f;
            s[nt][2] = (col0     > row1) ? -1e30f : s[nt][2] * 0.125f;
            s[nt][3] = (col0 + 1 > row1) ? -1e30f : s[nt][3] * 0.125f;
        }

        // ---- online softmax (rows warp-local; reduce over qc lanes) ----
        float mxA = -1e30f, mxB = -1e30f;
        #pragma unroll
        for (int nt = 0; nt < 8; nt++) {
            mxA = fmaxf(mxA, fmaxf(s[nt][0], s[nt][1]));
            mxB = fmaxf(mxB, fmaxf(s[nt][2], s[nt][3]));
        }
        mxA = fmaxf(mxA, __shfl_xor_sync(0xffffffffu, mxA, 1));
        mxA = fmaxf(mxA, __shfl_xor_sync(0xffffffffu, mxA, 2));
        mxB = fmaxf(mxB, __shfl_xor_sync(0xffffffffu, mxB, 1));
        mxB = fmaxf(mxB, __shfl_xor_sync(0xffffffffu, mxB, 2));

        float mnA = fmaxf(m_i[0], mxA), mnB = fmaxf(m_i[1], mxB);
        float aA = expf(m_i[0] - mnA), aB = expf(m_i[1] - mnB);
        m_i[0] = mnA; m_i[1] = mnB;

        float sumA = 0.f, sumB = 0.f;
        #pragma unroll
        for (int nt = 0; nt < 8; nt++) {
            s[nt][0] = expf(s[nt][0] - mnA); sumA += s[nt][0];
            s[nt][1] = expf(s[nt][1] - mnA); sumA += s[nt][1];
            s[nt][2] = expf(s[nt][2] - mnB); sumB += s[nt][2];
            s[nt][3] = expf(s[nt][3] - mnB); sumB += s[nt][3];
        }
        sumA += __shfl_xor_sync(0xffffffffu, sumA, 1);
        sumA += __shfl_xor_sync(0xffffffffu, sumA, 2);
        sumB += __shfl_xor_sync(0xffffffffu, sumB, 1);
        sumB += __shfl_xor_sync(0xffffffffu, sumB, 2);
        l_i[0] = l_i[0] * aA + sumA;
        l_i[1] = l_i[1] * aB + sumB;

        #pragma unroll
        for (int dt = 0; dt < 8; dt++) {
            o[dt][0] *= aA; o[dt][1] *= aA;
            o[dt][2] *= aB; o[dt][3] *= aB;
        }

        // ---- O += P V (3-pass split; P a-frags built from S registers) ----
        #pragma unroll
        for (int ks = 0; ks < 4; ks++) {
            uint32_t pah[4], pal[4];
            split2(s[2 * ks][0],     s[2 * ks][1],     pah[0], pal[0]);
            split2(s[2 * ks][2],     s[2 * ks][3],     pah[1], pal[1]);
            split2(s[2 * ks + 1][0], s[2 * ks + 1][1], pah[2], pal[2]);
            split2(s[2 * ks + 1][2], s[2 * ks + 1][3], pah[3], pal[3]);

            uint32_t vb[8][2];
            #pragma unroll
            for (int g = 0; g < 4; g++) {
                uint32_t a = smu + 2 * KVMAT +
                             (uint32_t)((ks * 16 + srb) * APAD + g * 16 + scb) * 2;
                ldm4t(vb[2 * g][0], vb[2 * g][1], vb[2 * g + 1][0], vb[2 * g + 1][1], a);
            }
            #pragma unroll
            for (int dt = 0; dt < 8; dt++) {
                mma_bf16(o[dt][0], o[dt][1], o[dt][2], o[dt][3],
                         pah[0], pah[1], pah[2], pah[3], vb[dt][0], vb[dt][1]);
                mma_bf16(o[dt][0], o[dt][1], o[dt][2], o[dt][3],
                         pal[0], pal[1], pal[2], pal[3], vb[dt][0], vb[dt][1]);
            }
            #pragma unroll
            for (int g = 0; g < 4; g++) {
                uint32_t a = smu + 3 * KVMAT +
                             (uint32_t)((ks * 16 + srb) * APAD + g * 16 + scb) * 2;
                ldm4t(vb[2 * g][0], vb[2 * g][1], vb[2 * g + 1][0], vb[2 * g + 1][1], a);
            }
            #pragma unroll
            for (int dt = 0; dt < 8; dt++)
                mma_bf16(o[dt][0], o[dt][1], o[dt][2], o[dt][3],
                         pah[0], pah[1], pah[2], pah[3], vb[dt][0], vb[dt][1]);
        }
    }

    // ---- normalize + split + store ctx [B,T,C] ----
    float invA = 1.0f / l_i[0], invB = 1.0f / l_i[1];
    int r0 = t0 + w * 16 + qr, r1 = r0 + 8;
    #pragma unroll
    for (int dt = 0; dt < 8; dt++) {
        int col = h * HD + dt * 8 + qc * 2;
        uint32_t h2, l2;
        split2(o[dt][0] * invA, o[dt][1] * invA, h2, l2);
        size_t off0 = ((size_t)(b * TSEQ + r0)) * CEMB + col;
        *(uint32_t*)(ctxh + off0) = h2;
        *(uint32_t*)(ctxl + off0) = l2;
        split2(o[dt][2] * invB, o[dt][3] * invB, h2, l2);
        size_t off1 = ((size_t)(b * TSEQ + r1)) * CEMB + col;
        *(uint32_t*)(ctxh + off1) = h2;
        *(uint32_t*)(ctxl + off1) = l2;
    }
}

// ---------------------------------------------------------------------------
// Launch
// ---------------------------------------------------------------------------
static float* sym(const void* s)
{
    void* p = nullptr;
    cudaGetSymbolAddress(&p, s);
    return (float*)p;
}
static bf16* symb(const void* s)
{
    void* p = nullptr;
    cudaGetSymbolAddress(&p, s);
    return (bf16*)p;
}

extern "C" void kernel_launch(void* const* d_in, const int* in_sizes, int n_in,
                              void* d_out, int out_size)
{
    const float* x      = (const float*)d_in[0];
    const float* ln1_w  = (const float*)d_in[1];
    const float* ln1_b  = (const float*)d_in[2];
    const float* ln2_w  = (const float*)d_in[3];
    const float* ln2_b  = (const float*)d_in[4];
    const float* q_w    = (const float*)d_in[5];
    const float* kvd_w  = (const float*)d_in[6];
    const float* kvln_w = (const float*)d_in[7];
    const float* kvln_b = (const float*)d_in[8];
    const float* kvu_w  = (const float*)d_in[9];
    const float* proj_w = (const float*)d_in[10];
    const float* proj_b = (const float*)d_in[11];
    const float* f1_w   = (const float*)d_in[12];
    const float* f1_b   = (const float*)d_in[13];
    const float* f2_w   = (const float*)d_in[14];
    const float* f2_b   = (const float*)d_in[15];
    float* out = (float*)d_out;

    float* qlin  = sym(g_qlin);
    float* ckv   = sym(g_ckv);
    float* kvlin = sym(g_kvlin);
    float* x1    = sym(g_x1);
    float* ct    = sym(g_cos);
    float* st    = sym(g_sin);
    bf16 *hh = symb(g_h_h),  *hl = symb(g_h_l);
    bf16 *ch = symb(g_ckv_h), *cl = symb(g_ckv_l);
    bf16 *xh = symb(g_ctx_h), *xl = symb(g_ctx_l);
    bf16 *h2h = symb(g_h2_h), *h2l = symb(g_h2_l);
    bf16 *fh = symb(g_ff1_h), *fl = symb(g_ff1_l);
    bf16 *qh = symb(g_qh), *ql = symb(g_ql);
    bf16 *kh = symb(g_kh), *kl = symb(g_kl);
    bf16 *vh = symb(g_vh), *vl = symb(g_vl);
    bf16 *wqh = symb(g_wq_h),  *wql = symb(g_wq_l);
    bf16 *wdh = symb(g_wkvd_h), *wdl = symb(g_wkvd_l);
    bf16 *wuh = symb(g_wkvu_h), *wul = symb(g_wkvu_l);
    bf16 *wph = symb(g_wpr_h),  *wpl = symb(g_wpr_l);
    bf16 *w1h = symb(g_wf1_h),  *w1l = symb(g_wf1_l);
    bf16 *w2h = symb(g_wf2_h),  *w2l = symb(g_wf2_l);

    // weight preprocess
    prep_w<<<dim3(CEMB / 32, CEMB / 32), 256>>>(q_w, wqh, wql, CEMB, CEMB);
    prep_w<<<dim3(RKV / 32, CEMB / 32), 256>>>(kvd_w, wdh, wdl, CEMB, RKV);
    prep_w<<<dim3(2 * CEMB / 32, RKV / 32), 256>>>(kvu_w, wuh, wul, RKV, 2 * CEMB);
    prep_w<<<dim3(CEMB / 32, CEMB / 32), 256>>>(proj_w, wph, wpl, CEMB, CEMB);
    prep_w<<<dim3(FF / 32, CEMB / 32), 256>>>(f1_w, w1h, w1l, CEMB, FF);
    prep_w<<<dim3(CEMB / 32, FF / 32), 256>>>(f2_w, w2h, w2l, FF, CEMB);

    // 1) h = LN1(x) -> split bf16
    ln_k<true><<<MROWS, 256>>>(x, ln1_w, ln1_b, nullptr, hh, hl, CEMB);
    // 2) qlin = h @ q_w
    gemm_mma<EPI_NONE, 0><<<dim3(CEMB / 128, MROWS / 128), 256>>>(
        hh, hl, wqh, wql, qlin, nullptr, nullptr, nullptr, nullptr,
        MROWS, CEMB, CEMB);
    // 3) ckv = h @ kvd_w (fp32)
    gemm_mma<EPI_NONE, 0><<<dim3(RKV / 128, MROWS / 128), 256>>>(
        hh, hl, wdh, wdl, ckv, nullptr, nullptr, nullptr, nullptr,
        MROWS, RKV, CEMB);
    // 4) ckv = LN_kv(ckv) -> split bf16
    ln_k<true><<<MROWS, 256>>>(ckv, kvln_w, kvln_b, nullptr, ch, cl, RKV);
    // 5) kvlin = ckv @ kvu_w
    gemm_mma<EPI_NONE, 0><<<dim3(2 * CEMB / 128, MROWS / 128), 256>>>(
        ch, cl, wuh, wul, kvlin, nullptr, nullptr, nullptr, nullptr,
        MROWS, 2 * CEMB, RKV);
    // 6/7) rope -> split bf16 q/k/v [B,H,T,D]
    rope_tab_k<<<(TSEQ * 32 + 255) / 256, 256>>>(ct, st);
    rope_qkv_k<<<(BSZ * TSEQ * NH * 32) / 256, 256>>>(qlin, kvlin, ct, st,
                                                      qh, ql, kh, kl, vh, vl);
    // 8) flash attention (mma.sync) -> ctx split bf16
    attn_mma<<<dim3(TSEQ / 128, NH, BSZ), 256>>>(qh, ql, kh, kl, vh, vl, xh, xl);
    // 9) x1 = x + ctx @ proj_w + proj_b
    gemm_mma<EPI_BIAS_RESID, 0><<<dim3(CEMB / 128, MROWS / 128), 256>>>(
        xh, xl, wph, wpl, x1, nullptr, nullptr, proj_b, x, MROWS, CEMB, CEMB);
    // 10) h2 = LN2(x1) -> split bf16
    ln_k<true><<<MROWS, 256>>>(x1, ln2_w, ln2_b, nullptr, h2h, h2l, CEMB);
    // 11) ff1 = gelu(h2 @ f1_w + f1_b) -> split bf16
    gemm_mma<EPI_BIAS_GELU, 1><<<dim3(FF / 128, MROWS / 128), 256>>>(
        h2h, h2l, w1h, w1l, nullptr, fh, fl, f1_b, nullptr, MROWS, FF, CEMB);
    // 12) out = x1 + ff1 @ f2_w + f2_b
    gemm_mma<EPI_BIAS_RESID, 0><<<dim3(CEMB / 128, MROWS / 128), 256>>>(
        fh, fl, w2h, w2l, out, nullptr, nullptr, f2_b, x1, MROWS, CEMB, FF);
}

// round 7
// speedup vs baseline: 2.1067x; 1.0084x over previous
#include <cuda_runtime.h>
#include <cuda_bf16.h>
#include <math.h>
#include <stdint.h>

// ---------------------------------------------------------------------------
// Problem constants
// ---------------------------------------------------------------------------
#define BSZ   4
#define TSEQ  2048
#define CEMB  1024
#define NH    16
#define HD    64
#define RKV   512
#define FF    4096
#define MROWS (BSZ * TSEQ)   // 8192

typedef __nv_bfloat16 bf16;

// ---------------------------------------------------------------------------
// Scratch (static __device__ arrays -- allocation-free per harness rules)
// ---------------------------------------------------------------------------
__device__ float g_qlin [MROWS * CEMB];
__device__ float g_ckv  [MROWS * RKV];
__device__ float g_kvlin[MROWS * 2 * CEMB];
__device__ float g_x1   [MROWS * CEMB];
__device__ float g_cos  [TSEQ * 32];
__device__ float g_sin  [TSEQ * 32];
// bf16 split activations
__device__ bf16 g_h_h  [MROWS * CEMB];
__device__ bf16 g_h_l  [MROWS * CEMB];
__device__ bf16 g_ckv_h[MROWS * RKV];
__device__ bf16 g_ckv_l[MROWS * RKV];
__device__ bf16 g_ctx_h[MROWS * CEMB];
__device__ bf16 g_ctx_l[MROWS * CEMB];
__device__ bf16 g_h2_h [MROWS * CEMB];
__device__ bf16 g_h2_l [MROWS * CEMB];
__device__ bf16 g_ff1_h[MROWS * FF];
__device__ bf16 g_ff1_l[MROWS * FF];
// split q/k/v in [B,H,T,D]
__device__ bf16 g_qh[MROWS * CEMB];
__device__ bf16 g_ql[MROWS * CEMB];
__device__ bf16 g_kh[MROWS * CEMB];
__device__ bf16 g_kl[MROWS * CEMB];
__device__ bf16 g_vh[MROWS * CEMB];
__device__ bf16 g_vl[MROWS * CEMB];
// bf16 split transposed weights [N,K]
__device__ bf16 g_wq_h  [CEMB * CEMB];
__device__ bf16 g_wq_l  [CEMB * CEMB];
__device__ bf16 g_wkvd_h[RKV * CEMB];
__device__ bf16 g_wkvd_l[RKV * CEMB];
__device__ bf16 g_wkvu_h[2 * CEMB * RKV];
__device__ bf16 g_wkvu_l[2 * CEMB * RKV];
__device__ bf16 g_wpr_h [CEMB * CEMB];
__device__ bf16 g_wpr_l [CEMB * CEMB];
__device__ bf16 g_wf1_h [FF * CEMB];
__device__ bf16 g_wf1_l [FF * CEMB];
__device__ bf16 g_wf2_h [CEMB * FF];
__device__ bf16 g_wf2_l [CEMB * FF];

// ---------------------------------------------------------------------------
// Helpers
// ---------------------------------------------------------------------------
__device__ __forceinline__ void split_f32(float x, bf16& h, bf16& l)
{
    h = __float2bfloat16_rn(x);
    l = __float2bfloat16_rn(x - __bfloat162float(h));
}
__device__ __forceinline__ void split2(float x, float y, uint32_t& h2, uint32_t& l2)
{
    bf16 hx, lx, hy, ly;
    split_f32(x, hx, lx);
    split_f32(y, hy, ly);
    __nv_bfloat162 H; H.x = hx; H.y = hy;
    __nv_bfloat162 L; L.x = lx; L.y = ly;
    h2 = *(uint32_t*)&H;
    l2 = *(uint32_t*)&L;
}
__device__ __forceinline__ float gelu_exact(float x)
{
    return 0.5f * x * (1.0f + erff(x * 0.70710678118654752f));
}
__device__ __forceinline__ void cpa16(uint32_t saddr, const void* g)
{
    asm volatile("cp.async.cg.shared.global [%0], [%1], 16;"
                 :: "r"(saddr), "l"(g) : "memory");
}
__device__ __forceinline__ void cpa_commit()
{
    asm volatile("cp.async.commit_group;" ::: "memory");
}
template <int N>
__device__ __forceinline__ void cpa_wait()
{
    asm volatile("cp.async.wait_group %0;" :: "n"(N) : "memory");
}
__device__ __forceinline__ void mma_bf16(float& c0, float& c1, float& c2, float& c3,
                                         uint32_t a0, uint32_t a1, uint32_t a2,
                                         uint32_t a3, uint32_t b0, uint32_t b1)
{
    asm volatile(
        "mma.sync.aligned.m16n8k16.row.col.f32.bf16.bf16.f32 "
        "{%0,%1,%2,%3}, {%4,%5,%6,%7}, {%8,%9}, {%0,%1,%2,%3};"
        : "+f"(c0), "+f"(c1), "+f"(c2), "+f"(c3)
        : "r"(a0), "r"(a1), "r"(a2), "r"(a3), "r"(b0), "r"(b1));
}
__device__ __forceinline__ void ldm4(uint32_t& r0, uint32_t& r1, uint32_t& r2,
                                     uint32_t& r3, uint32_t a)
{
    asm volatile("ldmatrix.sync.aligned.m8n8.x4.shared.b16 {%0,%1,%2,%3}, [%4];"
                 : "=r"(r0), "=r"(r1), "=r"(r2), "=r"(r3) : "r"(a));
}
__device__ __forceinline__ void ldm4t(uint32_t& r0, uint32_t& r1, uint32_t& r2,
                                      uint32_t& r3, uint32_t a)
{
    asm volatile("ldmatrix.sync.aligned.m8n8.x4.trans.shared.b16 {%0,%1,%2,%3}, [%4];"
                 : "=r"(r0), "=r"(r1), "=r"(r2), "=r"(r3) : "r"(a));
}

// ---------------------------------------------------------------------------
// LayerNorm (optionally writing split bf16 output)
// ---------------------------------------------------------------------------
template <bool SPLIT>
__global__ void __launch_bounds__(256) ln_k(const float* __restrict__ x,
                                            const float* __restrict__ w,
                                            const float* __restrict__ b,
                                            float* __restrict__ out,
                                            bf16* __restrict__ oh,
                                            bf16* __restrict__ ol, int W)
{
    size_t row = blockIdx.x;
    const float* xr = x + row * (size_t)W;

    float s = 0.f, s2 = 0.f;
    for (int i = threadIdx.x << 2; i < W; i += 256 * 4) {
        float4 v = *(const float4*)(xr + i);
        s  += v.x + v.y + v.z + v.w;
        s2 += v.x * v.x + v.y * v.y + v.z * v.z + v.w * v.w;
    }
    __shared__ float sh[8][2];
    #pragma unroll
    for (int off = 16; off; off >>= 1) {
        s  += __shfl_xor_sync(0xffffffffu, s,  off);
        s2 += __shfl_xor_sync(0xffffffffu, s2, off);
    }
    int wrp = threadIdx.x >> 5, ln = threadIdx.x & 31;
    if (ln == 0) { sh[wrp][0] = s; sh[wrp][1] = s2; }
    __syncthreads();
    s = 0.f; s2 = 0.f;
    #pragma unroll
    for (int i = 0; i < 8; i++) { s += sh[i][0]; s2 += sh[i][1]; }

    float invW = 1.0f / (float)W;
    float mu   = s * invW;
    float var  = s2 * invW - mu * mu;
    float rstd = rsqrtf(var + 1e-5f);

    for (int i = threadIdx.x << 2; i < W; i += 256 * 4) {
        float4 v  = *(const float4*)(xr + i);
        float4 wv = *(const float4*)(w + i);
        float4 bv = *(const float4*)(b + i);
        float r0 = (v.x - mu) * rstd * wv.x + bv.x;
        float r1 = (v.y - mu) * rstd * wv.y + bv.y;
        float r2 = (v.z - mu) * rstd * wv.z + bv.z;
        float r3 = (v.w - mu) * rstd * wv.w + bv.w;
        if (!SPLIT) {
            *(float4*)(out + row * (size_t)W + i) = make_float4(r0, r1, r2, r3);
        } else {
            uint32_t h0, l0, h1, l1;
            split2(r0, r1, h0, l0);
            split2(r2, r3, h1, l1);
            *(uint32_t*)(oh + row * (size_t)W + i)     = h0;
            *(uint32_t*)(oh + row * (size_t)W + i + 2) = h1;
            *(uint32_t*)(ol + row * (size_t)W + i)     = l0;
            *(uint32_t*)(ol + row * (size_t)W + i + 2) = l1;
        }
    }
}

// ---------------------------------------------------------------------------
// Weight preprocess: W[K,N] -> Th/Tl [N,K] bf16 hi/lo (tiled transpose)
// ---------------------------------------------------------------------------
__global__ void __launch_bounds__(256) prep_w(const float* __restrict__ W,
                                              bf16* __restrict__ Th,
                                              bf16* __restrict__ Tl,
                                              int K, int N)
{
    __shared__ float t[32][33];
    int nb = blockIdx.x * 32, kb = blockIdx.y * 32;
    int tx = threadIdx.x & 31, ty = threadIdx.x >> 5;  // 32 x 8
    #pragma unroll
    for (int j = 0; j < 32; j += 8)
        t[ty + j][tx] = W[(size_t)(kb + ty + j) * N + nb + tx];
    __syncthreads();
    #pragma unroll
    for (int j = 0; j < 32; j += 8) {
        float v = t[tx][ty + j];
        bf16 h, l;
        split_f32(v, h, l);
        size_t o = (size_t)(nb + ty + j) * K + kb + tx;
        Th[o] = h; Tl[o] = l;
    }
}

// ---------------------------------------------------------------------------
// RoPE table + fused RoPE/transpose -> split bf16 q/k/v in [B,H,T,D]
// ---------------------------------------------------------------------------
__global__ void rope_tab_k(float* __restrict__ ct, float* __restrict__ st)
{
    int idx = blockIdx.x * blockDim.x + threadIdx.x;
    if (idx >= TSEQ * 32) return;
    int t = idx >> 5, d = idx & 31;
    float inv = (float)pow(10000.0, -(double)d / 32.0);
    float ang = (float)t * inv;
    ct[idx] = (float)cos((double)ang);
    st[idx] = (float)sin((double)ang);
}

__global__ void __launch_bounds__(256) rope_qkv_k(
    const float* __restrict__ qlin, const float* __restrict__ kvlin,
    const float* __restrict__ ct, const float* __restrict__ st,
    bf16* __restrict__ qh, bf16* __restrict__ ql,
    bf16* __restrict__ kh, bf16* __restrict__ kl,
    bf16* __restrict__ vh, bf16* __restrict__ vl)
{
    int g = blockIdx.x * blockDim.x + threadIdx.x;
    int d = g & 31;
    int h = (g >> 5) & 15;
    int t = (g >> 9) & 2047;
    int b = g >> 20;

    float c = ct[t * 32 + d];
    float s = st[t * 32 + d];

    const float* qlp = qlin + ((size_t)(b * TSEQ + t)) * CEMB + h * HD;
    const float* klp = kvlin + ((size_t)(b * TSEQ + t)) * (2 * CEMB) + h * HD;
    const float* vlp = klp + CEMB;

    size_t o = (((size_t)(b * NH + h)) * TSEQ + t) * HD;

    float q0 = qlp[d], q1 = qlp[d + 32];
    float qa = q0 * c - q1 * s, qb = q1 * c + q0 * s;
    float k0 = klp[d], k1 = klp[d + 32];
    float ka = k0 * c - k1 * s, kb = k1 * c + k0 * s;
    float va = vlp[d], vb = vlp[d + 32];

    bf16 hh, ll;
    split_f32(qa, hh, ll); qh[o + d] = hh;      ql[o + d] = ll;
    split_f32(qb, hh, ll); qh[o + d + 32] = hh; ql[o + d + 32] = ll;
    split_f32(ka, hh, ll); kh[o + d] = hh;      kl[o + d] = ll;
    split_f32(kb, hh, ll); kh[o + d + 32] = hh; kl[o + d + 32] = ll;
    split_f32(va, hh, ll); vh[o + d] = hh;      vl[o + d] = ll;
    split_f32(vb, hh, ll); vh[o + d + 32] = hh; vl[o + d + 32] = ll;
}

// ---------------------------------------------------------------------------
// mma.sync split-bf16 GEMM: C[M,N] = A[M,K] @ W[N,K]^T, fused epilogues.
// BM=BN=128, BK=16, 8 warps (2x4), warp tile 64x32. 48KB static smem.
// Fragment loads via ldmatrix.x4 (12 per warp-ktile, was 48 LDS.32).
// Pass-outer MMA order: acc reuse distance 16 -> hides HMMA latency.
// ---------------------------------------------------------------------------
#define EPI_NONE       0
#define EPI_BIAS_RESID 1
#define EPI_BIAS_GELU  2

#define ROWP   24
#define MATB   (128 * ROWP * 2)
#define STAGEB (4 * MATB)

template <int EPI, int SPLITOUT>
__global__ void __launch_bounds__(256) gemm_mma(
    const bf16* __restrict__ Ah, const bf16* __restrict__ Al,
    const bf16* __restrict__ Bh, const bf16* __restrict__ Bl,
    float* __restrict__ C, bf16* __restrict__ Chi, bf16* __restrict__ Clo,
    const float* __restrict__ bias, const float* __restrict__ resid,
    int M, int N, int K)
{
    __shared__ char smem_raw[2 * STAGEB];
    uint32_t smem_u = (uint32_t)__cvta_generic_to_shared(smem_raw);

    int tid = threadIdx.x;
    int wid = tid >> 5, lid = tid & 31;
    int wm = wid & 1, wn = wid >> 1;
    int qr = lid >> 2, qc = lid & 3;
    int bm = blockIdx.y * 128, bn = blockIdx.x * 128;

    const bf16* Ahp = Ah + (size_t)bm * K;
    const bf16* Alp = Al + (size_t)bm * K;
    const bf16* Bhp = Bh + (size_t)bn * K;
    const bf16* Blp = Bl + (size_t)bn * K;

    int NK = K >> 4;

    int lrow = tid >> 1;
    int lc8  = (tid & 1) << 3;
    uint32_t lsoff = ((uint32_t)lrow * ROWP + lc8) * 2u;

    auto stage_load = [&](int kt, int buf) {
        size_t go = (size_t)lrow * K + (kt << 4) + lc8;
        uint32_t sa = smem_u + buf * STAGEB + lsoff;
        cpa16(sa + 0 * MATB, Ahp + go);
        cpa16(sa + 1 * MATB, Alp + go);
        cpa16(sa + 2 * MATB, Bhp + go);
        cpa16(sa + 3 * MATB, Blp + go);
        cpa_commit();
    };

    // ldmatrix lane addressing (same mapping validated in attn_mma)
    int arow = wm * 64 + ((lid >> 3) & 1) * 8 + (lid & 7);
    int acol = ((lid >> 4) & 1) * 8;
    uint32_t aoff = ((uint32_t)arow * ROWP + acol) * 2u;
    int brow = wn * 32 + ((lid >> 4) & 1) * 8 + (lid & 7);
    int bcol = ((lid >> 3) & 1) * 8;
    uint32_t boff = ((uint32_t)brow * ROWP + bcol) * 2u;

    float acc[4][4][4] = {};

    stage_load(0, 0);

    for (int kt = 0; kt < NK; kt++) {
        int buf = kt & 1;
        if (kt + 1 < NK) {
            stage_load(kt + 1, buf ^ 1);
            cpa_wait<1>();
        } else {
            cpa_wait<0>();
        }
        __syncthreads();

        uint32_t sAh = smem_u + buf * STAGEB + 0 * MATB;
        uint32_t sAl = smem_u + buf * STAGEB + 1 * MATB;
        uint32_t sBh = smem_u + buf * STAGEB + 2 * MATB;
        uint32_t sBl = smem_u + buf * STAGEB + 3 * MATB;

        uint32_t fah[4][4], fal[4][4], fbh[4][2], fbl[4][2];
        #pragma unroll
        for (int mi = 0; mi < 4; mi++) {
            uint32_t off = aoff + (uint32_t)(mi * 16 * ROWP) * 2u;
            ldm4(fah[mi][0], fah[mi][1], fah[mi][2], fah[mi][3], sAh + off);
            ldm4(fal[mi][0], fal[mi][1], fal[mi][2], fal[mi][3], sAl + off);
        }
        #pragma unroll
        for (int p = 0; p < 2; p++) {
            uint32_t off = boff + (uint32_t)(p * 16 * ROWP) * 2u;
            ldm4(fbh[2 * p][0], fbh[2 * p][1], fbh[2 * p + 1][0], fbh[2 * p + 1][1],
                 sBh + off);
            ldm4(fbl[2 * p][0], fbl[2 * p][1], fbl[2 * p + 1][0], fbl[2 * p + 1][1],
                 sBl + off);
        }

        // pass-outer: hi*hi, hi*lo, lo*hi (acc reuse distance = 16 MMAs)
        #pragma unroll
        for (int ni = 0; ni < 4; ni++)
            #pragma unroll
            for (int mi = 0; mi < 4; mi++)
                mma_bf16(acc[mi][ni][0], acc[mi][ni][1], acc[mi][ni][2], acc[mi][ni][3],
                         fah[mi][0], fah[mi][1], fah[mi][2], fah[mi][3],
                         fbh[ni][0], fbh[ni][1]);
        #pragma unroll
        for (int ni = 0; ni < 4; ni++)
            #pragma unroll
            for (int mi = 0; mi < 4; mi++)
                mma_bf16(acc[mi][ni][0], acc[mi][ni][1], acc[mi][ni][2], acc[mi][ni][3],
                         fah[mi][0], fah[mi][1], fah[mi][2], fah[mi][3],
                         fbl[ni][0], fbl[ni][1]);
        #pragma unroll
        for (int ni = 0; ni < 4; ni++)
            #pragma unroll
            for (int mi = 0; mi < 4; mi++)
                mma_bf16(acc[mi][ni][0], acc[mi][ni][1], acc[mi][ni][2], acc[mi][ni][3],
                         fal[mi][0], fal[mi][1], fal[mi][2], fal[mi][3],
                         fbh[ni][0], fbh[ni][1]);
        __syncthreads();
    }

    #pragma unroll
    for (int mi = 0; mi < 4; mi++) {
        #pragma unroll
        for (int ni = 0; ni < 4; ni++) {
            int col = bn + wn * 32 + ni * 8 + qc * 2;
            #pragma unroll
            for (int half = 0; half < 2; half++) {
                int row = bm + wm * 64 + mi * 16 + qr + half * 8;
                size_t off = (size_t)row * N + col;
                float v0 = acc[mi][ni][half * 2 + 0];
                float v1 = acc[mi][ni][half * 2 + 1];
                if (EPI != EPI_NONE) {
                    v0 += bias[col];
                    v1 += bias[col + 1];
                }
                if (EPI == EPI_BIAS_GELU) {
                    v0 = gelu_exact(v0);
                    v1 = gelu_exact(v1);
                }
                if (EPI == EPI_BIAS_RESID) {
                    float2 rv = *(const float2*)(resid + off);
                    v0 += rv.x; v1 += rv.y;
                }
                if (!SPLITOUT) {
                    *(float2*)(C + off) = make_float2(v0, v1);
                } else {
                    uint32_t h2, l2;
                    split2(v0, v1, h2, l2);
                    *(uint32_t*)(Chi + off) = h2;
                    *(uint32_t*)(Clo + off) = l2;
                }
            }
        }
    }
}

// ---------------------------------------------------------------------------
// Flash attention on mma.sync (unchanged from passing Round-6 kernel)
// ---------------------------------------------------------------------------
#define APAD 72
#define KVMAT (64 * APAD * 2)    // 9216 bytes per 64x64 matrix

__global__ void __launch_bounds__(256) attn_mma(
    const bf16* __restrict__ qh_, const bf16* __restrict__ ql_,
    const bf16* __restrict__ kh_, const bf16* __restrict__ kl_,
    const bf16* __restrict__ vh_, const bf16* __restrict__ vl_,
    bf16* __restrict__ ctxh, bf16* __restrict__ ctxl)
{
    __shared__ char sm[4 * KVMAT];   // 36864 bytes
    uint32_t smu = (uint32_t)__cvta_generic_to_shared(sm);

    int b = blockIdx.z, h = blockIdx.y, it = blockIdx.x;
    int t0 = it * 128;
    size_t bh = ((size_t)(b * NH + h)) * TSEQ * HD;

    int tid = threadIdx.x;
    int w = tid >> 5, lid = tid & 31;
    int qr = lid >> 2, qc = lid & 3;

    // ---- stage Q (hi at 0, lo at 2*KVMAT), then ldmatrix into registers ----
    {
        const bf16* srcs[2] = { qh_ + bh + (size_t)t0 * HD,
                                ql_ + bh + (size_t)t0 * HD };
        #pragma unroll
        for (int i = 0; i < 8; i++) {
            int chunk = tid + i * 256;
            int mat = chunk >> 10;
            int wi = chunk & 1023;
            int row = wi >> 3, c8 = (wi & 7) << 3;
            cpa16(smu + mat * (2 * KVMAT) + (row * APAD + c8) * 2,
                  srcs[mat] + (size_t)row * HD + c8);
        }
        cpa_commit();
        cpa_wait<0>();
    }
    __syncthreads();

    uint32_t qa_h[4][4], qa_l[4][4];
    {
        int row = w * 16 + ((lid >> 3) & 1) * 8 + (lid & 7);
        int colb = (lid >> 4) * 8;
        #pragma unroll
        for (int ks = 0; ks < 4; ks++) {
            uint32_t off = (uint32_t)(row * APAD + colb + ks * 16) * 2;
            ldm4(qa_h[ks][0], qa_h[ks][1], qa_h[ks][2], qa_h[ks][3], smu + off);
            ldm4(qa_l[ks][0], qa_l[ks][1], qa_l[ks][2], qa_l[ks][3],
                 smu + 2 * KVMAT + off);
        }
    }

    float m_i[2] = { -1e30f, -1e30f };
    float l_i[2] = { 0.f, 0.f };
    float o[8][4] = {};
    float s[8][4];

    int nrb = ((lid >> 4) & 1) * 8 + (lid & 7);
    int ncb = ((lid >> 3) & 1) * 8;
    int srb = ((lid >> 3) & 1) * 8 + (lid & 7);
    int scb = ((lid >> 4) & 1) * 8;

    int nk = 2 * (it + 1);
    for (int kt = 0; kt < nk; kt++) {
        int k0 = kt * 64;
        __syncthreads();
        {
            const bf16* srcs[4] = { kh_ + bh + (size_t)k0 * HD,
                                    kl_ + bh + (size_t)k0 * HD,
                                    vh_ + bh + (size_t)k0 * HD,
                                    vl_ + bh + (size_t)k0 * HD };
            #pragma unroll
            for (int i = 0; i < 8; i++) {
                int chunk = tid + i * 256;
                int mat = chunk >> 9;
                int wi = chunk & 511;
                int row = wi >> 3, c8 = (wi & 7) << 3;
                cpa16(smu + mat * KVMAT + (row * APAD + c8) * 2,
                      srcs[mat] + (size_t)row * HD + c8);
            }
            cpa_commit();
            cpa_wait<0>();
        }
        __syncthreads();

        #pragma unroll
        for (int nt = 0; nt < 8; nt++) {
            s[nt][0] = 0.f; s[nt][1] = 0.f; s[nt][2] = 0.f; s[nt][3] = 0.f;
        }
        #pragma unroll
        for (int ks = 0; ks < 4; ks++) {
            uint32_t kb[8][2];
            #pragma unroll
            for (int g = 0; g < 4; g++) {
                uint32_t a = smu + (uint32_t)((g * 16 + nrb) * APAD + ks * 16 + ncb) * 2;
                ldm4(kb[2 * g][0], kb[2 * g][1], kb[2 * g + 1][0], kb[2 * g + 1][1], a);
            }
            #pragma unroll
            for (int nt = 0; nt < 8; nt++) {
                mma_bf16(s[nt][0], s[nt][1], s[nt][2], s[nt][3],
                         qa_h[ks][0], qa_h[ks][1], qa_h[ks][2], qa_h[ks][3],
                         kb[nt][0], kb[nt][1]);
                mma_bf16(s[nt][0], s[nt][1], s[nt][2], s[nt][3],
                         qa_l[ks][0], qa_l[ks][1], qa_l[ks][2], qa_l[ks][3],
                         kb[nt][0], kb[nt][1]);
            }
            #pragma unroll
            for (int g = 0; g < 4; g++) {
                uint32_t a = smu + KVMAT +
                             (uint32_t)((g * 16 + nrb) * APAD + ks * 16 + ncb) * 2;
                ldm4(kb[2 * g][0], kb[2 * g][1], kb[2 * g + 1][0], kb[2 * g + 1][1], a);
            }
            #pragma unroll
            for (int nt = 0; nt < 8; nt++)
                mma_bf16(s[nt][0], s[nt][1], s[nt][2], s[nt][3],
                         qa_h[ks][0], qa_h[ks][1], qa_h[ks][2], qa_h[ks][3],
                         kb[nt][0], kb[nt][1]);
        }

        int row0 = t0 + w * 16 + qr;
        int row1 = row0 + 8;
        #pragma unroll
        for (int nt = 0; nt < 8; nt++) {
            int col0 = k0 + nt * 8 + qc * 2;
            s[nt][0] = (col0     > row0) ? -1e30f : s[nt][0] * 0.125f;
            s[nt][1] = (col0 + 1 > row0) ? -1e30f : s[nt][1] * 0.125f;
            s[nt][2] = (col0     > row1) ? -1e30f : s[nt][2] * 0.125f;
            s[nt][3] = (col0 + 1 > row1) ? -1e30f : s[nt][3] * 0.125f;
        }

        float mxA = -1e30f, mxB = -1e30f;
        #pragma unroll
        for (int nt = 0; nt < 8; nt++) {
            mxA = fmaxf(mxA, fmaxf(s[nt][0], s[nt][1]));
            mxB = fmaxf(mxB, fmaxf(s[nt][2], s[nt][3]));
        }
        mxA = fmaxf(mxA, __shfl_xor_sync(0xffffffffu, mxA, 1));
        mxA = fmaxf(mxA, __shfl_xor_sync(0xffffffffu, mxA, 2));
        mxB = fmaxf(mxB, __shfl_xor_sync(0xffffffffu, mxB, 1));
        mxB = fmaxf(mxB, __shfl_xor_sync(0xffffffffu, mxB, 2));

        float mnA = fmaxf(m_i[0], mxA), mnB = fmaxf(m_i[1], mxB);
        float aA = expf(m_i[0] - mnA), aB = expf(m_i[1] - mnB);
        m_i[0] = mnA; m_i[1] = mnB;

        float sumA = 0.f, sumB = 0.f;
        #pragma unroll
        for (int nt = 0; nt < 8; nt++) {
            s[nt][0] = expf(s[nt][0] - mnA); sumA += s[nt][0];
            s[nt][1] = expf(s[nt][1] - mnA); sumA += s[nt][1];
            s[nt][2] = expf(s[nt][2] - mnB); sumB += s[nt][2];
            s[nt][3] = expf(s[nt][3] - mnB); sumB += s[nt][3];
        }
        sumA += __shfl_xor_sync(0xffffffffu, sumA, 1);
        sumA += __shfl_xor_sync(0xffffffffu, sumA, 2);
        sumB += __shfl_xor_sync(0xffffffffu, sumB, 1);
        sumB += __shfl_xor_sync(0xffffffffu, sumB, 2);
        l_i[0] = l_i[0] * aA + sumA;
        l_i[1] = l_i[1] * aB + sumB;

        #pragma unroll
        for (int dt = 0; dt < 8; dt++) {
            o[dt][0] *= aA; o[dt][1] *= aA;
            o[dt][2] *= aB; o[dt][3] *= aB;
        }

        #pragma unroll
        for (int ks = 0; ks < 4; ks++) {
            uint32_t pah[4], pal[4];
            split2(s[2 * ks][0],     s[2 * ks][1],     pah[0], pal[0]);
            split2(s[2 * ks][2],     s[2 * ks][3],     pah[1], pal[1]);
            split2(s[2 * ks + 1][0], s[2 * ks + 1][1], pah[2], pal[2]);
            split2(s[2 * ks + 1][2], s[2 * ks + 1][3], pah[3], pal[3]);

            uint32_t vb[8][2];
            #pragma unroll
            for (int g = 0; g < 4; g++) {
                uint32_t a = smu + 2 * KVMAT +
                             (uint32_t)((ks * 16 + srb) * APAD + g * 16 + scb) * 2;
                ldm4t(vb[2 * g][0], vb[2 * g][1], vb[2 * g + 1][0], vb[2 * g + 1][1], a);
            }
            #pragma unroll
            for (int dt = 0; dt < 8; dt++) {
                mma_bf16(o[dt][0], o[dt][1], o[dt][2], o[dt][3],
                         pah[0], pah[1], pah[2], pah[3], vb[dt][0], vb[dt][1]);
                mma_bf16(o[dt][0], o[dt][1], o[dt][2], o[dt][3],
                         pal[0], pal[1], pal[2], pal[3], vb[dt][0], vb[dt][1]);
            }
            #pragma unroll
            for (int g = 0; g < 4; g++) {
                uint32_t a = smu + 3 * KVMAT +
                             (uint32_t)((ks * 16 + srb) * APAD + g * 16 + scb) * 2;
                ldm4t(vb[2 * g][0], vb[2 * g][1], vb[2 * g + 1][0], vb[2 * g + 1][1], a);
            }
            #pragma unroll
            for (int dt = 0; dt < 8; dt++)
                mma_bf16(o[dt][0], o[dt][1], o[dt][2], o[dt][3],
                         pah[0], pah[1], pah[2], pah[3], vb[dt][0], vb[dt][1]);
        }
    }

    float invA = 1.0f / l_i[0], invB = 1.0f / l_i[1];
    int r0 = t0 + w * 16 + qr, r1 = r0 + 8;
    #pragma unroll
    for (int dt = 0; dt < 8; dt++) {
        int col = h * HD + dt * 8 + qc * 2;
        uint32_t h2, l2;
        split2(o[dt][0] * invA, o[dt][1] * invA, h2, l2);
        size_t off0 = ((size_t)(b * TSEQ + r0)) * CEMB + col;
        *(uint32_t*)(ctxh + off0) = h2;
        *(uint32_t*)(ctxl + off0) = l2;
        split2(o[dt][2] * invB, o[dt][3] * invB, h2, l2);
        size_t off1 = ((size_t)(b * TSEQ + r1)) * CEMB + col;
        *(uint32_t*)(ctxh + off1) = h2;
        *(uint32_t*)(ctxl + off1) = l2;
    }
}

// ---------------------------------------------------------------------------
// Launch (reordered so ncu -s 5 -c 1 captures the main GEMM at index 5)
// ---------------------------------------------------------------------------
static float* sym(const void* s)
{
    void* p = nullptr;
    cudaGetSymbolAddress(&p, s);
    return (float*)p;
}
static bf16* symb(const void* s)
{
    void* p = nullptr;
    cudaGetSymbolAddress(&p, s);
    return (bf16*)p;
}

extern "C" void kernel_launch(void* const* d_in, const int* in_sizes, int n_in,
                              void* d_out, int out_size)
{
    const float* x      = (const float*)d_in[0];
    const float* ln1_w  = (const float*)d_in[1];
    const float* ln1_b  = (const float*)d_in[2];
    const float* ln2_w  = (const float*)d_in[3];
    const float* ln2_b  = (const float*)d_in[4];
    const float* q_w    = (const float*)d_in[5];
    const float* kvd_w  = (const float*)d_in[6];
    const float* kvln_w = (const float*)d_in[7];
    const float* kvln_b = (const float*)d_in[8];
    const float* kvu_w  = (const float*)d_in[9];
    const float* proj_w = (const float*)d_in[10];
    const float* proj_b = (const float*)d_in[11];
    const float* f1_w   = (const float*)d_in[12];
    const float* f1_b   = (const float*)d_in[13];
    const float* f2_w   = (const float*)d_in[14];
    const float* f2_b   = (const float*)d_in[15];
    float* out = (float*)d_out;

    float* qlin  = sym(g_qlin);
    float* ckv   = sym(g_ckv);
    float* kvlin = sym(g_kvlin);
    float* x1    = sym(g_x1);
    float* ct    = sym(g_cos);
    float* st    = sym(g_sin);
    bf16 *hh = symb(g_h_h),  *hl = symb(g_h_l);
    bf16 *ch = symb(g_ckv_h), *cl = symb(g_ckv_l);
    bf16 *xh = symb(g_ctx_h), *xl = symb(g_ctx_l);
    bf16 *h2h = symb(g_h2_h), *h2l = symb(g_h2_l);
    bf16 *fh = symb(g_ff1_h), *fl = symb(g_ff1_l);
    bf16 *qh = symb(g_qh), *ql = symb(g_ql);
    bf16 *kh = symb(g_kh), *kl = symb(g_kl);
    bf16 *vh = symb(g_vh), *vl = symb(g_vl);
    bf16 *wqh = symb(g_wq_h),  *wql = symb(g_wq_l);
    bf16 *wdh = symb(g_wkvd_h), *wdl = symb(g_wkvd_l);
    bf16 *wuh = symb(g_wkvu_h), *wul = symb(g_wkvu_l);
    bf16 *wph = symb(g_wpr_h),  *wpl = symb(g_wpr_l);
    bf16 *w1h = symb(g_wf1_h),  *w1l = symb(g_wf1_l);
    bf16 *w2h = symb(g_wf2_h),  *w2l = symb(g_wf2_l);

    // 0-3: weight preps needed early
    prep_w<<<dim3(CEMB / 32, CEMB / 32), 256>>>(q_w, wqh, wql, CEMB, CEMB);
    prep_w<<<dim3(RKV / 32, CEMB / 32), 256>>>(kvd_w, wdh, wdl, CEMB, RKV);
    prep_w<<<dim3(2 * CEMB / 32, RKV / 32), 256>>>(kvu_w, wuh, wul, RKV, 2 * CEMB);
    prep_w<<<dim3(CEMB / 32, CEMB / 32), 256>>>(proj_w, wph, wpl, CEMB, CEMB);
    // 4: h = LN1(x) -> split bf16
    ln_k<true><<<MROWS, 256>>>(x, ln1_w, ln1_b, nullptr, hh, hl, CEMB);
    // 5: qlin = h @ q_w        <-- ncu capture target
    gemm_mma<EPI_NONE, 0><<<dim3(CEMB / 128, MROWS / 128), 256>>>(
        hh, hl, wqh, wql, qlin, nullptr, nullptr, nullptr, nullptr,
        MROWS, CEMB, CEMB);
    // 6: ckv = h @ kvd_w
    gemm_mma<EPI_NONE, 0><<<dim3(RKV / 128, MROWS / 128), 256>>>(
        hh, hl, wdh, wdl, ckv, nullptr, nullptr, nullptr, nullptr,
        MROWS, RKV, CEMB);
    // 7: ckv = LN_kv(ckv) -> split bf16
    ln_k<true><<<MROWS, 256>>>(ckv, kvln_w, kvln_b, nullptr, ch, cl, RKV);
    // 8: kvlin = ckv @ kvu_w
    gemm_mma<EPI_NONE, 0><<<dim3(2 * CEMB / 128, MROWS / 128), 256>>>(
        ch, cl, wuh, wul, kvlin, nullptr, nullptr, nullptr, nullptr,
        MROWS, 2 * CEMB, RKV);
    // 9/10: rope -> split bf16 q/k/v [B,H,T,D]
    rope_tab_k<<<(TSEQ * 32 + 255) / 256, 256>>>(ct, st);
    rope_qkv_k<<<(BSZ * TSEQ * NH * 32) / 256, 256>>>(qlin, kvlin, ct, st,
                                                      qh, ql, kh, kl, vh, vl);
    // 11: flash attention (mma.sync) -> ctx split bf16
    attn_mma<<<dim3(TSEQ / 128, NH, BSZ), 256>>>(qh, ql, kh, kl, vh, vl, xh, xl);
    // 12/13: FFN weight preps
    prep_w<<<dim3(FF / 32, CEMB / 32), 256>>>(f1_w, w1h, w1l, CEMB, FF);
    prep_w<<<dim3(CEMB / 32, FF / 32), 256>>>(f2_w, w2h, w2l, FF, CEMB);
    // 14: x1 = x + ctx @ proj_w + proj_b
    gemm_mma<EPI_BIAS_RESID, 0><<<dim3(CEMB / 128, MROWS / 128), 256>>>(
        xh, xl, wph, wpl, x1, nullptr, nullptr, proj_b, x, MROWS, CEMB, CEMB);
    // 15: h2 = LN2(x1) -> split bf16
    ln_k<true><<<MROWS, 256>>>(x1, ln2_w, ln2_b, nullptr, h2h, h2l, CEMB);
    // 16: ff1 = gelu(h2 @ f1_w + f1_b) -> split bf16
    gemm_mma<EPI_BIAS_GELU, 1><<<dim3(FF / 128, MROWS / 128), 256>>>(
        h2h, h2l, w1h, w1l, nullptr, fh, fl, f1_b, nullptr, MROWS, FF, CEMB);
    // 17: out = x1 + ff1 @ f2_w + f2_b
    gemm_mma<EPI_BIAS_RESID, 0><<<dim3(CEMB / 128, MROWS / 128), 256>>>(
        fh, fl, w2h, w2l, out, nullptr, nullptr, f2_b, x1, MROWS, CEMB, FF);
}

// round 8
// speedup vs baseline: 2.2851x; 1.0847x over previous
#include <cuda_runtime.h>
#include <cuda_bf16.h>
#include <math.h>
#include <stdint.h>

// ---------------------------------------------------------------------------
// Problem constants
// ---------------------------------------------------------------------------
#define BSZ   4
#define TSEQ  2048
#define CEMB  1024
#define NH    16
#define HD    64
#define RKV   512
#define FF    4096
#define MROWS (BSZ * TSEQ)   // 8192

typedef __nv_bfloat16 bf16;

// ---------------------------------------------------------------------------
// Scratch (static __device__ arrays -- allocation-free per harness rules)
// ---------------------------------------------------------------------------
__device__ float g_qlin [MROWS * CEMB];
__device__ float g_ckv  [MROWS * RKV];
__device__ float g_kvlin[MROWS * 2 * CEMB];
__device__ float g_x1   [MROWS * CEMB];
__device__ float g_cos  [TSEQ * 32];
__device__ float g_sin  [TSEQ * 32];
// bf16 split activations
__device__ bf16 g_h_h  [MROWS * CEMB];
__device__ bf16 g_h_l  [MROWS * CEMB];
__device__ bf16 g_ckv_h[MROWS * RKV];
__device__ bf16 g_ckv_l[MROWS * RKV];
__device__ bf16 g_ctx_h[MROWS * CEMB];
__device__ bf16 g_ctx_l[MROWS * CEMB];
__device__ bf16 g_h2_h [MROWS * CEMB];
__device__ bf16 g_h2_l [MROWS * CEMB];
__device__ bf16 g_ff1_h[MROWS * FF];
__device__ bf16 g_ff1_l[MROWS * FF];
// split q/k/v in [B,H,T,D]
__device__ bf16 g_qh[MROWS * CEMB];
__device__ bf16 g_ql[MROWS * CEMB];
__device__ bf16 g_kh[MROWS * CEMB];
__device__ bf16 g_kl[MROWS * CEMB];
__device__ bf16 g_vh[MROWS * CEMB];
__device__ bf16 g_vl[MROWS * CEMB];
// bf16 split transposed weights [N,K]
__device__ bf16 g_wq_h  [CEMB * CEMB];
__device__ bf16 g_wq_l  [CEMB * CEMB];
__device__ bf16 g_wkvd_h[RKV * CEMB];
__device__ bf16 g_wkvd_l[RKV * CEMB];
__device__ bf16 g_wkvu_h[2 * CEMB * RKV];
__device__ bf16 g_wkvu_l[2 * CEMB * RKV];
__device__ bf16 g_wpr_h [CEMB * CEMB];
__device__ bf16 g_wpr_l [CEMB * CEMB];
__device__ bf16 g_wf1_h [FF * CEMB];
__device__ bf16 g_wf1_l [FF * CEMB];
__device__ bf16 g_wf2_h [CEMB * FF];
__device__ bf16 g_wf2_l [CEMB * FF];

// ---------------------------------------------------------------------------
// Helpers
// ---------------------------------------------------------------------------
__device__ __forceinline__ void split_f32(float x, bf16& h, bf16& l)
{
    h = __float2bfloat16_rn(x);
    l = __float2bfloat16_rn(x - __bfloat162float(h));
}
__device__ __forceinline__ void split2(float x, float y, uint32_t& h2, uint32_t& l2)
{
    bf16 hx, lx, hy, ly;
    split_f32(x, hx, lx);
    split_f32(y, hy, ly);
    __nv_bfloat162 H; H.x = hx; H.y = hy;
    __nv_bfloat162 L; L.x = lx; L.y = ly;
    h2 = *(uint32_t*)&H;
    l2 = *(uint32_t*)&L;
}
__device__ __forceinline__ float gelu_exact(float x)
{
    return 0.5f * x * (1.0f + erff(x * 0.70710678118654752f));
}
__device__ __forceinline__ void cpa16(uint32_t saddr, const void* g)
{
    asm volatile("cp.async.cg.shared.global [%0], [%1], 16;"
                 :: "r"(saddr), "l"(g) : "memory");
}
__device__ __forceinline__ void cpa_commit()
{
    asm volatile("cp.async.commit_group;" ::: "memory");
}
template <int N>
__device__ __forceinline__ void cpa_wait()
{
    asm volatile("cp.async.wait_group %0;" :: "n"(N) : "memory");
}
__device__ __forceinline__ void mma_bf16(float& c0, float& c1, float& c2, float& c3,
                                         uint32_t a0, uint32_t a1, uint32_t a2,
                                         uint32_t a3, uint32_t b0, uint32_t b1)
{
    asm volatile(
        "mma.sync.aligned.m16n8k16.row.col.f32.bf16.bf16.f32 "
        "{%0,%1,%2,%3}, {%4,%5,%6,%7}, {%8,%9}, {%0,%1,%2,%3};"
        : "+f"(c0), "+f"(c1), "+f"(c2), "+f"(c3)
        : "r"(a0), "r"(a1), "r"(a2), "r"(a3), "r"(b0), "r"(b1));
}
__device__ __forceinline__ void ldm4(uint32_t& r0, uint32_t& r1, uint32_t& r2,
                                     uint32_t& r3, uint32_t a)
{
    asm volatile("ldmatrix.sync.aligned.m8n8.x4.shared.b16 {%0,%1,%2,%3}, [%4];"
                 : "=r"(r0), "=r"(r1), "=r"(r2), "=r"(r3) : "r"(a));
}
__device__ __forceinline__ void ldm4t(uint32_t& r0, uint32_t& r1, uint32_t& r2,
                                      uint32_t& r3, uint32_t a)
{
    asm volatile("ldmatrix.sync.aligned.m8n8.x4.trans.shared.b16 {%0,%1,%2,%3}, [%4];"
                 : "=r"(r0), "=r"(r1), "=r"(r2), "=r"(r3) : "r"(a));
}

// ---------------------------------------------------------------------------
// LayerNorm (optionally writing split bf16 output)
// ---------------------------------------------------------------------------
template <bool SPLIT>
__global__ void __launch_bounds__(256) ln_k(const float* __restrict__ x,
                                            const float* __restrict__ w,
                                            const float* __restrict__ b,
                                            float* __restrict__ out,
                                            bf16* __restrict__ oh,
                                            bf16* __restrict__ ol, int W)
{
    size_t row = blockIdx.x;
    const float* xr = x + row * (size_t)W;

    float s = 0.f, s2 = 0.f;
    for (int i = threadIdx.x << 2; i < W; i += 256 * 4) {
        float4 v = *(const float4*)(xr + i);
        s  += v.x + v.y + v.z + v.w;
        s2 += v.x * v.x + v.y * v.y + v.z * v.z + v.w * v.w;
    }
    __shared__ float sh[8][2];
    #pragma unroll
    for (int off = 16; off; off >>= 1) {
        s  += __shfl_xor_sync(0xffffffffu, s,  off);
        s2 += __shfl_xor_sync(0xffffffffu, s2, off);
    }
    int wrp = threadIdx.x >> 5, ln = threadIdx.x & 31;
    if (ln == 0) { sh[wrp][0] = s; sh[wrp][1] = s2; }
    __syncthreads();
    s = 0.f; s2 = 0.f;
    #pragma unroll
    for (int i = 0; i < 8; i++) { s += sh[i][0]; s2 += sh[i][1]; }

    float invW = 1.0f / (float)W;
    float mu   = s * invW;
    float var  = s2 * invW - mu * mu;
    float rstd = rsqrtf(var + 1e-5f);

    for (int i = threadIdx.x << 2; i < W; i += 256 * 4) {
        float4 v  = *(const float4*)(xr + i);
        float4 wv = *(const float4*)(w + i);
        float4 bv = *(const float4*)(b + i);
        float r0 = (v.x - mu) * rstd * wv.x + bv.x;
        float r1 = (v.y - mu) * rstd * wv.y + bv.y;
        float r2 = (v.z - mu) * rstd * wv.z + bv.z;
        float r3 = (v.w - mu) * rstd * wv.w + bv.w;
        if (!SPLIT) {
            *(float4*)(out + row * (size_t)W + i) = make_float4(r0, r1, r2, r3);
        } else {
            uint32_t h0, l0, h1, l1;
            split2(r0, r1, h0, l0);
            split2(r2, r3, h1, l1);
            *(uint32_t*)(oh + row * (size_t)W + i)     = h0;
            *(uint32_t*)(oh + row * (size_t)W + i + 2) = h1;
            *(uint32_t*)(ol + row * (size_t)W + i)     = l0;
            *(uint32_t*)(ol + row * (size_t)W + i + 2) = l1;
        }
    }
}

// ---------------------------------------------------------------------------
// Weight preprocess: W[K,N] -> Th/Tl [N,K] bf16 hi/lo (tiled transpose)
// ---------------------------------------------------------------------------
__global__ void __launch_bounds__(256) prep_w(const float* __restrict__ W,
                                              bf16* __restrict__ Th,
                                              bf16* __restrict__ Tl,
                                              int K, int N)
{
    __shared__ float t[32][33];
    int nb = blockIdx.x * 32, kb = blockIdx.y * 32;
    int tx = threadIdx.x & 31, ty = threadIdx.x >> 5;  // 32 x 8
    #pragma unroll
    for (int j = 0; j < 32; j += 8)
        t[ty + j][tx] = W[(size_t)(kb + ty + j) * N + nb + tx];
    __syncthreads();
    #pragma unroll
    for (int j = 0; j < 32; j += 8) {
        float v = t[tx][ty + j];
        bf16 h, l;
        split_f32(v, h, l);
        size_t o = (size_t)(nb + ty + j) * K + kb + tx;
        Th[o] = h; Tl[o] = l;
    }
}

// ---------------------------------------------------------------------------
// RoPE table + fused RoPE/transpose -> split bf16 q/k/v in [B,H,T,D]
// ---------------------------------------------------------------------------
__global__ void rope_tab_k(float* __restrict__ ct, float* __restrict__ st)
{
    int idx = blockIdx.x * blockDim.x + threadIdx.x;
    if (idx >= TSEQ * 32) return;
    int t = idx >> 5, d = idx & 31;
    float inv = (float)pow(10000.0, -(double)d / 32.0);
    float ang = (float)t * inv;
    ct[idx] = (float)cos((double)ang);
    st[idx] = (float)sin((double)ang);
}

__global__ void __launch_bounds__(256) rope_qkv_k(
    const float* __restrict__ qlin, const float* __restrict__ kvlin,
    const float* __restrict__ ct, const float* __restrict__ st,
    bf16* __restrict__ qh, bf16* __restrict__ ql,
    bf16* __restrict__ kh, bf16* __restrict__ kl,
    bf16* __restrict__ vh, bf16* __restrict__ vl)
{
    int g = blockIdx.x * blockDim.x + threadIdx.x;
    int d = g & 31;
    int h = (g >> 5) & 15;
    int t = (g >> 9) & 2047;
    int b = g >> 20;

    float c = ct[t * 32 + d];
    float s = st[t * 32 + d];

    const float* qlp = qlin + ((size_t)(b * TSEQ + t)) * CEMB + h * HD;
    const float* klp = kvlin + ((size_t)(b * TSEQ + t)) * (2 * CEMB) + h * HD;
    const float* vlp = klp + CEMB;

    size_t o = (((size_t)(b * NH + h)) * TSEQ + t) * HD;

    float q0 = qlp[d], q1 = qlp[d + 32];
    float qa = q0 * c - q1 * s, qb = q1 * c + q0 * s;
    float k0 = klp[d], k1 = klp[d + 32];
    float ka = k0 * c - k1 * s, kb = k1 * c + k0 * s;
    float va = vlp[d], vb = vlp[d + 32];

    bf16 hh, ll;
    split_f32(qa, hh, ll); qh[o + d] = hh;      ql[o + d] = ll;
    split_f32(qb, hh, ll); qh[o + d + 32] = hh; ql[o + d + 32] = ll;
    split_f32(ka, hh, ll); kh[o + d] = hh;      kl[o + d] = ll;
    split_f32(kb, hh, ll); kh[o + d + 32] = hh; kl[o + d + 32] = ll;
    split_f32(va, hh, ll); vh[o + d] = hh;      vl[o + d] = ll;
    split_f32(vb, hh, ll); vh[o + d + 32] = hh; vl[o + d + 32] = ll;
}

// ---------------------------------------------------------------------------
// mma.sync split-bf16 GEMM: C[M,N] = A[M,K] @ W[N,K]^T, fused epilogues.
// BM=BN=128, BK=16, 8 warps (2x4), warp tile 64x32. 48KB static smem.
// Reg-lean: fragments reloaded per pass (peak live ~116 regs) so 2 CTAs/SM.
// ---------------------------------------------------------------------------
#define EPI_NONE       0
#define EPI_BIAS_RESID 1
#define EPI_BIAS_GELU  2

#define ROWP   24
#define MATB   (128 * ROWP * 2)
#define STAGEB (4 * MATB)

template <int EPI, int SPLITOUT>
__global__ void __launch_bounds__(256, 2) gemm_mma(
    const bf16* __restrict__ Ah, const bf16* __restrict__ Al,
    const bf16* __restrict__ Bh, const bf16* __restrict__ Bl,
    float* __restrict__ C, bf16* __restrict__ Chi, bf16* __restrict__ Clo,
    const float* __restrict__ bias, const float* __restrict__ resid,
    int M, int N, int K)
{
    __shared__ char smem_raw[2 * STAGEB];
    uint32_t smem_u = (uint32_t)__cvta_generic_to_shared(smem_raw);

    int tid = threadIdx.x;
    int wid = tid >> 5, lid = tid & 31;
    int wm = wid & 1, wn = wid >> 1;
    int qr = lid >> 2, qc = lid & 3;
    int bm = blockIdx.y * 128, bn = blockIdx.x * 128;

    const bf16* Ahp = Ah + (size_t)bm * K;
    const bf16* Alp = Al + (size_t)bm * K;
    const bf16* Bhp = Bh + (size_t)bn * K;
    const bf16* Blp = Bl + (size_t)bn * K;

    int NK = K >> 4;

    int lrow = tid >> 1;
    int lc8  = (tid & 1) << 3;
    uint32_t lsoff = ((uint32_t)lrow * ROWP + lc8) * 2u;

    auto stage_load = [&](int kt, int buf) {
        size_t go = (size_t)lrow * K + (kt << 4) + lc8;
        uint32_t sa = smem_u + buf * STAGEB + lsoff;
        cpa16(sa + 0 * MATB, Ahp + go);
        cpa16(sa + 1 * MATB, Alp + go);
        cpa16(sa + 2 * MATB, Bhp + go);
        cpa16(sa + 3 * MATB, Blp + go);
        cpa_commit();
    };

    // ldmatrix lane addressing
    int arow = wm * 64 + ((lid >> 3) & 1) * 8 + (lid & 7);
    int acol = ((lid >> 4) & 1) * 8;
    uint32_t aoff = ((uint32_t)arow * ROWP + acol) * 2u;
    int brow = wn * 32 + ((lid >> 4) & 1) * 8 + (lid & 7);
    int bcol = ((lid >> 3) & 1) * 8;
    uint32_t boff = ((uint32_t)brow * ROWP + bcol) * 2u;

    float acc[4][4][4] = {};

    stage_load(0, 0);

    for (int kt = 0; kt < NK; kt++) {
        int buf = kt & 1;
        if (kt + 1 < NK) {
            stage_load(kt + 1, buf ^ 1);
            cpa_wait<1>();
        } else {
            cpa_wait<0>();
        }
        __syncthreads();

        uint32_t sAh = smem_u + buf * STAGEB + 0 * MATB;
        uint32_t sAl = smem_u + buf * STAGEB + 1 * MATB;
        uint32_t sBh = smem_u + buf * STAGEB + 2 * MATB;
        uint32_t sBl = smem_u + buf * STAGEB + 3 * MATB;

        uint32_t fa[4][4], fbh[4][2], fbl[4][2];
        // pass 1: Ah * Bh
        #pragma unroll
        for (int mi = 0; mi < 4; mi++)
            ldm4(fa[mi][0], fa[mi][1], fa[mi][2], fa[mi][3],
                 sAh + aoff + (uint32_t)(mi * 16 * ROWP) * 2u);
        #pragma unroll
        for (int p = 0; p < 2; p++) {
            uint32_t off = boff + (uint32_t)(p * 16 * ROWP) * 2u;
            ldm4(fbh[2 * p][0], fbh[2 * p][1], fbh[2 * p + 1][0], fbh[2 * p + 1][1],
                 sBh + off);
            ldm4(fbl[2 * p][0], fbl[2 * p][1], fbl[2 * p + 1][0], fbl[2 * p + 1][1],
                 sBl + off);
        }
        #pragma unroll
        for (int ni = 0; ni < 4; ni++)
            #pragma unroll
            for (int mi = 0; mi < 4; mi++)
                mma_bf16(acc[mi][ni][0], acc[mi][ni][1], acc[mi][ni][2], acc[mi][ni][3],
                         fa[mi][0], fa[mi][1], fa[mi][2], fa[mi][3],
                         fbh[ni][0], fbh[ni][1]);
        // pass 2: Ah * Bl (reuse fa)
        #pragma unroll
        for (int ni = 0; ni < 4; ni++)
            #pragma unroll
            for (int mi = 0; mi < 4; mi++)
                mma_bf16(acc[mi][ni][0], acc[mi][ni][1], acc[mi][ni][2], acc[mi][ni][3],
                         fa[mi][0], fa[mi][1], fa[mi][2], fa[mi][3],
                         fbl[ni][0], fbl[ni][1]);
        // pass 3: Al * Bh (reload fa <- Al)
        #pragma unroll
        for (int mi = 0; mi < 4; mi++)
            ldm4(fa[mi][0], fa[mi][1], fa[mi][2], fa[mi][3],
                 sAl + aoff + (uint32_t)(mi * 16 * ROWP) * 2u);
        #pragma unroll
        for (int ni = 0; ni < 4; ni++)
            #pragma unroll
            for (int mi = 0; mi < 4; mi++)
                mma_bf16(acc[mi][ni][0], acc[mi][ni][1], acc[mi][ni][2], acc[mi][ni][3],
                         fa[mi][0], fa[mi][1], fa[mi][2], fa[mi][3],
                         fbh[ni][0], fbh[ni][1]);
        __syncthreads();
    }

    #pragma unroll
    for (int mi = 0; mi < 4; mi++) {
        #pragma unroll
        for (int ni = 0; ni < 4; ni++) {
            int col = bn + wn * 32 + ni * 8 + qc * 2;
            #pragma unroll
            for (int half = 0; half < 2; half++) {
                int row = bm + wm * 64 + mi * 16 + qr + half * 8;
                size_t off = (size_t)row * N + col;
                float v0 = acc[mi][ni][half * 2 + 0];
                float v1 = acc[mi][ni][half * 2 + 1];
                if (EPI != EPI_NONE) {
                    v0 += bias[col];
                    v1 += bias[col + 1];
                }
                if (EPI == EPI_BIAS_GELU) {
                    v0 = gelu_exact(v0);
                    v1 = gelu_exact(v1);
                }
                if (EPI == EPI_BIAS_RESID) {
                    float2 rv = *(const float2*)(resid + off);
                    v0 += rv.x; v1 += rv.y;
                }
                if (!SPLITOUT) {
                    *(float2*)(C + off) = make_float2(v0, v1);
                } else {
                    uint32_t h2, l2;
                    split2(v0, v1, h2, l2);
                    *(uint32_t*)(Chi + off) = h2;
                    *(uint32_t*)(Clo + off) = l2;
                }
            }
        }
    }
}

// ---------------------------------------------------------------------------
// Flash attention on mma.sync (unchanged from passing Round-6/7 kernel)
// ---------------------------------------------------------------------------
#define APAD 72
#define KVMAT (64 * APAD * 2)    // 9216 bytes per 64x64 matrix

__global__ void __launch_bounds__(256) attn_mma(
    const bf16* __restrict__ qh_, const bf16* __restrict__ ql_,
    const bf16* __restrict__ kh_, const bf16* __restrict__ kl_,
    const bf16* __restrict__ vh_, const bf16* __restrict__ vl_,
    bf16* __restrict__ ctxh, bf16* __restrict__ ctxl)
{
    __shared__ char sm[4 * KVMAT];   // 36864 bytes
    uint32_t smu = (uint32_t)__cvta_generic_to_shared(sm);

    int b = blockIdx.z, h = blockIdx.y, it = blockIdx.x;
    int t0 = it * 128;
    size_t bh = ((size_t)(b * NH + h)) * TSEQ * HD;

    int tid = threadIdx.x;
    int w = tid >> 5, lid = tid & 31;
    int qr = lid >> 2, qc = lid & 3;

    {
        const bf16* srcs[2] = { qh_ + bh + (size_t)t0 * HD,
                                ql_ + bh + (size_t)t0 * HD };
        #pragma unroll
        for (int i = 0; i < 8; i++) {
            int chunk = tid + i * 256;
            int mat = chunk >> 10;
            int wi = chunk & 1023;
            int row = wi >> 3, c8 = (wi & 7) << 3;
            cpa16(smu + mat * (2 * KVMAT) + (row * APAD + c8) * 2,
                  srcs[mat] + (size_t)row * HD + c8);
        }
        cpa_commit();
        cpa_wait<0>();
    }
    __syncthreads();

    uint32_t qa_h[4][4], qa_l[4][4];
    {
        int row = w * 16 + ((lid >> 3) & 1) * 8 + (lid & 7);
        int colb = (lid >> 4) * 8;
        #pragma unroll
        for (int ks = 0; ks < 4; ks++) {
            uint32_t off = (uint32_t)(row * APAD + colb + ks * 16) * 2;
            ldm4(qa_h[ks][0], qa_h[ks][1], qa_h[ks][2], qa_h[ks][3], smu + off);
            ldm4(qa_l[ks][0], qa_l[ks][1], qa_l[ks][2], qa_l[ks][3],
                 smu + 2 * KVMAT + off);
        }
    }

    float m_i[2] = { -1e30f, -1e30f };
    float l_i[2] = { 0.f, 0.f };
    float o[8][4] = {};
    float s[8][4];

    int nrb = ((lid >> 4) & 1) * 8 + (lid & 7);
    int ncb = ((lid >> 3) & 1) * 8;
    int srb = ((lid >> 3) & 1) * 8 + (lid & 7);
    int scb = ((lid >> 4) & 1) * 8;

    int nk = 2 * (it + 1);
    for (int kt = 0; kt < nk; kt++) {
        int k0 = kt * 64;
        __syncthreads();
        {
            const bf16* srcs[4] = { kh_ + bh + (size_t)k0 * HD,
                                    kl_ + bh + (size_t)k0 * HD,
                                    vh_ + bh + (size_t)k0 * HD,
                                    vl_ + bh + (size_t)k0 * HD };
            #pragma unroll
            for (int i = 0; i < 8; i++) {
                int chunk = tid + i * 256;
                int mat = chunk >> 9;
                int wi = chunk & 511;
                int row = wi >> 3, c8 = (wi & 7) << 3;
                cpa16(smu + mat * KVMAT + (row * APAD + c8) * 2,
                      srcs[mat] + (size_t)row * HD + c8);
            }
            cpa_commit();
            cpa_wait<0>();
        }
        __syncthreads();

        #pragma unroll
        for (int nt = 0; nt < 8; nt++) {
            s[nt][0] = 0.f; s[nt][1] = 0.f; s[nt][2] = 0.f; s[nt][3] = 0.f;
        }
        #pragma unroll
        for (int ks = 0; ks < 4; ks++) {
            uint32_t kb[8][2];
            #pragma unroll
            for (int g = 0; g < 4; g++) {
                uint32_t a = smu + (uint32_t)((g * 16 + nrb) * APAD + ks * 16 + ncb) * 2;
                ldm4(kb[2 * g][0], kb[2 * g][1], kb[2 * g + 1][0], kb[2 * g + 1][1], a);
            }
            #pragma unroll
            for (int nt = 0; nt < 8; nt++) {
                mma_bf16(s[nt][0], s[nt][1], s[nt][2], s[nt][3],
                         qa_h[ks][0], qa_h[ks][1], qa_h[ks][2], qa_h[ks][3],
                         kb[nt][0], kb[nt][1]);
                mma_bf16(s[nt][0], s[nt][1], s[nt][2], s[nt][3],
                         qa_l[ks][0], qa_l[ks][1], qa_l[ks][2], qa_l[ks][3],
                         kb[nt][0], kb[nt][1]);
            }
            #pragma unroll
            for (int g = 0; g < 4; g++) {
                uint32_t a = smu + KVMAT +
                             (uint32_t)((g * 16 + nrb) * APAD + ks * 16 + ncb) * 2;
                ldm4(kb[2 * g][0], kb[2 * g][1], kb[2 * g + 1][0], kb[2 * g + 1][1], a);
            }
            #pragma unroll
            for (int nt = 0; nt < 8; nt++)
                mma_bf16(s[nt][0], s[nt][1], s[nt][2], s[nt][3],
                         qa_h[ks][0], qa_h[ks][1], qa_h[ks][2], qa_h[ks][3],
                         kb[nt][0], kb[nt][1]);
        }

        int row0 = t0 + w * 16 + qr;
        int row1 = row0 + 8;
        #pragma unroll
        for (int nt = 0; nt < 8; nt++) {
            int col0 = k0 + nt * 8 + qc * 2;
            s[nt][0] = (col0     > row0) ? -1e30f : s[nt][0] * 0.125f;
            s[nt][1] = (col0 + 1 > row0) ? -1e30f : s[nt][1] * 0.125f;
            s[nt][2] = (col0     > row1) ? -1e30f : s[nt][2] * 0.125f;
            s[nt][3] = (col0 + 1 > row1) ? -1e30f : s[nt][3] * 0.125f;
        }

        float mxA = -1e30f, mxB = -1e30f;
        #pragma unroll
        for (int nt = 0; nt < 8; nt++) {
            mxA = fmaxf(mxA, fmaxf(s[nt][0], s[nt][1]));
            mxB = fmaxf(mxB, fmaxf(s[nt][2], s[nt][3]));
        }
        mxA = fmaxf(mxA, __shfl_xor_sync(0xffffffffu, mxA, 1));
        mxA = fmaxf(mxA, __shfl_xor_sync(0xffffffffu, mxA, 2));
        mxB = fmaxf(mxB, __shfl_xor_sync(0xffffffffu, mxB, 1));
        mxB = fmaxf(mxB, __shfl_xor_sync(0xffffffffu, mxB, 2));

        float mnA = fmaxf(m_i[0], mxA), mnB = fmaxf(m_i[1], mxB);
        float aA = expf(m_i[0] - mnA), aB = expf(m_i[1] - mnB);
        m_i[0] = mnA; m_i[1] = mnB;

        float sumA = 0.f, sumB = 0.f;
        #pragma unroll
        for (int nt = 0; nt < 8; nt++) {
            s[nt][0] = expf(s[nt][0] - mnA); sumA += s[nt][0];
            s[nt][1] = expf(s[nt][1] - mnA); sumA += s[nt][1];
            s[nt][2] = expf(s[nt][2] - mnB); sumB += s[nt][2];
            s[nt][3] = expf(s[nt][3] - mnB); sumB += s[nt][3];
        }
        sumA += __shfl_xor_sync(0xffffffffu, sumA, 1);
        sumA += __shfl_xor_sync(0xffffffffu, sumA, 2);
        sumB += __shfl_xor_sync(0xffffffffu, sumB, 1);
        sumB += __shfl_xor_sync(0xffffffffu, sumB, 2);
        l_i[0] = l_i[0] * aA + sumA;
        l_i[1] = l_i[1] * aB + sumB;

        #pragma unroll
        for (int dt = 0; dt < 8; dt++) {
            o[dt][0] *= aA; o[dt][1] *= aA;
            o[dt][2] *= aB; o[dt][3] *= aB;
        }

        #pragma unroll
        for (int ks = 0; ks < 4; ks++) {
            uint32_t pah[4], pal[4];
            split2(s[2 * ks][0],     s[2 * ks][1],     pah[0], pal[0]);
            split2(s[2 * ks][2],     s[2 * ks][3],     pah[1], pal[1]);
            split2(s[2 * ks + 1][0], s[2 * ks + 1][1], pah[2], pal[2]);
            split2(s[2 * ks + 1][2], s[2 * ks + 1][3], pah[3], pal[3]);

            uint32_t vb[8][2];
            #pragma unroll
            for (int g = 0; g < 4; g++) {
                uint32_t a = smu + 2 * KVMAT +
                             (uint32_t)((ks * 16 + srb) * APAD + g * 16 + scb) * 2;
                ldm4t(vb[2 * g][0], vb[2 * g][1], vb[2 * g + 1][0], vb[2 * g + 1][1], a);
            }
            #pragma unroll
            for (int dt = 0; dt < 8; dt++) {
                mma_bf16(o[dt][0], o[dt][1], o[dt][2], o[dt][3],
                         pah[0], pah[1], pah[2], pah[3], vb[dt][0], vb[dt][1]);
                mma_bf16(o[dt][0], o[dt][1], o[dt][2], o[dt][3],
                         pal[0], pal[1], pal[2], pal[3], vb[dt][0], vb[dt][1]);
            }
            #pragma unroll
            for (int g = 0; g < 4; g++) {
                uint32_t a = smu + 3 * KVMAT +
                             (uint32_t)((ks * 16 + srb) * APAD + g * 16 + scb) * 2;
                ldm4t(vb[2 * g][0], vb[2 * g][1], vb[2 * g + 1][0], vb[2 * g + 1][1], a);
            }
            #pragma unroll
            for (int dt = 0; dt < 8; dt++)
                mma_bf16(o[dt][0], o[dt][1], o[dt][2], o[dt][3],
                         pah[0], pah[1], pah[2], pah[3], vb[dt][0], vb[dt][1]);
        }
    }

    float invA = 1.0f / l_i[0], invB = 1.0f / l_i[1];
    int r0 = t0 + w * 16 + qr, r1 = r0 + 8;
    #pragma unroll
    for (int dt = 0; dt < 8; dt++) {
        int col = h * HD + dt * 8 + qc * 2;
        uint32_t h2, l2;
        split2(o[dt][0] * invA, o[dt][1] * invA, h2, l2);
        size_t off0 = ((size_t)(b * TSEQ + r0)) * CEMB + col;
        *(uint32_t*)(ctxh + off0) = h2;
        *(uint32_t*)(ctxl + off0) = l2;
        split2(o[dt][2] * invB, o[dt][3] * invB, h2, l2);
        size_t off1 = ((size_t)(b * TSEQ + r1)) * CEMB + col;
        *(uint32_t*)(ctxh + off1) = h2;
        *(uint32_t*)(ctxl + off1) = l2;
    }
}

// ---------------------------------------------------------------------------
// Launch (indices 3 AND 5 are main GEMMs so ncu hits one regardless of
// harness-internal launch offset)
// ---------------------------------------------------------------------------
static float* sym(const void* s)
{
    void* p = nullptr;
    cudaGetSymbolAddress(&p, s);
    return (float*)p;
}
static bf16* symb(const void* s)
{
    void* p = nullptr;
    cudaGetSymbolAddress(&p, s);
    return (bf16*)p;
}

extern "C" void kernel_launch(void* const* d_in, const int* in_sizes, int n_in,
                              void* d_out, int out_size)
{
    const float* x      = (const float*)d_in[0];
    const float* ln1_w  = (const float*)d_in[1];
    const float* ln1_b  = (const float*)d_in[2];
    const float* ln2_w  = (const float*)d_in[3];
    const float* ln2_b  = (const float*)d_in[4];
    const float* q_w    = (const float*)d_in[5];
    const float* kvd_w  = (const float*)d_in[6];
    const float* kvln_w = (const float*)d_in[7];
    const float* kvln_b = (const float*)d_in[8];
    const float* kvu_w  = (const float*)d_in[9];
    const float* proj_w = (const float*)d_in[10];
    const float* proj_b = (const float*)d_in[11];
    const float* f1_w   = (const float*)d_in[12];
    const float* f1_b   = (const float*)d_in[13];
    const float* f2_w   = (const float*)d_in[14];
    const float* f2_b   = (const float*)d_in[15];
    float* out = (float*)d_out;

    float* qlin  = sym(g_qlin);
    float* ckv   = sym(g_ckv);
    float* kvlin = sym(g_kvlin);
    float* x1    = sym(g_x1);
    float* ct    = sym(g_cos);
    float* st    = sym(g_sin);
    bf16 *hh = symb(g_h_h),  *hl = symb(g_h_l);
    bf16 *ch = symb(g_ckv_h), *cl = symb(g_ckv_l);
    bf16 *xh = symb(g_ctx_h), *xl = symb(g_ctx_l);
    bf16 *h2h = symb(g_h2_h), *h2l = symb(g_h2_l);
    bf16 *fh = symb(g_ff1_h), *fl = symb(g_ff1_l);
    bf16 *qh = symb(g_qh), *ql = symb(g_ql);
    bf16 *kh = symb(g_kh), *kl = symb(g_kl);
    bf16 *vh = symb(g_vh), *vl = symb(g_vl);
    bf16 *wqh = symb(g_wq_h),  *wql = symb(g_wq_l);
    bf16 *wdh = symb(g_wkvd_h), *wdl = symb(g_wkvd_l);
    bf16 *wuh = symb(g_wkvu_h), *wul = symb(g_wkvu_l);
    bf16 *wph = symb(g_wpr_h),  *wpl = symb(g_wpr_l);
    bf16 *w1h = symb(g_wf1_h),  *w1l = symb(g_wf1_l);
    bf16 *w2h = symb(g_wf2_h),  *w2l = symb(g_wf2_l);

    // 0: prep q_w
    prep_w<<<dim3(CEMB / 32, CEMB / 32), 256>>>(q_w, wqh, wql, CEMB, CEMB);
    // 1: h = LN1(x)
    ln_k<true><<<MROWS, 256>>>(x, ln1_w, ln1_b, nullptr, hh, hl, CEMB);
    // 2: prep kvd_w
    prep_w<<<dim3(RKV / 32, CEMB / 32), 256>>>(kvd_w, wdh, wdl, CEMB, RKV);
    // 3: qlin = h @ q_w            <-- ncu target (offset 2)
    gemm_mma<EPI_NONE, 0><<<dim3(CEMB / 128, MROWS / 128), 256>>>(
        hh, hl, wqh, wql, qlin, nullptr, nullptr, nullptr, nullptr,
        MROWS, CEMB, CEMB);
    // 4: prep kvu_w
    prep_w<<<dim3(2 * CEMB / 32, RKV / 32), 256>>>(kvu_w, wuh, wul, RKV, 2 * CEMB);
    // 5: ckv = h @ kvd_w           <-- ncu target (offset 0)
    gemm_mma<EPI_NONE, 0><<<dim3(RKV / 128, MROWS / 128), 256>>>(
        hh, hl, wdh, wdl, ckv, nullptr, nullptr, nullptr, nullptr,
        MROWS, RKV, CEMB);
    // 6: ckv = LN_kv(ckv)
    ln_k<true><<<MROWS, 256>>>(ckv, kvln_w, kvln_b, nullptr, ch, cl, RKV);
    // 7: kvlin = ckv @ kvu_w
    gemm_mma<EPI_NONE, 0><<<dim3(2 * CEMB / 128, MROWS / 128), 256>>>(
        ch, cl, wuh, wul, kvlin, nullptr, nullptr, nullptr, nullptr,
        MROWS, 2 * CEMB, RKV);
    // 8: prep proj_w
    prep_w<<<dim3(CEMB / 32, CEMB / 32), 256>>>(proj_w, wph, wpl, CEMB, CEMB);
    // 9/10: rope
    rope_tab_k<<<(TSEQ * 32 + 255) / 256, 256>>>(ct, st);
    rope_qkv_k<<<(BSZ * TSEQ * NH * 32) / 256, 256>>>(qlin, kvlin, ct, st,
                                                      qh, ql, kh, kl, vh, vl);
    // 11: flash attention
    attn_mma<<<dim3(TSEQ / 128, NH, BSZ), 256>>>(qh, ql, kh, kl, vh, vl, xh, xl);
    // 12: x1 = x + ctx @ proj_w + proj_b
    gemm_mma<EPI_BIAS_RESID, 0><<<dim3(CEMB / 128, MROWS / 128), 256>>>(
        xh, xl, wph, wpl, x1, nullptr, nullptr, proj_b, x, MROWS, CEMB, CEMB);
    // 13: h2 = LN2(x1)
    ln_k<true><<<MROWS, 256>>>(x1, ln2_w, ln2_b, nullptr, h2h, h2l, CEMB);
    // 14: prep f1_w
    prep_w<<<dim3(FF / 32, CEMB / 32), 256>>>(f1_w, w1h, w1l, CEMB, FF);
    // 15: ff1 = gelu(h2 @ f1_w + f1_b)
    gemm_mma<EPI_BIAS_GELU, 1><<<dim3(FF / 128, MROWS / 128), 256>>>(
        h2h, h2l, w1h, w1l, nullptr, fh, fl, f1_b, nullptr, MROWS, FF, CEMB);
    // 16: prep f2_w
    prep_w<<<dim3(CEMB / 32, FF / 32), 256>>>(f2_w, w2h, w2l, FF, CEMB);
    // 17: out = x1 + ff1 @ f2_w + f2_b
    gemm_mma<EPI_BIAS_RESID, 0><<<dim3(CEMB / 128, MROWS / 128), 256>>>(
        fh, fl, w2h, w2l, out, nullptr, nullptr, f2_b, x1, MROWS, CEMB, FF);
}

// round 9
// speedup vs baseline: 3.2692x; 1.4307x over previous
#include <cuda_runtime.h>
#include <cuda_fp16.h>
#include <math.h>
#include <stdint.h>

// ---------------------------------------------------------------------------
// Problem constants
// ---------------------------------------------------------------------------
#define BSZ   4
#define TSEQ  2048
#define CEMB  1024
#define NH    16
#define HD    64
#define RKV   512
#define FF    4096
#define MROWS (BSZ * TSEQ)   // 8192

typedef __half hf;

// ---------------------------------------------------------------------------
// Scratch (static __device__ arrays -- allocation-free per harness rules)
// ---------------------------------------------------------------------------
__device__ float g_qlin [MROWS * CEMB];
__device__ float g_ckv  [MROWS * RKV];
__device__ float g_kvlin[MROWS * 2 * CEMB];
__device__ float g_x1   [MROWS * CEMB];
__device__ float g_cos  [TSEQ * 32];
__device__ float g_sin  [TSEQ * 32];
// fp16 activations (GEMM A operands -- unsplit)
__device__ hf g_h   [MROWS * CEMB];
__device__ hf g_ckva[MROWS * RKV];
__device__ hf g_ctx [MROWS * CEMB];
__device__ hf g_h2  [MROWS * CEMB];
__device__ hf g_ff1 [MROWS * FF];
// q unsplit; k/v split hi/lo, [B,H,T,D]
__device__ hf g_q [MROWS * CEMB];
__device__ hf g_kh[MROWS * CEMB];
__device__ hf g_kl[MROWS * CEMB];
__device__ hf g_vh[MROWS * CEMB];
__device__ hf g_vl[MROWS * CEMB];
// fp16 split transposed weights [N,K]
__device__ hf g_wq_h  [CEMB * CEMB];
__device__ hf g_wq_l  [CEMB * CEMB];
__device__ hf g_wkvd_h[RKV * CEMB];
__device__ hf g_wkvd_l[RKV * CEMB];
__device__ hf g_wkvu_h[2 * CEMB * RKV];
__device__ hf g_wkvu_l[2 * CEMB * RKV];
__device__ hf g_wpr_h [CEMB * CEMB];
__device__ hf g_wpr_l [CEMB * CEMB];
__device__ hf g_wf1_h [FF * CEMB];
__device__ hf g_wf1_l [FF * CEMB];
__device__ hf g_wf2_h [CEMB * FF];
__device__ hf g_wf2_l [CEMB * FF];

// ---------------------------------------------------------------------------
// Helpers
// ---------------------------------------------------------------------------
__device__ __forceinline__ void split_f32(float x, hf& h, hf& l)
{
    h = __float2half_rn(x);
    l = __float2half_rn(x - __half2float(h));
}
__device__ __forceinline__ uint32_t pack2h(float x, float y)
{
    __half2 p = __floats2half2_rn(x, y);
    return *(uint32_t*)&p;
}
__device__ __forceinline__ float gelu_exact(float x)
{
    return 0.5f * x * (1.0f + erff(x * 0.70710678118654752f));
}
__device__ __forceinline__ void cpa16(uint32_t saddr, const void* g)
{
    asm volatile("cp.async.cg.shared.global [%0], [%1], 16;"
                 :: "r"(saddr), "l"(g) : "memory");
}
__device__ __forceinline__ void cpa_commit()
{
    asm volatile("cp.async.commit_group;" ::: "memory");
}
template <int N>
__device__ __forceinline__ void cpa_wait()
{
    asm volatile("cp.async.wait_group %0;" :: "n"(N) : "memory");
}
__device__ __forceinline__ void mma_f16(float& c0, float& c1, float& c2, float& c3,
                                        uint32_t a0, uint32_t a1, uint32_t a2,
                                        uint32_t a3, uint32_t b0, uint32_t b1)
{
    asm volatile(
        "mma.sync.aligned.m16n8k16.row.col.f32.f16.f16.f32 "
        "{%0,%1,%2,%3}, {%4,%5,%6,%7}, {%8,%9}, {%0,%1,%2,%3};"
        : "+f"(c0), "+f"(c1), "+f"(c2), "+f"(c3)
        : "r"(a0), "r"(a1), "r"(a2), "r"(a3), "r"(b0), "r"(b1));
}
__device__ __forceinline__ void ldm4(uint32_t& r0, uint32_t& r1, uint32_t& r2,
                                     uint32_t& r3, uint32_t a)
{
    asm volatile("ldmatrix.sync.aligned.m8n8.x4.shared.b16 {%0,%1,%2,%3}, [%4];"
                 : "=r"(r0), "=r"(r1), "=r"(r2), "=r"(r3) : "r"(a));
}
__device__ __forceinline__ void ldm4t(uint32_t& r0, uint32_t& r1, uint32_t& r2,
                                      uint32_t& r3, uint32_t a)
{
    asm volatile("ldmatrix.sync.aligned.m8n8.x4.trans.shared.b16 {%0,%1,%2,%3}, [%4];"
                 : "=r"(r0), "=r"(r1), "=r"(r2), "=r"(r3) : "r"(a));
}

// ---------------------------------------------------------------------------
// LayerNorm: writes f32 or unsplit fp16
// ---------------------------------------------------------------------------
template <bool HOUT>
__global__ void __launch_bounds__(256) ln_k(const float* __restrict__ x,
                                            const float* __restrict__ w,
                                            const float* __restrict__ b,
                                            float* __restrict__ out,
                                            hf* __restrict__ oh, int W)
{
    size_t row = blockIdx.x;
    const float* xr = x + row * (size_t)W;

    float s = 0.f, s2 = 0.f;
    for (int i = threadIdx.x << 2; i < W; i += 256 * 4) {
        float4 v = *(const float4*)(xr + i);
        s  += v.x + v.y + v.z + v.w;
        s2 += v.x * v.x + v.y * v.y + v.z * v.z + v.w * v.w;
    }
    __shared__ float sh[8][2];
    #pragma unroll
    for (int off = 16; off; off >>= 1) {
        s  += __shfl_xor_sync(0xffffffffu, s,  off);
        s2 += __shfl_xor_sync(0xffffffffu, s2, off);
    }
    int wrp = threadIdx.x >> 5, ln = threadIdx.x & 31;
    if (ln == 0) { sh[wrp][0] = s; sh[wrp][1] = s2; }
    __syncthreads();
    s = 0.f; s2 = 0.f;
    #pragma unroll
    for (int i = 0; i < 8; i++) { s += sh[i][0]; s2 += sh[i][1]; }

    float invW = 1.0f / (float)W;
    float mu   = s * invW;
    float var  = s2 * invW - mu * mu;
    float rstd = rsqrtf(var + 1e-5f);

    for (int i = threadIdx.x << 2; i < W; i += 256 * 4) {
        float4 v  = *(const float4*)(xr + i);
        float4 wv = *(const float4*)(w + i);
        float4 bv = *(const float4*)(b + i);
        float r0 = (v.x - mu) * rstd * wv.x + bv.x;
        float r1 = (v.y - mu) * rstd * wv.y + bv.y;
        float r2 = (v.z - mu) * rstd * wv.z + bv.z;
        float r3 = (v.w - mu) * rstd * wv.w + bv.w;
        if (!HOUT) {
            *(float4*)(out + row * (size_t)W + i) = make_float4(r0, r1, r2, r3);
        } else {
            *(uint32_t*)(oh + row * (size_t)W + i)     = pack2h(r0, r1);
            *(uint32_t*)(oh + row * (size_t)W + i + 2) = pack2h(r2, r3);
        }
    }
}

// ---------------------------------------------------------------------------
// Weight preprocess: W[K,N] -> Th/Tl [N,K] fp16 hi/lo (tiled transpose)
// ---------------------------------------------------------------------------
__global__ void __launch_bounds__(256) prep_w(const float* __restrict__ W,
                                              hf* __restrict__ Th,
                                              hf* __restrict__ Tl,
                                              int K, int N)
{
    __shared__ float t[32][33];
    int nb = blockIdx.x * 32, kb = blockIdx.y * 32;
    int tx = threadIdx.x & 31, ty = threadIdx.x >> 5;  // 32 x 8
    #pragma unroll
    for (int j = 0; j < 32; j += 8)
        t[ty + j][tx] = W[(size_t)(kb + ty + j) * N + nb + tx];
    __syncthreads();
    #pragma unroll
    for (int j = 0; j < 32; j += 8) {
        float v = t[tx][ty + j];
        hf h, l;
        split_f32(v, h, l);
        size_t o = (size_t)(nb + ty + j) * K + kb + tx;
        Th[o] = h; Tl[o] = l;
    }
}

// ---------------------------------------------------------------------------
// RoPE table + fused RoPE/transpose -> q unsplit, k/v split, [B,H,T,D]
// ---------------------------------------------------------------------------
__global__ void rope_tab_k(float* __restrict__ ct, float* __restrict__ st)
{
    int idx = blockIdx.x * blockDim.x + threadIdx.x;
    if (idx >= TSEQ * 32) return;
    int t = idx >> 5, d = idx & 31;
    float inv = (float)pow(10000.0, -(double)d / 32.0);
    float ang = (float)t * inv;
    ct[idx] = (float)cos((double)ang);
    st[idx] = (float)sin((double)ang);
}

__global__ void __launch_bounds__(256) rope_qkv_k(
    const float* __restrict__ qlin, const float* __restrict__ kvlin,
    const float* __restrict__ ct, const float* __restrict__ st,
    hf* __restrict__ q,
    hf* __restrict__ kh, hf* __restrict__ kl,
    hf* __restrict__ vh, hf* __restrict__ vl)
{
    int g = blockIdx.x * blockDim.x + threadIdx.x;
    int d = g & 31;
    int h = (g >> 5) & 15;
    int t = (g >> 9) & 2047;
    int b = g >> 20;

    float c = ct[t * 32 + d];
    float s = st[t * 32 + d];

    const float* qlp = qlin + ((size_t)(b * TSEQ + t)) * CEMB + h * HD;
    const float* klp = kvlin + ((size_t)(b * TSEQ + t)) * (2 * CEMB) + h * HD;
    const float* vlp = klp + CEMB;

    size_t o = (((size_t)(b * NH + h)) * TSEQ + t) * HD;

    float q0 = qlp[d], q1 = qlp[d + 32];
    q[o + d]      = __float2half_rn(q0 * c - q1 * s);
    q[o + d + 32] = __float2half_rn(q1 * c + q0 * s);

    float k0 = klp[d], k1 = klp[d + 32];
    hf hh, ll;
    split_f32(k0 * c - k1 * s, hh, ll); kh[o + d] = hh;      kl[o + d] = ll;
    split_f32(k1 * c + k0 * s, hh, ll); kh[o + d + 32] = hh; kl[o + d + 32] = ll;
    split_f32(vlp[d], hh, ll);          vh[o + d] = hh;      vl[o + d] = ll;
    split_f32(vlp[d + 32], hh, ll);     vh[o + d + 32] = hh; vl[o + d + 32] = ll;
}

// ---------------------------------------------------------------------------
// mma.sync fp16 GEMM: C[M,N] = A[M,K] @ W[N,K]^T, 2-pass (A x Bh + A x Bl).
// BM=BN=128, BK=16, 8 warps (2x4), warp tile 64x32. 36.9KB static smem.
// ---------------------------------------------------------------------------
#define EPI_NONE       0
#define EPI_BIAS_RESID 1
#define EPI_BIAS_GELU  2

#define ROWP   24
#define MATB   (128 * ROWP * 2)
#define STAGEB (3 * MATB)       // A, Bh, Bl

template <int EPI, int HOUT>
__global__ void __launch_bounds__(256, 2) gemm_mma(
    const hf* __restrict__ A,
    const hf* __restrict__ Bh, const hf* __restrict__ Bl,
    float* __restrict__ C, hf* __restrict__ Ch,
    const float* __restrict__ bias, const float* __restrict__ resid,
    int M, int N, int K)
{
    __shared__ char smem_raw[2 * STAGEB];
    uint32_t smem_u = (uint32_t)__cvta_generic_to_shared(smem_raw);

    int tid = threadIdx.x;
    int wid = tid >> 5, lid = tid & 31;
    int wm = wid & 1, wn = wid >> 1;
    int qr = lid >> 2, qc = lid & 3;
    int bm = blockIdx.y * 128, bn = blockIdx.x * 128;

    const hf* Ap  = A  + (size_t)bm * K;
    const hf* Bhp = Bh + (size_t)bn * K;
    const hf* Blp = Bl + (size_t)bn * K;

    int NK = K >> 4;

    int lrow = tid >> 1;
    int lc8  = (tid & 1) << 3;
    uint32_t lsoff = ((uint32_t)lrow * ROWP + lc8) * 2u;

    auto stage_load = [&](int kt, int buf) {
        size_t go = (size_t)lrow * K + (kt << 4) + lc8;
        uint32_t sa = smem_u + buf * STAGEB + lsoff;
        cpa16(sa + 0 * MATB, Ap + go);
        cpa16(sa + 1 * MATB, Bhp + go);
        cpa16(sa + 2 * MATB, Blp + go);
        cpa_commit();
    };

    int arow = wm * 64 + ((lid >> 3) & 1) * 8 + (lid & 7);
    int acol = ((lid >> 4) & 1) * 8;
    uint32_t aoff = ((uint32_t)arow * ROWP + acol) * 2u;
    int brow = wn * 32 + ((lid >> 4) & 1) * 8 + (lid & 7);
    int bcol = ((lid >> 3) & 1) * 8;
    uint32_t boff = ((uint32_t)brow * ROWP + bcol) * 2u;

    float acc[4][4][4] = {};

    stage_load(0, 0);

    for (int kt = 0; kt < NK; kt++) {
        int buf = kt & 1;
        if (kt + 1 < NK) {
            stage_load(kt + 1, buf ^ 1);
            cpa_wait<1>();
        } else {
            cpa_wait<0>();
        }
        __syncthreads();

        uint32_t sA  = smem_u + buf * STAGEB + 0 * MATB;
        uint32_t sBh = smem_u + buf * STAGEB + 1 * MATB;
        uint32_t sBl = smem_u + buf * STAGEB + 2 * MATB;

        uint32_t fa[4][4], fbh[4][2], fbl[4][2];
        #pragma unroll
        for (int mi = 0; mi < 4; mi++)
            ldm4(fa[mi][0], fa[mi][1], fa[mi][2], fa[mi][3],
                 sA + aoff + (uint32_t)(mi * 16 * ROWP) * 2u);
        #pragma unroll
        for (int p = 0; p < 2; p++) {
            uint32_t off = boff + (uint32_t)(p * 16 * ROWP) * 2u;
            ldm4(fbh[2 * p][0], fbh[2 * p][1], fbh[2 * p + 1][0], fbh[2 * p + 1][1],
                 sBh + off);
            ldm4(fbl[2 * p][0], fbl[2 * p][1], fbl[2 * p + 1][0], fbl[2 * p + 1][1],
                 sBl + off);
        }
        #pragma unroll
        for (int ni = 0; ni < 4; ni++)
            #pragma unroll
            for (int mi = 0; mi < 4; mi++)
                mma_f16(acc[mi][ni][0], acc[mi][ni][1], acc[mi][ni][2], acc[mi][ni][3],
                        fa[mi][0], fa[mi][1], fa[mi][2], fa[mi][3],
                        fbh[ni][0], fbh[ni][1]);
        #pragma unroll
        for (int ni = 0; ni < 4; ni++)
            #pragma unroll
            for (int mi = 0; mi < 4; mi++)
                mma_f16(acc[mi][ni][0], acc[mi][ni][1], acc[mi][ni][2], acc[mi][ni][3],
                        fa[mi][0], fa[mi][1], fa[mi][2], fa[mi][3],
                        fbl[ni][0], fbl[ni][1]);
        __syncthreads();
    }

    #pragma unroll
    for (int mi = 0; mi < 4; mi++) {
        #pragma unroll
        for (int ni = 0; ni < 4; ni++) {
            int col = bn + wn * 32 + ni * 8 + qc * 2;
            #pragma unroll
            for (int half = 0; half < 2; half++) {
                int row = bm + wm * 64 + mi * 16 + qr + half * 8;
                size_t off = (size_t)row * N + col;
                float v0 = acc[mi][ni][half * 2 + 0];
                float v1 = acc[mi][ni][half * 2 + 1];
                if (EPI != EPI_NONE) {
                    v0 += bias[col];
                    v1 += bias[col + 1];
                }
                if (EPI == EPI_BIAS_GELU) {
                    v0 = gelu_exact(v0);
                    v1 = gelu_exact(v1);
                }
                if (EPI == EPI_BIAS_RESID) {
                    float2 rv = *(const float2*)(resid + off);
                    v0 += rv.x; v1 += rv.y;
                }
                if (!HOUT) {
                    *(float2*)(C + off) = make_float2(v0, v1);
                } else {
                    *(uint32_t*)(Ch + off) = pack2h(v0, v1);
                }
            }
        }
    }
}

// ---------------------------------------------------------------------------
// Flash attention on fp16 mma.sync (2-pass: K and V split, Q/P unsplit).
// Br=128, Bc=64. 8 warps x 16 rows. 36.9KB static smem.
// ---------------------------------------------------------------------------
#define APAD 72
#define KVMAT (64 * APAD * 2)    // 9216 bytes per 64x64 matrix

__global__ void __launch_bounds__(256) attn_mma(
    const hf* __restrict__ q_,
    const hf* __restrict__ kh_, const hf* __restrict__ kl_,
    const hf* __restrict__ vh_, const hf* __restrict__ vl_,
    hf* __restrict__ ctx)
{
    __shared__ char sm[4 * KVMAT];   // 36864 bytes
    uint32_t smu = (uint32_t)__cvta_generic_to_shared(sm);

    int b = blockIdx.z, h = blockIdx.y, it = blockIdx.x;
    int t0 = it * 128;
    size_t bh = ((size_t)(b * NH + h)) * TSEQ * HD;

    int tid = threadIdx.x;
    int w = tid >> 5, lid = tid & 31;
    int qr = lid >> 2, qc = lid & 3;

    // ---- stage Q (128x64, unsplit) at offset 0, ldmatrix into registers ----
    {
        const hf* src = q_ + bh + (size_t)t0 * HD;
        #pragma unroll
        for (int i = 0; i < 4; i++) {
            int chunk = tid + i * 256;      // 0..1023
            int row = chunk >> 3, c8 = (chunk & 7) << 3;
            cpa16(smu + (row * APAD + c8) * 2, src + (size_t)row * HD + c8);
        }
        cpa_commit();
        cpa_wait<0>();
    }
    __syncthreads();

    uint32_t qa[4][4];
    {
        int row = w * 16 + ((lid >> 3) & 1) * 8 + (lid & 7);
        int colb = (lid >> 4) * 8;
        #pragma unroll
        for (int ks = 0; ks < 4; ks++) {
            uint32_t off = (uint32_t)(row * APAD + colb + ks * 16) * 2;
            ldm4(qa[ks][0], qa[ks][1], qa[ks][2], qa[ks][3], smu + off);
        }
    }

    float m_i[2] = { -1e30f, -1e30f };
    float l_i[2] = { 0.f, 0.f };
    float o[8][4] = {};
    float s[8][4];

    int nrb = ((lid >> 4) & 1) * 8 + (lid & 7);
    int ncb = ((lid >> 3) & 1) * 8;
    int srb = ((lid >> 3) & 1) * 8 + (lid & 7);
    int scb = ((lid >> 4) & 1) * 8;

    int nk = 2 * (it + 1);
    for (int kt = 0; kt < nk; kt++) {
        int k0 = kt * 64;
        __syncthreads();
        {
            const hf* srcs[4] = { kh_ + bh + (size_t)k0 * HD,
                                  kl_ + bh + (size_t)k0 * HD,
                                  vh_ + bh + (size_t)k0 * HD,
                                  vl_ + bh + (size_t)k0 * HD };
            #pragma unroll
            for (int i = 0; i < 8; i++) {
                int chunk = tid + i * 256;
                int mat = chunk >> 9;
                int wi = chunk & 511;
                int row = wi >> 3, c8 = (wi & 7) << 3;
                cpa16(smu + mat * KVMAT + (row * APAD + c8) * 2,
                      srcs[mat] + (size_t)row * HD + c8);
            }
            cpa_commit();
            cpa_wait<0>();
        }
        __syncthreads();

        // ---- S = Q K^T (2-pass: Kh then Kl) ----
        #pragma unroll
        for (int nt = 0; nt < 8; nt++) {
            s[nt][0] = 0.f; s[nt][1] = 0.f; s[nt][2] = 0.f; s[nt][3] = 0.f;
        }
        #pragma unroll
        for (int ks = 0; ks < 4; ks++) {
            uint32_t kb[8][2];
            #pragma unroll
            for (int g = 0; g < 4; g++) {
                uint32_t a = smu + (uint32_t)((g * 16 + nrb) * APAD + ks * 16 + ncb) * 2;
                ldm4(kb[2 * g][0], kb[2 * g][1], kb[2 * g + 1][0], kb[2 * g + 1][1], a);
            }
            #pragma unroll
            for (int nt = 0; nt < 8; nt++)
                mma_f16(s[nt][0], s[nt][1], s[nt][2], s[nt][3],
                        qa[ks][0], qa[ks][1], qa[ks][2], qa[ks][3],
                        kb[nt][0], kb[nt][1]);
            #pragma unroll
            for (int g = 0; g < 4; g++) {
                uint32_t a = smu + KVMAT +
                             (uint32_t)((g * 16 + nrb) * APAD + ks * 16 + ncb) * 2;
                ldm4(kb[2 * g][0], kb[2 * g][1], kb[2 * g + 1][0], kb[2 * g + 1][1], a);
            }
            #pragma unroll
            for (int nt = 0; nt < 8; nt++)
                mma_f16(s[nt][0], s[nt][1], s[nt][2], s[nt][3],
                        qa[ks][0], qa[ks][1], qa[ks][2], qa[ks][3],
                        kb[nt][0], kb[nt][1]);
        }

        int row0 = t0 + w * 16 + qr;
        int row1 = row0 + 8;
        #pragma unroll
        for (int nt = 0; nt < 8; nt++) {
            int col0 = k0 + nt * 8 + qc * 2;
            s[nt][0] = (col0     > row0) ? -1e30f : s[nt][0] * 0.125f;
            s[nt][1] = (col0 + 1 > row0) ? -1e30f : s[nt][1] * 0.125f;
            s[nt][2] = (col0     > row1) ? -1e30f : s[nt][2] * 0.125f;
            s[nt][3] = (col0 + 1 > row1) ? -1e30f : s[nt][3] * 0.125f;
        }

        float mxA = -1e30f, mxB = -1e30f;
        #pragma unroll
        for (int nt = 0; nt < 8; nt++) {
            mxA = fmaxf(mxA, fmaxf(s[nt][0], s[nt][1]));
            mxB = fmaxf(mxB, fmaxf(s[nt][2], s[nt][3]));
        }
        mxA = fmaxf(mxA, __shfl_xor_sync(0xffffffffu, mxA, 1));
        mxA = fmaxf(mxA, __shfl_xor_sync(0xffffffffu, mxA, 2));
        mxB = fmaxf(mxB, __shfl_xor_sync(0xffffffffu, mxB, 1));
        mxB = fmaxf(mxB, __shfl_xor_sync(0xffffffffu, mxB, 2));

        float mnA = fmaxf(m_i[0], mxA), mnB = fmaxf(m_i[1], mxB);
        float aA = expf(m_i[0] - mnA), aB = expf(m_i[1] - mnB);
        m_i[0] = mnA; m_i[1] = mnB;

        float sumA = 0.f, sumB = 0.f;
        #pragma unroll
        for (int nt = 0; nt < 8; nt++) {
            s[nt][0] = expf(s[nt][0] - mnA); sumA += s[nt][0];
            s[nt][1] = expf(s[nt][1] - mnA); sumA += s[nt][1];
            s[nt][2] = expf(s[nt][2] - mnB); sumB += s[nt][2];
            s[nt][3] = expf(s[nt][3] - mnB); sumB += s[nt][3];
        }
        sumA += __shfl_xor_sync(0xffffffffu, sumA, 1);
        sumA += __shfl_xor_sync(0xffffffffu, sumA, 2);
        sumB += __shfl_xor_sync(0xffffffffu, sumB, 1);
        sumB += __shfl_xor_sync(0xffffffffu, sumB, 2);
        l_i[0] = l_i[0] * aA + sumA;
        l_i[1] = l_i[1] * aB + sumB;

        #pragma unroll
        for (int dt = 0; dt < 8; dt++) {
            o[dt][0] *= aA; o[dt][1] *= aA;
            o[dt][2] *= aB; o[dt][3] *= aB;
        }

        // ---- O += P V (2-pass: Vh then Vl; P unsplit fp16) ----
        #pragma unroll
        for (int ks = 0; ks < 4; ks++) {
            uint32_t pa[4];
            pa[0] = pack2h(s[2 * ks][0],     s[2 * ks][1]);
            pa[1] = pack2h(s[2 * ks][2],     s[2 * ks][3]);
            pa[2] = pack2h(s[2 * ks + 1][0], s[2 * ks + 1][1]);
            pa[3] = pack2h(s[2 * ks + 1][2], s[2 * ks + 1][3]);

            uint32_t vb[8][2];
            #pragma unroll
            for (int g = 0; g < 4; g++) {
                uint32_t a = smu + 2 * KVMAT +
                             (uint32_t)((ks * 16 + srb) * APAD + g * 16 + scb) * 2;
                ldm4t(vb[2 * g][0], vb[2 * g][1], vb[2 * g + 1][0], vb[2 * g + 1][1], a);
            }
            #pragma unroll
            for (int dt = 0; dt < 8; dt++)
                mma_f16(o[dt][0], o[dt][1], o[dt][2], o[dt][3],
                        pa[0], pa[1], pa[2], pa[3], vb[dt][0], vb[dt][1]);
            #pragma unroll
            for (int g = 0; g < 4; g++) {
                uint32_t a = smu + 3 * KVMAT +
                             (uint32_t)((ks * 16 + srb) * APAD + g * 16 + scb) * 2;
                ldm4t(vb[2 * g][0], vb[2 * g][1], vb[2 * g + 1][0], vb[2 * g + 1][1], a);
            }
            #pragma unroll
            for (int dt = 0; dt < 8; dt++)
                mma_f16(o[dt][0], o[dt][1], o[dt][2], o[dt][3],
                        pa[0], pa[1], pa[2], pa[3], vb[dt][0], vb[dt][1]);
        }
    }

    // ---- normalize + store ctx [B,T,C] fp16 ----
    float invA = 1.0f / l_i[0], invB = 1.0f / l_i[1];
    int r0 = t0 + w * 16 + qr, r1 = r0 + 8;
    #pragma unroll
    for (int dt = 0; dt < 8; dt++) {
        int col = h * HD + dt * 8 + qc * 2;
        size_t off0 = ((size_t)(b * TSEQ + r0)) * CEMB + col;
        *(uint32_t*)(ctx + off0) = pack2h(o[dt][0] * invA, o[dt][1] * invA);
        size_t off1 = ((size_t)(b * TSEQ + r1)) * CEMB + col;
        *(uint32_t*)(ctx + off1) = pack2h(o[dt][2] * invB, o[dt][3] * invB);
    }
}

// ---------------------------------------------------------------------------
// Launch (indices 3 AND 5 are main GEMMs for ncu capture)
// ---------------------------------------------------------------------------
static float* sym(const void* s)
{
    void* p = nullptr;
    cudaGetSymbolAddress(&p, s);
    return (float*)p;
}
static hf* symh(const void* s)
{
    void* p = nullptr;
    cudaGetSymbolAddress(&p, s);
    return (hf*)p;
}

extern "C" void kernel_launch(void* const* d_in, const int* in_sizes, int n_in,
                              void* d_out, int out_size)
{
    const float* x      = (const float*)d_in[0];
    const float* ln1_w  = (const float*)d_in[1];
    const float* ln1_b  = (const float*)d_in[2];
    const float* ln2_w  = (const float*)d_in[3];
    const float* ln2_b  = (const float*)d_in[4];
    const float* q_w    = (const float*)d_in[5];
    const float* kvd_w  = (const float*)d_in[6];
    const float* kvln_w = (const float*)d_in[7];
    const float* kvln_b = (const float*)d_in[8];
    const float* kvu_w  = (const float*)d_in[9];
    const float* proj_w = (const float*)d_in[10];
    const float* proj_b = (const float*)d_in[11];
    const float* f1_w   = (const float*)d_in[12];
    const float* f1_b   = (const float*)d_in[13];
    const float* f2_w   = (const float*)d_in[14];
    const float* f2_b   = (const float*)d_in[15];
    float* out = (float*)d_out;

    float* qlin  = sym(g_qlin);
    float* ckv   = sym(g_ckv);
    float* kvlin = sym(g_kvlin);
    float* x1    = sym(g_x1);
    float* ct    = sym(g_cos);
    float* st    = sym(g_sin);
    hf *hh  = symh(g_h);
    hf *cva = symh(g_ckva);
    hf *ctx = symh(g_ctx);
    hf *h2  = symh(g_h2);
    hf *ff1 = symh(g_ff1);
    hf *q = symh(g_q);
    hf *kh = symh(g_kh), *kl = symh(g_kl);
    hf *vh = symh(g_vh), *vl = symh(g_vl);
    hf *wqh = symh(g_wq_h),  *wql = symh(g_wq_l);
    hf *wdh = symh(g_wkvd_h), *wdl = symh(g_wkvd_l);
    hf *wuh = symh(g_wkvu_h), *wul = symh(g_wkvu_l);
    hf *wph = symh(g_wpr_h),  *wpl = symh(g_wpr_l);
    hf *w1h = symh(g_wf1_h),  *w1l = symh(g_wf1_l);
    hf *w2h = symh(g_wf2_h),  *w2l = symh(g_wf2_l);

    // 0: prep q_w
    prep_w<<<dim3(CEMB / 32, CEMB / 32), 256>>>(q_w, wqh, wql, CEMB, CEMB);
    // 1: h = LN1(x) -> fp16
    ln_k<true><<<MROWS, 256>>>(x, ln1_w, ln1_b, nullptr, hh, CEMB);
    // 2: prep kvd_w
    prep_w<<<dim3(RKV / 32, CEMB / 32), 256>>>(kvd_w, wdh, wdl, CEMB, RKV);
    // 3: qlin = h @ q_w            <-- ncu target (offset 2)
    gemm_mma<EPI_NONE, 0><<<dim3(CEMB / 128, MROWS / 128), 256>>>(
        hh, wqh, wql, qlin, nullptr, nullptr, nullptr, MROWS, CEMB, CEMB);
    // 4: prep kvu_w
    prep_w<<<dim3(2 * CEMB / 32, RKV / 32), 256>>>(kvu_w, wuh, wul, RKV, 2 * CEMB);
    // 5: ckv = h @ kvd_w           <-- ncu target (offset 0)
    gemm_mma<EPI_NONE, 0><<<dim3(RKV / 128, MROWS / 128), 256>>>(
        hh, wdh, wdl, ckv, nullptr, nullptr, nullptr, MROWS, RKV, CEMB);
    // 6: ckv = LN_kv(ckv) -> fp16
    ln_k<true><<<MROWS, 256>>>(ckv, kvln_w, kvln_b, nullptr, cva, RKV);
    // 7: kvlin = ckv @ kvu_w
    gemm_mma<EPI_NONE, 0><<<dim3(2 * CEMB / 128, MROWS / 128), 256>>>(
        cva, wuh, wul, kvlin, nullptr, nullptr, nullptr, MROWS, 2 * CEMB, RKV);
    // 8: prep proj_w
    prep_w<<<dim3(CEMB / 32, CEMB / 32), 256>>>(proj_w, wph, wpl, CEMB, CEMB);
    // 9/10: rope
    rope_tab_k<<<(TSEQ * 32 + 255) / 256, 256>>>(ct, st);
    rope_qkv_k<<<(BSZ * TSEQ * NH * 32) / 256, 256>>>(qlin, kvlin, ct, st,
                                                      q, kh, kl, vh, vl);
    // 11: flash attention
    attn_mma<<<dim3(TSEQ / 128, NH, BSZ), 256>>>(q, kh, kl, vh, vl, ctx);
    // 12: x1 = x + ctx @ proj_w + proj_b
    gemm_mma<EPI_BIAS_RESID, 0><<<dim3(CEMB / 128, MROWS / 128), 256>>>(
        ctx, wph, wpl, x1, nullptr, proj_b, x, MROWS, CEMB, CEMB);
    // 13: h2 = LN2(x1) -> fp16
    ln_k<true><<<MROWS, 256>>>(x1, ln2_w, ln2_b, nullptr, h2, CEMB);
    // 14: prep f1_w
    prep_w<<<dim3(FF / 32, CEMB / 32), 256>>>(f1_w, w1h, w1l, CEMB, FF);
    // 15: ff1 = gelu(h2 @ f1_w + f1_b) -> fp16
    gemm_mma<EPI_BIAS_GELU, 1><<<dim3(FF / 128, MROWS / 128), 256>>>(
        h2, w1h, w1l, nullptr, ff1, f1_b, nullptr, MROWS, FF, CEMB);
    // 16: prep f2_w
    prep_w<<<dim3(CEMB / 32, FF / 32), 256>>>(f2_w, w2h, w2l, FF, CEMB);
    // 17: out = x1 + ff1 @ f2_w + f2_b
    gemm_mma<EPI_BIAS_RESID, 0><<<dim3(CEMB / 128, MROWS / 128), 256>>>(
        ff1, w2h, w2l, out, nullptr, f2_b, x1, MROWS, CEMB, FF);
}

// round 10
// speedup vs baseline: 5.3916x; 1.6492x over previous
#include <cuda_runtime.h>
#include <cuda_fp16.h>
#include <math.h>
#include <stdint.h>

// ---------------------------------------------------------------------------
// Problem constants
// ---------------------------------------------------------------------------
#define BSZ   4
#define TSEQ  2048
#define CEMB  1024
#define NH    16
#define HD    64
#define RKV   512
#define FF    4096
#define MROWS (BSZ * TSEQ)   // 8192

typedef __half hf;

// ---------------------------------------------------------------------------
// Scratch (static __device__ arrays -- allocation-free per harness rules)
// ---------------------------------------------------------------------------
__device__ float g_qlin [MROWS * CEMB];
__device__ float g_ckv  [MROWS * RKV];
__device__ float g_kvlin[MROWS * 2 * CEMB];
__device__ float g_x1   [MROWS * CEMB];
__device__ float g_cos  [TSEQ * 32];
__device__ float g_sin  [TSEQ * 32];
// fp16 activations (GEMM A operands)
__device__ hf g_h   [MROWS * CEMB];
__device__ hf g_ckva[MROWS * RKV];
__device__ hf g_ctx [MROWS * CEMB];
__device__ hf g_h2  [MROWS * CEMB];
__device__ hf g_ff1 [MROWS * FF];
// q/k/v fp16, [B,H,T,D]
__device__ hf g_q[MROWS * CEMB];
__device__ hf g_k[MROWS * CEMB];
__device__ hf g_v[MROWS * CEMB];
// fp16 transposed weights [N,K]
__device__ hf g_wq [CEMB * CEMB];
__device__ hf g_wkvd[RKV * CEMB];
__device__ hf g_wkvu[2 * CEMB * RKV];
__device__ hf g_wpr[CEMB * CEMB];
__device__ hf g_wf1[FF * CEMB];
__device__ hf g_wf2[CEMB * FF];

// ---------------------------------------------------------------------------
// Helpers
// ---------------------------------------------------------------------------
__device__ __forceinline__ uint32_t pack2h(float x, float y)
{
    __half2 p = __floats2half2_rn(x, y);
    return *(uint32_t*)&p;
}
__device__ __forceinline__ float gelu_exact(float x)
{
    return 0.5f * x * (1.0f + erff(x * 0.70710678118654752f));
}
__device__ __forceinline__ void cpa16(uint32_t saddr, const void* g)
{
    asm volatile("cp.async.cg.shared.global [%0], [%1], 16;"
                 :: "r"(saddr), "l"(g) : "memory");
}
__device__ __forceinline__ void cpa_commit()
{
    asm volatile("cp.async.commit_group;" ::: "memory");
}
template <int N>
__device__ __forceinline__ void cpa_wait()
{
    asm volatile("cp.async.wait_group %0;" :: "n"(N) : "memory");
}
__device__ __forceinline__ void mma_f16(float& c0, float& c1, float& c2, float& c3,
                                        uint32_t a0, uint32_t a1, uint32_t a2,
                                        uint32_t a3, uint32_t b0, uint32_t b1)
{
    asm volatile(
        "mma.sync.aligned.m16n8k16.row.col.f32.f16.f16.f32 "
        "{%0,%1,%2,%3}, {%4,%5,%6,%7}, {%8,%9}, {%0,%1,%2,%3};"
        : "+f"(c0), "+f"(c1), "+f"(c2), "+f"(c3)
        : "r"(a0), "r"(a1), "r"(a2), "r"(a3), "r"(b0), "r"(b1));
}
__device__ __forceinline__ void ldm4(uint32_t& r0, uint32_t& r1, uint32_t& r2,
                                     uint32_t& r3, uint32_t a)
{
    asm volatile("ldmatrix.sync.aligned.m8n8.x4.shared.b16 {%0,%1,%2,%3}, [%4];"
                 : "=r"(r0), "=r"(r1), "=r"(r2), "=r"(r3) : "r"(a));
}
__device__ __forceinline__ void ldm4t(uint32_t& r0, uint32_t& r1, uint32_t& r2,
                                      uint32_t& r3, uint32_t a)
{
    asm volatile("ldmatrix.sync.aligned.m8n8.x4.trans.shared.b16 {%0,%1,%2,%3}, [%4];"
                 : "=r"(r0), "=r"(r1), "=r"(r2), "=r"(r3) : "r"(a));
}

// ---------------------------------------------------------------------------
// LayerNorm: writes f32 or fp16
// ---------------------------------------------------------------------------
template <bool HOUT>
__global__ void __launch_bounds__(256) ln_k(const float* __restrict__ x,
                                            const float* __restrict__ w,
                                            const float* __restrict__ b,
                                            float* __restrict__ out,
                                            hf* __restrict__ oh, int W)
{
    size_t row = blockIdx.x;
    const float* xr = x + row * (size_t)W;

    float s = 0.f, s2 = 0.f;
    for (int i = threadIdx.x << 2; i < W; i += 256 * 4) {
        float4 v = *(const float4*)(xr + i);
        s  += v.x + v.y + v.z + v.w;
        s2 += v.x * v.x + v.y * v.y + v.z * v.z + v.w * v.w;
    }
    __shared__ float sh[8][2];
    #pragma unroll
    for (int off = 16; off; off >>= 1) {
        s  += __shfl_xor_sync(0xffffffffu, s,  off);
        s2 += __shfl_xor_sync(0xffffffffu, s2, off);
    }
    int wrp = threadIdx.x >> 5, ln = threadIdx.x & 31;
    if (ln == 0) { sh[wrp][0] = s; sh[wrp][1] = s2; }
    __syncthreads();
    s = 0.f; s2 = 0.f;
    #pragma unroll
    for (int i = 0; i < 8; i++) { s += sh[i][0]; s2 += sh[i][1]; }

    float invW = 1.0f / (float)W;
    float mu   = s * invW;
    float var  = s2 * invW - mu * mu;
    float rstd = rsqrtf(var + 1e-5f);

    for (int i = threadIdx.x << 2; i < W; i += 256 * 4) {
        float4 v  = *(const float4*)(xr + i);
        float4 wv = *(const float4*)(w + i);
        float4 bv = *(const float4*)(b + i);
        float r0 = (v.x - mu) * rstd * wv.x + bv.x;
        float r1 = (v.y - mu) * rstd * wv.y + bv.y;
        float r2 = (v.z - mu) * rstd * wv.z + bv.z;
        float r3 = (v.w - mu) * rstd * wv.w + bv.w;
        if (!HOUT) {
            *(float4*)(out + row * (size_t)W + i) = make_float4(r0, r1, r2, r3);
        } else {
            *(uint32_t*)(oh + row * (size_t)W + i)     = pack2h(r0, r1);
            *(uint32_t*)(oh + row * (size_t)W + i + 2) = pack2h(r2, r3);
        }
    }
}

// ---------------------------------------------------------------------------
// Weight preprocess: W[K,N] -> T [N,K] fp16 (tiled transpose)
// ---------------------------------------------------------------------------
__global__ void __launch_bounds__(256) prep_w(const float* __restrict__ W,
                                              hf* __restrict__ T,
                                              int K, int N)
{
    __shared__ float t[32][33];
    int nb = blockIdx.x * 32, kb = blockIdx.y * 32;
    int tx = threadIdx.x & 31, ty = threadIdx.x >> 5;  // 32 x 8
    #pragma unroll
    for (int j = 0; j < 32; j += 8)
        t[ty + j][tx] = W[(size_t)(kb + ty + j) * N + nb + tx];
    __syncthreads();
    #pragma unroll
    for (int j = 0; j < 32; j += 8)
        T[(size_t)(nb + ty + j) * K + kb + tx] = __float2half_rn(t[tx][ty + j]);
}

// ---------------------------------------------------------------------------
// RoPE table + fused RoPE/transpose -> fp16 q/k/v [B,H,T,D]
// ---------------------------------------------------------------------------
__global__ void rope_tab_k(float* __restrict__ ct, float* __restrict__ st)
{
    int idx = blockIdx.x * blockDim.x + threadIdx.x;
    if (idx >= TSEQ * 32) return;
    int t = idx >> 5, d = idx & 31;
    float inv = (float)pow(10000.0, -(double)d / 32.0);
    float ang = (float)t * inv;
    ct[idx] = (float)cos((double)ang);
    st[idx] = (float)sin((double)ang);
}

__global__ void __launch_bounds__(256) rope_qkv_k(
    const float* __restrict__ qlin, const float* __restrict__ kvlin,
    const float* __restrict__ ct, const float* __restrict__ st,
    hf* __restrict__ q, hf* __restrict__ k, hf* __restrict__ v)
{
    int g = blockIdx.x * blockDim.x + threadIdx.x;
    int d = g & 31;
    int h = (g >> 5) & 15;
    int t = (g >> 9) & 2047;
    int b = g >> 20;

    float c = ct[t * 32 + d];
    float s = st[t * 32 + d];

    const float* qlp = qlin + ((size_t)(b * TSEQ + t)) * CEMB + h * HD;
    const float* klp = kvlin + ((size_t)(b * TSEQ + t)) * (2 * CEMB) + h * HD;
    const float* vlp = klp + CEMB;

    size_t o = (((size_t)(b * NH + h)) * TSEQ + t) * HD;

    float q0 = qlp[d], q1 = qlp[d + 32];
    q[o + d]      = __float2half_rn(q0 * c - q1 * s);
    q[o + d + 32] = __float2half_rn(q1 * c + q0 * s);

    float k0 = klp[d], k1 = klp[d + 32];
    k[o + d]      = __float2half_rn(k0 * c - k1 * s);
    k[o + d + 32] = __float2half_rn(k1 * c + k0 * s);

    v[o + d]      = __float2half_rn(vlp[d]);
    v[o + d + 32] = __float2half_rn(vlp[d + 32]);
}

// ---------------------------------------------------------------------------
// mma.sync fp16 GEMM (1-pass): C[M,N] = A[M,K] @ W[N,K]^T.
// BM=BN=128, BK=32, 8 warps (2x4), warp tile 64x32.
// Rows padded 32->40 fp16 (stride 20 words: ldmatrix rows hit distinct banks).
// 2-stage cp.async, 40KB static smem, 2 CTAs/SM.
// ---------------------------------------------------------------------------
#define EPI_NONE       0
#define EPI_BIAS_RESID 1
#define EPI_BIAS_GELU  2

#define ROWP   40
#define MATB   (128 * ROWP * 2)     // 10240 bytes
#define STAGEB (2 * MATB)           // A, B

template <int EPI, int HOUT>
__global__ void __launch_bounds__(256, 2) gemm_mma(
    const hf* __restrict__ A, const hf* __restrict__ B,
    float* __restrict__ C, hf* __restrict__ Ch,
    const float* __restrict__ bias, const float* __restrict__ resid,
    int M, int N, int K)
{
    __shared__ char smem_raw[2 * STAGEB];   // 40960
    uint32_t smem_u = (uint32_t)__cvta_generic_to_shared(smem_raw);

    int tid = threadIdx.x;
    int wid = tid >> 5, lid = tid & 31;
    int wm = wid & 1, wn = wid >> 1;
    int qr = lid >> 2, qc = lid & 3;
    int bm = blockIdx.y * 128, bn = blockIdx.x * 128;

    const hf* Ap = A + (size_t)bm * K;
    const hf* Bp = B + (size_t)bn * K;

    int NK = K >> 5;    // BK = 32

    int lrow = tid >> 2;            // 0..63 base rows (2 chunks/thread)
    int lc8  = (tid & 3) << 3;      // 0,8,16,24
    // chunk i covers rows lrow + i*64

    auto stage_load = [&](int kt, int buf) {
        #pragma unroll
        for (int i = 0; i < 2; i++) {
            int row = lrow + i * 64;
            size_t go = (size_t)row * K + (kt << 5) + lc8;
            uint32_t sa = smem_u + buf * STAGEB + ((uint32_t)row * ROWP + lc8) * 2u;
            cpa16(sa + 0 * MATB, Ap + go);
            cpa16(sa + 1 * MATB, Bp + go);
        }
        cpa_commit();
    };

    int arow = wm * 64 + ((lid >> 3) & 1) * 8 + (lid & 7);
    int acolb = ((lid >> 4) & 1) * 8;
    int brow = wn * 32 + ((lid >> 4) & 1) * 8 + (lid & 7);
    int bcolb = ((lid >> 3) & 1) * 8;

    float acc[4][4][4] = {};

    stage_load(0, 0);

    for (int kt = 0; kt < NK; kt++) {
        int buf = kt & 1;
        if (kt + 1 < NK) {
            stage_load(kt + 1, buf ^ 1);
            cpa_wait<1>();
        } else {
            cpa_wait<0>();
        }
        __syncthreads();

        uint32_t sA = smem_u + buf * STAGEB + 0 * MATB;
        uint32_t sB = smem_u + buf * STAGEB + 1 * MATB;

        #pragma unroll
        for (int kh = 0; kh < 2; kh++) {     // two k16 halves of BK=32
            int kc = kh * 16;
            uint32_t fa[4][4], fb[4][2];
            #pragma unroll
            for (int mi = 0; mi < 4; mi++)
                ldm4(fa[mi][0], fa[mi][1], fa[mi][2], fa[mi][3],
                     sA + ((uint32_t)((arow + mi * 16) * ROWP + kc + acolb)) * 2u);
            #pragma unroll
            for (int p = 0; p < 2; p++)
                ldm4(fb[2 * p][0], fb[2 * p][1], fb[2 * p + 1][0], fb[2 * p + 1][1],
                     sB + ((uint32_t)((brow + p * 16) * ROWP + kc + bcolb)) * 2u);
            #pragma unroll
            for (int ni = 0; ni < 4; ni++)
                #pragma unroll
                for (int mi = 0; mi < 4; mi++)
                    mma_f16(acc[mi][ni][0], acc[mi][ni][1],
                            acc[mi][ni][2], acc[mi][ni][3],
                            fa[mi][0], fa[mi][1], fa[mi][2], fa[mi][3],
                            fb[ni][0], fb[ni][1]);
        }
        __syncthreads();
    }

    #pragma unroll
    for (int mi = 0; mi < 4; mi++) {
        #pragma unroll
        for (int ni = 0; ni < 4; ni++) {
            int col = bn + wn * 32 + ni * 8 + qc * 2;
            #pragma unroll
            for (int half = 0; half < 2; half++) {
                int row = bm + wm * 64 + mi * 16 + qr + half * 8;
                size_t off = (size_t)row * N + col;
                float v0 = acc[mi][ni][half * 2 + 0];
                float v1 = acc[mi][ni][half * 2 + 1];
                if (EPI != EPI_NONE) {
                    v0 += bias[col];
                    v1 += bias[col + 1];
                }
                if (EPI == EPI_BIAS_GELU) {
                    v0 = gelu_exact(v0);
                    v1 = gelu_exact(v1);
                }
                if (EPI == EPI_BIAS_RESID) {
                    float2 rv = *(const float2*)(resid + off);
                    v0 += rv.x; v1 += rv.y;
                }
                if (!HOUT) {
                    *(float2*)(C + off) = make_float2(v0, v1);
                } else {
                    *(uint32_t*)(Ch + off) = pack2h(v0, v1);
                }
            }
        }
    }
}

// ---------------------------------------------------------------------------
// Flash attention on fp16 mma.sync (1-pass). Br=128, Bc=64, 8 warps x 16 rows.
// K/V unsplit, 18KB static smem.
// ---------------------------------------------------------------------------
#define APAD 72
#define KVMAT (64 * APAD * 2)    // 9216 bytes per 64x64 matrix

__global__ void __launch_bounds__(256) attn_mma(
    const hf* __restrict__ q_, const hf* __restrict__ k_,
    const hf* __restrict__ v_, hf* __restrict__ ctx)
{
    __shared__ char sm[2 * KVMAT];   // 18432 bytes (also fits staged Q 128xAPAD)
    uint32_t smu = (uint32_t)__cvta_generic_to_shared(sm);

    int b = blockIdx.z, h = blockIdx.y, it = blockIdx.x;
    int t0 = it * 128;
    size_t bh = ((size_t)(b * NH + h)) * TSEQ * HD;

    int tid = threadIdx.x;
    int w = tid >> 5, lid = tid & 31;
    int qr = lid >> 2, qc = lid & 3;

    // ---- stage Q (128x64) across whole smem, ldmatrix into registers ----
    {
        const hf* src = q_ + bh + (size_t)t0 * HD;
        #pragma unroll
        for (int i = 0; i < 4; i++) {
            int chunk = tid + i * 256;      // 0..1023
            int row = chunk >> 3, c8 = (chunk & 7) << 3;
            cpa16(smu + (row * APAD + c8) * 2, src + (size_t)row * HD + c8);
        }
        cpa_commit();
        cpa_wait<0>();
    }
    __syncthreads();

    uint32_t qa[4][4];
    {
        int row = w * 16 + ((lid >> 3) & 1) * 8 + (lid & 7);
        int colb = (lid >> 4) * 8;
        #pragma unroll
        for (int ks = 0; ks < 4; ks++) {
            uint32_t off = (uint32_t)(row * APAD + colb + ks * 16) * 2;
            ldm4(qa[ks][0], qa[ks][1], qa[ks][2], qa[ks][3], smu + off);
        }
    }

    float m_i[2] = { -1e30f, -1e30f };
    float l_i[2] = { 0.f, 0.f };
    float o[8][4] = {};
    float s[8][4];

    int nrb = ((lid >> 4) & 1) * 8 + (lid & 7);
    int ncb = ((lid >> 3) & 1) * 8;
    int srb = ((lid >> 3) & 1) * 8 + (lid & 7);
    int scb = ((lid >> 4) & 1) * 8;

    int nk = 2 * (it + 1);
    for (int kt = 0; kt < nk; kt++) {
        int k0 = kt * 64;
        __syncthreads();
        {
            const hf* srcs[2] = { k_ + bh + (size_t)k0 * HD,
                                  v_ + bh + (size_t)k0 * HD };
            #pragma unroll
            for (int i = 0; i < 4; i++) {
                int chunk = tid + i * 256;   // 0..1023
                int mat = chunk >> 9;        // 0=K, 1=V
                int wi = chunk & 511;
                int row = wi >> 3, c8 = (wi & 7) << 3;
                cpa16(smu + mat * KVMAT + (row * APAD + c8) * 2,
                      srcs[mat] + (size_t)row * HD + c8);
            }
            cpa_commit();
            cpa_wait<0>();
        }
        __syncthreads();

        // ---- S = Q K^T ----
        #pragma unroll
        for (int nt = 0; nt < 8; nt++) {
            s[nt][0] = 0.f; s[nt][1] = 0.f; s[nt][2] = 0.f; s[nt][3] = 0.f;
        }
        #pragma unroll
        for (int ks = 0; ks < 4; ks++) {
            uint32_t kb[8][2];
            #pragma unroll
            for (int g = 0; g < 4; g++) {
                uint32_t a = smu + (uint32_t)((g * 16 + nrb) * APAD + ks * 16 + ncb) * 2;
                ldm4(kb[2 * g][0], kb[2 * g][1], kb[2 * g + 1][0], kb[2 * g + 1][1], a);
            }
            #pragma unroll
            for (int nt = 0; nt < 8; nt++)
                mma_f16(s[nt][0], s[nt][1], s[nt][2], s[nt][3],
                        qa[ks][0], qa[ks][1], qa[ks][2], qa[ks][3],
                        kb[nt][0], kb[nt][1]);
        }

        int row0 = t0 + w * 16 + qr;
        int row1 = row0 + 8;
        #pragma unroll
        for (int nt = 0; nt < 8; nt++) {
            int col0 = k0 + nt * 8 + qc * 2;
            s[nt][0] = (col0     > row0) ? -1e30f : s[nt][0] * 0.125f;
            s[nt][1] = (col0 + 1 > row0) ? -1e30f : s[nt][1] * 0.125f;
            s[nt][2] = (col0     > row1) ? -1e30f : s[nt][2] * 0.125f;
            s[nt][3] = (col0 + 1 > row1) ? -1e30f : s[nt][3] * 0.125f;
        }

        float mxA = -1e30f, mxB = -1e30f;
        #pragma unroll
        for (int nt = 0; nt < 8; nt++) {
            mxA = fmaxf(mxA, fmaxf(s[nt][0], s[nt][1]));
            mxB = fmaxf(mxB, fmaxf(s[nt][2], s[nt][3]));
        }
        mxA = fmaxf(mxA, __shfl_xor_sync(0xffffffffu, mxA, 1));
        mxA = fmaxf(mxA, __shfl_xor_sync(0xffffffffu, mxA, 2));
        mxB = fmaxf(mxB, __shfl_xor_sync(0xffffffffu, mxB, 1));
        mxB = fmaxf(mxB, __shfl_xor_sync(0xffffffffu, mxB, 2));

        float mnA = fmaxf(m_i[0], mxA), mnB = fmaxf(m_i[1], mxB);
        float aA = expf(m_i[0] - mnA), aB = expf(m_i[1] - mnB);
        m_i[0] = mnA; m_i[1] = mnB;

        float sumA = 0.f, sumB = 0.f;
        #pragma unroll
        for (int nt = 0; nt < 8; nt++) {
            s[nt][0] = expf(s[nt][0] - mnA); sumA += s[nt][0];
            s[nt][1] = expf(s[nt][1] - mnA); sumA += s[nt][1];
            s[nt][2] = expf(s[nt][2] - mnB); sumB += s[nt][2];
            s[nt][3] = expf(s[nt][3] - mnB); sumB += s[nt][3];
        }
        sumA += __shfl_xor_sync(0xffffffffu, sumA, 1);
        sumA += __shfl_xor_sync(0xffffffffu, sumA, 2);
        sumB += __shfl_xor_sync(0xffffffffu, sumB, 1);
        sumB += __shfl_xor_sync(0xffffffffu, sumB, 2);
        l_i[0] = l_i[0] * aA + sumA;
        l_i[1] = l_i[1] * aB + sumB;

        #pragma unroll
        for (int dt = 0; dt < 8; dt++) {
            o[dt][0] *= aA; o[dt][1] *= aA;
            o[dt][2] *= aB; o[dt][3] *= aB;
        }

        // ---- O += P V ----
        #pragma unroll
        for (int ks = 0; ks < 4; ks++) {
            uint32_t pa[4];
            pa[0] = pack2h(s[2 * ks][0],     s[2 * ks][1]);
            pa[1] = pack2h(s[2 * ks][2],     s[2 * ks][3]);
            pa[2] = pack2h(s[2 * ks + 1][0], s[2 * ks + 1][1]);
            pa[3] = pack2h(s[2 * ks + 1][2], s[2 * ks + 1][3]);

            uint32_t vb[8][2];
            #pragma unroll
            for (int g = 0; g < 4; g++) {
                uint32_t a = smu + KVMAT +
                             (uint32_t)((ks * 16 + srb) * APAD + g * 16 + scb) * 2;
                ldm4t(vb[2 * g][0], vb[2 * g][1], vb[2 * g + 1][0], vb[2 * g + 1][1], a);
            }
            #pragma unroll
            for (int dt = 0; dt < 8; dt++)
                mma_f16(o[dt][0], o[dt][1], o[dt][2], o[dt][3],
                        pa[0], pa[1], pa[2], pa[3], vb[dt][0], vb[dt][1]);
        }
    }

    float invA = 1.0f / l_i[0], invB = 1.0f / l_i[1];
    int r0 = t0 + w * 16 + qr, r1 = r0 + 8;
    #pragma unroll
    for (int dt = 0; dt < 8; dt++) {
        int col = h * HD + dt * 8 + qc * 2;
        size_t off0 = ((size_t)(b * TSEQ + r0)) * CEMB + col;
        *(uint32_t*)(ctx + off0) = pack2h(o[dt][0] * invA, o[dt][1] * invA);
        size_t off1 = ((size_t)(b * TSEQ + r1)) * CEMB + col;
        *(uint32_t*)(ctx + off1) = pack2h(o[dt][2] * invB, o[dt][3] * invB);
    }
}

// ---------------------------------------------------------------------------
// Launch (indices 3 AND 5 are main GEMMs for ncu capture)
// ---------------------------------------------------------------------------
static float* sym(const void* s)
{
    void* p = nullptr;
    cudaGetSymbolAddress(&p, s);
    return (float*)p;
}
static hf* symh(const void* s)
{
    void* p = nullptr;
    cudaGetSymbolAddress(&p, s);
    return (hf*)p;
}

extern "C" void kernel_launch(void* const* d_in, const int* in_sizes, int n_in,
                              void* d_out, int out_size)
{
    const float* x      = (const float*)d_in[0];
    const float* ln1_w  = (const float*)d_in[1];
    const float* ln1_b  = (const float*)d_in[2];
    const float* ln2_w  = (const float*)d_in[3];
    const float* ln2_b  = (const float*)d_in[4];
    const float* q_w    = (const float*)d_in[5];
    const float* kvd_w  = (const float*)d_in[6];
    const float* kvln_w = (const float*)d_in[7];
    const float* kvln_b = (const float*)d_in[8];
    const float* kvu_w  = (const float*)d_in[9];
    const float* proj_w = (const float*)d_in[10];
    const float* proj_b = (const float*)d_in[11];
    const float* f1_w   = (const float*)d_in[12];
    const float* f1_b   = (const float*)d_in[13];
    const float* f2_w   = (const float*)d_in[14];
    const float* f2_b   = (const float*)d_in[15];
    float* out = (float*)d_out;

    float* qlin  = sym(g_qlin);
    float* ckv   = sym(g_ckv);
    float* kvlin = sym(g_kvlin);
    float* x1    = sym(g_x1);
    float* ct    = sym(g_cos);
    float* st    = sym(g_sin);
    hf *hh  = symh(g_h);
    hf *cva = symh(g_ckva);
    hf *ctx = symh(g_ctx);
    hf *h2  = symh(g_h2);
    hf *ff1 = symh(g_ff1);
    hf *q = symh(g_q), *k = symh(g_k), *v = symh(g_v);
    hf *wq = symh(g_wq), *wd = symh(g_wkvd), *wu = symh(g_wkvu);
    hf *wp = symh(g_wpr), *w1 = symh(g_wf1), *w2 = symh(g_wf2);

    // 0: prep q_w
    prep_w<<<dim3(CEMB / 32, CEMB / 32), 256>>>(q_w, wq, CEMB, CEMB);
    // 1: h = LN1(x) -> fp16
    ln_k<true><<<MROWS, 256>>>(x, ln1_w, ln1_b, nullptr, hh, CEMB);
    // 2: prep kvd_w
    prep_w<<<dim3(RKV / 32, CEMB / 32), 256>>>(kvd_w, wd, CEMB, RKV);
    // 3: qlin = h @ q_w            <-- ncu target (offset 2)
    gemm_mma<EPI_NONE, 0><<<dim3(CEMB / 128, MROWS / 128), 256>>>(
        hh, wq, qlin, nullptr, nullptr, nullptr, MROWS, CEMB, CEMB);
    // 4: prep kvu_w
    prep_w<<<dim3(2 * CEMB / 32, RKV / 32), 256>>>(kvu_w, wu, RKV, 2 * CEMB);
    // 5: ckv = h @ kvd_w           <-- ncu target (offset 0)
    gemm_mma<EPI_NONE, 0><<<dim3(RKV / 128, MROWS / 128), 256>>>(
        hh, wd, ckv, nullptr, nullptr, nullptr, MROWS, RKV, CEMB);
    // 6: ckv = LN_kv(ckv) -> fp16
    ln_k<true><<<MROWS, 256>>>(ckv, kvln_w, kvln_b, nullptr, cva, RKV);
    // 7: kvlin = ckv @ kvu_w
    gemm_mma<EPI_NONE, 0><<<dim3(2 * CEMB / 128, MROWS / 128), 256>>>(
        cva, wu, kvlin, nullptr, nullptr, nullptr, MROWS, 2 * CEMB, RKV);
    // 8: prep proj_w
    prep_w<<<dim3(CEMB / 32, CEMB / 32), 256>>>(proj_w, wp, CEMB, CEMB);
    // 9/10: rope
    rope_tab_k<<<(TSEQ * 32 + 255) / 256, 256>>>(ct, st);
    rope_qkv_k<<<(BSZ * TSEQ * NH * 32) / 256, 256>>>(qlin, kvlin, ct, st, q, k, v);
    // 11: flash attention
    attn_mma<<<dim3(TSEQ / 128, NH, BSZ), 256>>>(q, k, v, ctx);
    // 12: x1 = x + ctx @ proj_w + proj_b
    gemm_mma<EPI_BIAS_RESID, 0><<<dim3(CEMB / 128, MROWS / 128), 256>>>(
        ctx, wp, x1, nullptr, proj_b, x, MROWS, CEMB, CEMB);
    // 13: h2 = LN2(x1) -> fp16
    ln_k<true><<<MROWS, 256>>>(x1, ln2_w, ln2_b, nullptr, h2, CEMB);
    // 14: prep f1_w
    prep_w<<<dim3(FF / 32, CEMB / 32), 256>>>(f1_w, w1, CEMB, FF);
    // 15: ff1 = gelu(h2 @ f1_w + f1_b) -> fp16
    gemm_mma<EPI_BIAS_GELU, 1><<<dim3(FF / 128, MROWS / 128), 256>>>(
        h2, w1, nullptr, ff1, f1_b, nullptr, MROWS, FF, CEMB);
    // 16: prep f2_w
    prep_w<<<dim3(CEMB / 32, FF / 32), 256>>>(f2_w, w2, FF, CEMB);
    // 17: out = x1 + ff1 @ f2_w + f2_b
    gemm_mma<EPI_BIAS_RESID, 0><<<dim3(CEMB / 128, MROWS / 128), 256>>>(
        ff1, w2, out, nullptr, f2_b, x1, MROWS, CEMB, FF);
}